// round 1
// baseline (speedup 1.0000x reference)
#include <cuda_runtime.h>
#include <math.h>

#define S_LEN  2048
#define HID    4096
#define NHEAD  32
#define HDIM   128
#define RECENT 204           // int(2048 * 0.1)
#define SINKN  4
#define EVLEN  (SINKN + RECENT)   // 208

// -------- scratch (static device allocations; no cudaMalloc allowed) --------
static __device__ float g_q[NHEAD * S_LEN * HDIM];   // [NH][S][HD] (post-RoPE)
static __device__ float g_k[NHEAD * S_LEN * HDIM];   // [NH][S][HD] (post-RoPE)
static __device__ float g_v[NHEAD * S_LEN * HDIM];   // [NH][S][HD]
static __device__ float g_o[S_LEN * HID];            // [S][H] attention output

// ============================================================================
// SGEMM: C = A @ B^T.  A [M,K] row-major, B [N,K] row-major.
// Block tile 128x128, K-tile 16, 256 threads, 8x8 per thread.
// HEADS_LAYOUT=1 -> write C to [NH][S][HD] layout; 0 -> row-major [M][N].
// ============================================================================
template <int HEADS_LAYOUT>
__global__ __launch_bounds__(256, 2)
void sgemm_nt_kernel(const float* __restrict__ A, const float* __restrict__ B,
                     float* __restrict__ C, int M, int N, int K)
{
    const int BM = 128, BN = 128, BK = 16, LDT = BM + 4;   // padded stride
    __shared__ float As[BK * LDT];
    __shared__ float Bs[BK * LDT];

    int tid = threadIdx.x;
    int m0 = blockIdx.y * BM;
    int n0 = blockIdx.x * BN;
    int ti = tid >> 4;       // 0..15 -> M sub-tile
    int tj = tid & 15;       // 0..15 -> N sub-tile

    float acc[8][8];
#pragma unroll
    for (int i = 0; i < 8; i++)
#pragma unroll
        for (int j = 0; j < 8; j++) acc[i][j] = 0.0f;

    for (int k0 = 0; k0 < K; k0 += BK) {
        // ---- load A,B tiles (transposed into [k][m]) ----
#pragma unroll
        for (int l = 0; l < 2; l++) {
            int u   = tid + l * 256;           // 0..511
            int row = u >> 2;                  // 0..127
            int seg = (u & 3) * 4;             // 0,4,8,12
            float4 a4 = *(const float4*)(A + (size_t)(m0 + row) * K + k0 + seg);
            As[(seg + 0) * LDT + row] = a4.x;
            As[(seg + 1) * LDT + row] = a4.y;
            As[(seg + 2) * LDT + row] = a4.z;
            As[(seg + 3) * LDT + row] = a4.w;
            float4 b4 = *(const float4*)(B + (size_t)(n0 + row) * K + k0 + seg);
            Bs[(seg + 0) * LDT + row] = b4.x;
            Bs[(seg + 1) * LDT + row] = b4.y;
            Bs[(seg + 2) * LDT + row] = b4.z;
            Bs[(seg + 3) * LDT + row] = b4.w;
        }
        __syncthreads();

#pragma unroll
        for (int k = 0; k < BK; k++) {
            float4 a0 = *(const float4*)(As + k * LDT + ti * 8);
            float4 a1 = *(const float4*)(As + k * LDT + ti * 8 + 4);
            float4 b0 = *(const float4*)(Bs + k * LDT + tj * 8);
            float4 b1 = *(const float4*)(Bs + k * LDT + tj * 8 + 4);
            float av[8] = {a0.x, a0.y, a0.z, a0.w, a1.x, a1.y, a1.z, a1.w};
            float bv[8] = {b0.x, b0.y, b0.z, b0.w, b1.x, b1.y, b1.z, b1.w};
#pragma unroll
            for (int i = 0; i < 8; i++)
#pragma unroll
                for (int j = 0; j < 8; j++)
                    acc[i][j] = fmaf(av[i], bv[j], acc[i][j]);
        }
        __syncthreads();
    }

    // ---- epilogue ----
#pragma unroll
    for (int i = 0; i < 8; i++) {
        int m = m0 + ti * 8 + i;
#pragma unroll
        for (int j = 0; j < 8; j += 4) {
            int n = n0 + tj * 8 + j;
            float4 val = make_float4(acc[i][j], acc[i][j + 1], acc[i][j + 2], acc[i][j + 3]);
            if (HEADS_LAYOUT) {
                // head = n>>7 is constant per 128-wide N block; (n&127) is 4-aligned
                float* dst = C + ((size_t)(n >> 7) * S_LEN + m) * HDIM + (n & 127);
                *(float4*)dst = val;
            } else {
                *(float4*)(C + (size_t)m * N + n) = val;
            }
        }
    }
}

// ============================================================================
// RoPE applied in-place to g_q and g_k. position_ids == arange(S) by problem
// construction; angles computed in fp64 then truncated.
// ============================================================================
__global__ void rope_kernel()
{
    int idx = blockIdx.x * blockDim.x + threadIdx.x;
    if (idx >= NHEAD * S_LEN * 64) return;
    int d = idx & 63;
    int s = (idx >> 6) & (S_LEN - 1);
    int h = idx >> 17;

    double inv = pow(10000.0, -(double)(2 * d) / 128.0);
    double ang = (double)s * inv;
    double sd, cd;
    sincos(ang, &sd, &cd);
    float c = (float)cd, sn = (float)sd;

    size_t base = ((size_t)h * S_LEN + s) * HDIM;
    float q1 = g_q[base + d], q2 = g_q[base + d + 64];
    g_q[base + d]      = q1 * c - q2 * sn;
    g_q[base + d + 64] = q2 * c + q1 * sn;
    float k1 = g_k[base + d], k2 = g_k[base + d + 64];
    g_k[base + d]      = k1 * c - k2 * sn;
    g_k[base + d + 64] = k2 * c + k1 * sn;
}

// ============================================================================
// Flash attention, fp32, causal. One block per (q-tile of 64 rows, head).
// Shared: Q^T [128][68], K^T [128][68], V [64][128], P^T [64][68], row stats.
// Thread (ti,tj) in 16x16: scores 4 rows x 4 cols; O 4 rows x 8 cols.
// ============================================================================
#define FA_SMEM_FLOATS (128 * 68 * 2 + 64 * 128 + 64 * 68 + 3 * 64)
#define FA_SMEM_BYTES  (FA_SMEM_FLOATS * 4)

__global__ __launch_bounds__(256, 1)
void flash_attn_kernel()
{
    extern __shared__ float smem[];
    float* sQ  = smem;                 // [128][68]  (Q^T)
    float* sK  = sQ  + 128 * 68;       // [128][68]  (K^T)
    float* sV  = sK  + 128 * 68;       // [64][128]
    float* sP  = sV  + 64 * 128;       // [64][68]   (P^T: [c][r])
    float* sM  = sP  + 64 * 68;        // [64]
    float* sL  = sM  + 64;             // [64]
    float* sAl = sL  + 64;             // [64]

    int qi  = blockIdx.x;     // 0..31
    int h   = blockIdx.y;     // 0..31
    int tid = threadIdx.x;
    int ti  = tid >> 4;       // rows r = 4*ti..+3
    int tj  = tid & 15;       // cols c = 4*tj..+3 (scores), d = 8*tj..+7 (O)
    const float scale = 0.08838834764831845f;   // 1/sqrt(128)

    // load Q tile transposed
    const float* Qg = g_q + ((size_t)h * S_LEN + (size_t)qi * 64) * HDIM;
    for (int u = tid; u < 64 * HDIM / 4; u += 256) {
        int r  = u >> 5;
        int ds = (u & 31) * 4;
        float4 v4 = *(const float4*)(Qg + r * HDIM + ds);
        sQ[(ds + 0) * 68 + r] = v4.x;
        sQ[(ds + 1) * 68 + r] = v4.y;
        sQ[(ds + 2) * 68 + r] = v4.z;
        sQ[(ds + 3) * 68 + r] = v4.w;
    }
    if (tid < 64) { sM[tid] = -INFINITY; sL[tid] = 0.0f; }

    float oacc[4][8];
#pragma unroll
    for (int i = 0; i < 4; i++)
#pragma unroll
        for (int j = 0; j < 8; j++) oacc[i][j] = 0.0f;

    int q0 = qi * 64;
    for (int kt = 0; kt <= qi; kt++) {
        __syncthreads();   // prev iter's P/V reads done (also covers Q/stat init)

        const float* Kg = g_k + ((size_t)h * S_LEN + (size_t)kt * 64) * HDIM;
        const float* Vg = g_v + ((size_t)h * S_LEN + (size_t)kt * 64) * HDIM;
        for (int u = tid; u < 64 * HDIM / 4; u += 256) {
            int c  = u >> 5;
            int ds = (u & 31) * 4;
            float4 v4 = *(const float4*)(Kg + c * HDIM + ds);
            sK[(ds + 0) * 68 + c] = v4.x;
            sK[(ds + 1) * 68 + c] = v4.y;
            sK[(ds + 2) * 68 + c] = v4.z;
            sK[(ds + 3) * 68 + c] = v4.w;
            ((float4*)sV)[u] = ((const float4*)Vg)[u];
        }
        __syncthreads();

        // ---- S = Q @ K^T ----
        float sacc[4][4];
#pragma unroll
        for (int i = 0; i < 4; i++)
#pragma unroll
            for (int j = 0; j < 4; j++) sacc[i][j] = 0.0f;
#pragma unroll 4
        for (int d = 0; d < HDIM; d++) {
            float4 a4 = *(const float4*)(sQ + d * 68 + ti * 4);
            float4 b4 = *(const float4*)(sK + d * 68 + tj * 4);
            float av[4] = {a4.x, a4.y, a4.z, a4.w};
            float bv[4] = {b4.x, b4.y, b4.z, b4.w};
#pragma unroll
            for (int i = 0; i < 4; i++)
#pragma unroll
                for (int j = 0; j < 4; j++)
                    sacc[i][j] = fmaf(av[i], bv[j], sacc[i][j]);
        }

        // ---- mask + scale, store P^T ----
        int k0 = kt * 64;
#pragma unroll
        for (int i = 0; i < 4; i++) {
            int gr = q0 + ti * 4 + i;
#pragma unroll
            for (int j = 0; j < 4; j++) {
                int gc = k0 + tj * 4 + j;
                float v = sacc[i][j] * scale;
                if (gc > gr) v = -INFINITY;
                sP[(tj * 4 + j) * 68 + (ti * 4 + i)] = v;
            }
        }
        __syncthreads();

        // ---- online softmax (one thread per row) ----
        if (tid < 64) {
            int r = tid;
            float mold = sM[r];
            float mx = mold;
            for (int c = 0; c < 64; c++) mx = fmaxf(mx, sP[c * 68 + r]);
            float alpha = expf(mold - mx);
            float lsum = 0.0f;
            for (int c = 0; c < 64; c++) {
                float p = expf(sP[c * 68 + r] - mx);
                sP[c * 68 + r] = p;
                lsum += p;
            }
            sM[r]  = mx;
            sL[r]  = sL[r] * alpha + lsum;
            sAl[r] = alpha;
        }
        __syncthreads();

        // ---- O = O*alpha + P @ V ----
        float al[4];
#pragma unroll
        for (int i = 0; i < 4; i++) al[i] = sAl[ti * 4 + i];
#pragma unroll
        for (int i = 0; i < 4; i++)
#pragma unroll
            for (int j = 0; j < 8; j++) oacc[i][j] *= al[i];

#pragma unroll 4
        for (int c = 0; c < 64; c++) {
            float4 p4 = *(const float4*)(sP + c * 68 + ti * 4);
            float4 v0 = *(const float4*)(sV + c * HDIM + tj * 8);
            float4 v1 = *(const float4*)(sV + c * HDIM + tj * 8 + 4);
            float pv[4] = {p4.x, p4.y, p4.z, p4.w};
            float vv[8] = {v0.x, v0.y, v0.z, v0.w, v1.x, v1.y, v1.z, v1.w};
#pragma unroll
            for (int i = 0; i < 4; i++)
#pragma unroll
                for (int j = 0; j < 8; j++)
                    oacc[i][j] = fmaf(pv[i], vv[j], oacc[i][j]);
        }
    }

    // ---- normalize and write O to [S][H] ----
#pragma unroll
    for (int i = 0; i < 4; i++) {
        int r = ti * 4 + i;
        float linv = 1.0f / sL[r];
        float* dst = g_o + (size_t)(q0 + r) * HID + h * HDIM + tj * 8;
        *(float4*)(dst)     = make_float4(oacc[i][0] * linv, oacc[i][1] * linv,
                                          oacc[i][2] * linv, oacc[i][3] * linv);
        *(float4*)(dst + 4) = make_float4(oacc[i][4] * linv, oacc[i][5] * linv,
                                          oacc[i][6] * linv, oacc[i][7] * linv);
    }
}

// ============================================================================
// KV eviction: out = concat(kv[:, :, :4], kv[:, :, S-204:]) -> [NH][208][HD]
// ============================================================================
__global__ void evict_kernel(float* __restrict__ outk, float* __restrict__ outv)
{
    int idx = blockIdx.x * blockDim.x + threadIdx.x;
    if (idx >= NHEAD * EVLEN * HDIM) return;
    int d = idx & 127;
    int t = (idx >> 7) % EVLEN;
    int h = idx / (EVLEN * HDIM);
    int src = (t < SINKN) ? t : (S_LEN - RECENT) + (t - SINKN);
    size_t si = ((size_t)h * S_LEN + src) * HDIM + d;
    outk[idx] = g_k[si];
    outv[idx] = g_v[si];
}

// ============================================================================
extern "C" void kernel_launch(void* const* d_in, const int* in_sizes, int n_in,
                              void* d_out, int out_size)
{
    const float* X  = (const float*)d_in[0];
    const float* Wq = (const float*)d_in[1];
    const float* Wk = (const float*)d_in[2];
    const float* Wv = (const float*)d_in[3];
    const float* Wo = (const float*)d_in[4];
    float* out = (float*)d_out;

    float *qb, *kb, *vb, *ob;
    cudaGetSymbolAddress((void**)&qb, g_q);
    cudaGetSymbolAddress((void**)&kb, g_k);
    cudaGetSymbolAddress((void**)&vb, g_v);
    cudaGetSymbolAddress((void**)&ob, g_o);

    dim3 gg(HID / 128, S_LEN / 128);   // (32, 16)

    // Q/K/V projections into heads layout
    sgemm_nt_kernel<1><<<gg, 256>>>(X, Wq, qb, S_LEN, HID, HID);
    sgemm_nt_kernel<1><<<gg, 256>>>(X, Wk, kb, S_LEN, HID, HID);
    sgemm_nt_kernel<1><<<gg, 256>>>(X, Wv, vb, S_LEN, HID, HID);

    // RoPE on q,k
    rope_kernel<<<(NHEAD * S_LEN * 64) / 256, 256>>>();

    // causal flash attention
    cudaFuncSetAttribute(flash_attn_kernel,
                         cudaFuncAttributeMaxDynamicSharedMemorySize, FA_SMEM_BYTES);
    flash_attn_kernel<<<dim3(S_LEN / 64, NHEAD), 256, FA_SMEM_BYTES>>>();

    // output projection directly into d_out
    sgemm_nt_kernel<0><<<gg, 256>>>(ob, Wo, out, S_LEN, HID, HID);

    // evicted KV cache
    size_t attn_elems = (size_t)S_LEN * HID;
    size_t ev_elems   = (size_t)NHEAD * EVLEN * HDIM;
    evict_kernel<<<(int)((ev_elems + 255) / 256), 256>>>(out + attn_elems,
                                                         out + attn_elems + ev_elems);
}

// round 3
// speedup vs baseline: 1.8474x; 1.8474x over previous
#include <cuda_runtime.h>
#include <cuda_bf16.h>
#include <math.h>
#include <stdint.h>

#define S_LEN  2048
#define HID    4096
#define NHEAD  32
#define HDIM   128
#define RECENT 204           // int(2048 * 0.1)
#define SINKN  4
#define EVLEN  (SINKN + RECENT)   // 208

#define KP     (3 * HID)     // 12288: split-K [hi|x|x]
#define NKIT   (KP / 32)     // 384 k-iterations of BK=32
#define LDT    40            // padded bf16 per smem row (80B, conflict-free)
#define STAGEB (128 * LDT * 2)          // 10240 B per operand per stage
#define GEMM_SMEM (4 * 2 * STAGEB)      // 81920 B (4 stages x (A+B))

// -------- scratch (static device arrays; no cudaMalloc allowed) -------------
static __device__ float g_q[NHEAD * S_LEN * HDIM];
static __device__ float g_k[NHEAD * S_LEN * HDIM];
static __device__ float g_v[NHEAD * S_LEN * HDIM];
static __device__ float g_o[S_LEN * HID];
static __device__ __nv_bfloat16 g_xp[(size_t)S_LEN * KP];
static __device__ __nv_bfloat16 g_wp[(size_t)HID * KP];
static __device__ float g_cosT[S_LEN * 64];
static __device__ float g_sinT[S_LEN * 64];

// ============================ helpers =======================================
__device__ __forceinline__ uint32_t smem_u32(const void* p) {
    uint32_t a;
    asm("{ .reg .u64 t; cvta.to.shared.u64 t, %1; cvt.u32.u64 %0, t; }"
        : "=r"(a) : "l"(p));
    return a;
}
#define CP_ASYNC16(dst, src) \
    asm volatile("cp.async.cg.shared.global [%0], [%1], 16;" \
                 :: "r"(dst), "l"(src) : "memory")
#define CP_COMMIT() asm volatile("cp.async.commit_group;" ::: "memory")
#define CP_WAIT2()  asm volatile("cp.async.wait_group 2;" ::: "memory")
#define CP_WAIT0()  asm volatile("cp.async.wait_group 0;" ::: "memory")

__device__ __forceinline__ uint32_t lds32(uint32_t addr) {
    uint32_t v;
    asm volatile("ld.shared.b32 %0, [%1];" : "=r"(v) : "r"(addr));
    return v;
}
__device__ __forceinline__ void mma16816(float* c, const uint32_t* a,
                                         const uint32_t* b) {
    asm volatile(
        "mma.sync.aligned.m16n8k16.row.col.f32.bf16.bf16.f32 "
        "{%0,%1,%2,%3}, {%4,%5,%6,%7}, {%8,%9}, {%0,%1,%2,%3};"
        : "+f"(c[0]), "+f"(c[1]), "+f"(c[2]), "+f"(c[3])
        : "r"(a[0]), "r"(a[1]), "r"(a[2]), "r"(a[3]), "r"(b[0]), "r"(b[1]));
}

// ============================================================================
// Split conversion: src [rows][4096] f32 -> dst [rows][12288] bf16
// modeA=1 (acts): [hi|hi|lo];  modeA=0 (weights): [hi|lo|hi]
// ============================================================================
__global__ void convert_split_kernel(const float* __restrict__ src,
                                     __nv_bfloat16* __restrict__ dst,
                                     int nquads, int modeA)
{
    int idx = blockIdx.x * blockDim.x + threadIdx.x;
    if (idx >= nquads) return;
    int r  = idx >> 10;
    int c4 = (idx & 1023) * 4;
    float4 x = *(const float4*)(src + (size_t)r * HID + c4);

    __nv_bfloat16 h0 = __float2bfloat16(x.x), h1 = __float2bfloat16(x.y);
    __nv_bfloat16 h2 = __float2bfloat16(x.z), h3 = __float2bfloat16(x.w);
    __nv_bfloat16 l0 = __float2bfloat16(x.x - __bfloat162float(h0));
    __nv_bfloat16 l1 = __float2bfloat16(x.y - __bfloat162float(h1));
    __nv_bfloat16 l2 = __float2bfloat16(x.z - __bfloat162float(h2));
    __nv_bfloat16 l3 = __float2bfloat16(x.w - __bfloat162float(h3));

    __nv_bfloat162 hA = __halves2bfloat162(h0, h1), hB = __halves2bfloat162(h2, h3);
    __nv_bfloat162 lA = __halves2bfloat162(l0, l1), lB = __halves2bfloat162(l2, l3);

    size_t base = (size_t)r * KP + c4;
    __nv_bfloat162* d0 = (__nv_bfloat162*)(dst + base);
    __nv_bfloat162* d1 = (__nv_bfloat162*)(dst + base + HID);
    __nv_bfloat162* d2 = (__nv_bfloat162*)(dst + base + 2 * HID);
    d0[0] = hA; d0[1] = hB;
    if (modeA) { d1[0] = hA; d1[1] = hB; d2[0] = lA; d2[1] = lB; }
    else       { d1[0] = lA; d1[1] = lB; d2[0] = hA; d2[1] = hB; }
}

// ============================================================================
// bf16 mma.sync GEMM: C[2048,4096] = A'[2048,KP] @ B'[4096,KP]^T, f32 accum.
// CTA 128x128, BK=32, 8 warps (4x2), warp tile 32x64, 4-stage cp.async.
// ============================================================================
template <int HEADS_LAYOUT>
__global__ __launch_bounds__(256, 1)
void mma_gemm_kernel(const __nv_bfloat16* __restrict__ Ap,
                     const __nv_bfloat16* __restrict__ Bp,
                     float* __restrict__ C)
{
    extern __shared__ char smem[];
    uint32_t sb = smem_u32(smem);

    int tid  = threadIdx.x;
    int wid  = tid >> 5, lane = tid & 31;
    int wm   = wid >> 1;          // 0..3: 32-row strip
    int wn   = wid & 1;           // 0..1: 64-col strip
    int m0   = blockIdx.x * 128;
    int n0   = blockIdx.y * 128;

    const char* Ag = (const char*)(Ap + (size_t)m0 * KP);
    const char* Bg = (const char*)(Bp + (size_t)n0 * KP);

    // per-thread cp.async assignments: u = tid + i*256, row=u>>2, chunk=u&3
    int r0g = tid >> 2,            c0g = (tid & 3) * 16;
    int r1g = (tid + 256) >> 2,    c1g = ((tid + 256) & 3) * 16;

    auto issue_stage = [&](int kt) {
        int buf = kt & 3;
        uint32_t sA = sb + (uint32_t)buf * (2 * STAGEB);
        uint32_t sB = sA + STAGEB;
        size_t koff = (size_t)kt * 64;   // BK=32 bf16 = 64 B
        CP_ASYNC16(sA + r0g * 80 + c0g, Ag + (size_t)r0g * (KP * 2) + koff + c0g);
        CP_ASYNC16(sA + r1g * 80 + c1g, Ag + (size_t)r1g * (KP * 2) + koff + c1g);
        CP_ASYNC16(sB + r0g * 80 + c0g, Bg + (size_t)r0g * (KP * 2) + koff + c0g);
        CP_ASYNC16(sB + r1g * 80 + c1g, Bg + (size_t)r1g * (KP * 2) + koff + c1g);
    };

    float acc[2][8][4];
#pragma unroll
    for (int i = 0; i < 2; i++)
#pragma unroll
        for (int j = 0; j < 8; j++)
#pragma unroll
            for (int q = 0; q < 4; q++) acc[i][j][q] = 0.0f;

    issue_stage(0); CP_COMMIT();
    issue_stage(1); CP_COMMIT();
    issue_stage(2); CP_COMMIT();

    // fragment base offsets (bytes) within a stage buffer
    uint32_t aoff = (uint32_t)((wm * 32 + (lane >> 2)) * 80 + (lane & 3) * 4);
    uint32_t boff = (uint32_t)((wn * 64 + (lane >> 2)) * 80 + (lane & 3) * 4);

#pragma unroll 1
    for (int kt = 0; kt < NKIT; kt++) {
        CP_WAIT2();
        __syncthreads();

        int buf = kt & 3;
        uint32_t sA = sb + (uint32_t)buf * (2 * STAGEB);
        uint32_t sB = sA + STAGEB;

#pragma unroll
        for (int ks = 0; ks < 2; ks++) {
            uint32_t kbyte = ks * 32;       // 16 bf16
            uint32_t a[2][4], b[8][2];
#pragma unroll
            for (int mt = 0; mt < 2; mt++) {
                uint32_t base = sA + aoff + mt * (16 * 80) + kbyte;
                a[mt][0] = lds32(base);
                a[mt][1] = lds32(base + 8 * 80);
                a[mt][2] = lds32(base + 16);
                a[mt][3] = lds32(base + 8 * 80 + 16);
            }
#pragma unroll
            for (int nt = 0; nt < 8; nt++) {
                uint32_t base = sB + boff + nt * (8 * 80) + kbyte;
                b[nt][0] = lds32(base);
                b[nt][1] = lds32(base + 16);
            }
#pragma unroll
            for (int mt = 0; mt < 2; mt++)
#pragma unroll
                for (int nt = 0; nt < 8; nt++)
                    mma16816(acc[mt][nt], a[mt], b[nt]);
        }

        if (kt + 3 < NKIT) issue_stage(kt + 3);
        CP_COMMIT();
    }
    CP_WAIT0();

    // ---- epilogue ----
#pragma unroll
    for (int mt = 0; mt < 2; mt++) {
        int row = m0 + wm * 32 + mt * 16 + (lane >> 2);
#pragma unroll
        for (int nt = 0; nt < 8; nt++) {
            int col = n0 + wn * 64 + nt * 8 + (lane & 3) * 2;
            float2 v01 = make_float2(acc[mt][nt][0], acc[mt][nt][1]);
            float2 v23 = make_float2(acc[mt][nt][2], acc[mt][nt][3]);
            if (HEADS_LAYOUT) {
                int hh = col >> 7, cc = col & 127;
                *(float2*)(C + ((size_t)hh * S_LEN + row) * HDIM + cc)       = v01;
                *(float2*)(C + ((size_t)hh * S_LEN + row + 8) * HDIM + cc)   = v23;
            } else {
                *(float2*)(C + (size_t)row * HID + col)       = v01;
                *(float2*)(C + (size_t)(row + 8) * HID + col) = v23;
            }
        }
    }
}

// ============================================================================
// RoPE: fp64 sincos table [S][64], then elementwise rotation of g_q/g_k.
// ============================================================================
__global__ void rope_table_kernel()
{
    int idx = blockIdx.x * blockDim.x + threadIdx.x;
    if (idx >= S_LEN * 64) return;
    int d = idx & 63;
    int s = idx >> 6;
    double inv = pow(10000.0, -(double)(2 * d) / 128.0);
    double sd, cd;
    sincos((double)s * inv, &sd, &cd);
    g_cosT[idx] = (float)cd;
    g_sinT[idx] = (float)sd;
}

__global__ void rope_kernel()
{
    int idx = blockIdx.x * blockDim.x + threadIdx.x;
    if (idx >= NHEAD * S_LEN * 64) return;
    int t = idx & (S_LEN * 64 - 1);
    int d = idx & 63;
    int s = (idx >> 6) & (S_LEN - 1);
    int h = idx >> 17;
    float c = g_cosT[t], sn = g_sinT[t];

    size_t base = ((size_t)h * S_LEN + s) * HDIM;
    float q1 = g_q[base + d], q2 = g_q[base + d + 64];
    g_q[base + d]      = q1 * c - q2 * sn;
    g_q[base + d + 64] = q2 * c + q1 * sn;
    float k1 = g_k[base + d], k2 = g_k[base + d + 64];
    g_k[base + d]      = k1 * c - k2 * sn;
    g_k[base + d + 64] = k2 * c + k1 * sn;
}

// ============================================================================
// Flash attention, fp32, causal (R1-verified; tensorize in a later round).
// ============================================================================
#define FA_SMEM_FLOATS (128 * 68 * 2 + 64 * 128 + 64 * 68 + 3 * 64)
#define FA_SMEM_BYTES  (FA_SMEM_FLOATS * 4)

__global__ __launch_bounds__(256, 1)
void flash_attn_kernel()
{
    extern __shared__ float fsm[];
    float* sQ  = fsm;
    float* sK  = sQ  + 128 * 68;
    float* sV  = sK  + 128 * 68;
    float* sP  = sV  + 64 * 128;
    float* sM  = sP  + 64 * 68;
    float* sL  = sM  + 64;
    float* sAl = sL  + 64;

    int qi  = blockIdx.x;
    int h   = blockIdx.y;
    int tid = threadIdx.x;
    int ti  = tid >> 4;
    int tj  = tid & 15;
    const float scale = 0.08838834764831845f;

    const float* Qg = g_q + ((size_t)h * S_LEN + (size_t)qi * 64) * HDIM;
    for (int u = tid; u < 64 * HDIM / 4; u += 256) {
        int r  = u >> 5;
        int ds = (u & 31) * 4;
        float4 v4 = *(const float4*)(Qg + r * HDIM + ds);
        sQ[(ds + 0) * 68 + r] = v4.x;
        sQ[(ds + 1) * 68 + r] = v4.y;
        sQ[(ds + 2) * 68 + r] = v4.z;
        sQ[(ds + 3) * 68 + r] = v4.w;
    }
    if (tid < 64) { sM[tid] = -INFINITY; sL[tid] = 0.0f; }

    float oacc[4][8];
#pragma unroll
    for (int i = 0; i < 4; i++)
#pragma unroll
        for (int j = 0; j < 8; j++) oacc[i][j] = 0.0f;

    int q0 = qi * 64;
    for (int kt = 0; kt <= qi; kt++) {
        __syncthreads();
        const float* Kg = g_k + ((size_t)h * S_LEN + (size_t)kt * 64) * HDIM;
        const float* Vg = g_v + ((size_t)h * S_LEN + (size_t)kt * 64) * HDIM;
        for (int u = tid; u < 64 * HDIM / 4; u += 256) {
            int c  = u >> 5;
            int ds = (u & 31) * 4;
            float4 v4 = *(const float4*)(Kg + c * HDIM + ds);
            sK[(ds + 0) * 68 + c] = v4.x;
            sK[(ds + 1) * 68 + c] = v4.y;
            sK[(ds + 2) * 68 + c] = v4.z;
            sK[(ds + 3) * 68 + c] = v4.w;
            ((float4*)sV)[u] = ((const float4*)Vg)[u];
        }
        __syncthreads();

        float sacc[4][4];
#pragma unroll
        for (int i = 0; i < 4; i++)
#pragma unroll
            for (int j = 0; j < 4; j++) sacc[i][j] = 0.0f;
#pragma unroll 4
        for (int d = 0; d < HDIM; d++) {
            float4 a4 = *(const float4*)(sQ + d * 68 + ti * 4);
            float4 b4 = *(const float4*)(sK + d * 68 + tj * 4);
            float av[4] = {a4.x, a4.y, a4.z, a4.w};
            float bv[4] = {b4.x, b4.y, b4.z, b4.w};
#pragma unroll
            for (int i = 0; i < 4; i++)
#pragma unroll
                for (int j = 0; j < 4; j++)
                    sacc[i][j] = fmaf(av[i], bv[j], sacc[i][j]);
        }

        int k0 = kt * 64;
#pragma unroll
        for (int i = 0; i < 4; i++) {
            int gr = q0 + ti * 4 + i;
#pragma unroll
            for (int j = 0; j < 4; j++) {
                int gc = k0 + tj * 4 + j;
                float v = sacc[i][j] * scale;
                if (gc > gr) v = -INFINITY;
                sP[(tj * 4 + j) * 68 + (ti * 4 + i)] = v;
            }
        }
        __syncthreads();

        if (tid < 64) {
            int r = tid;
            float mold = sM[r];
            float mx = mold;
            for (int c = 0; c < 64; c++) mx = fmaxf(mx, sP[c * 68 + r]);
            float alpha = expf(mold - mx);
            float lsum = 0.0f;
            for (int c = 0; c < 64; c++) {
                float p = expf(sP[c * 68 + r] - mx);
                sP[c * 68 + r] = p;
                lsum += p;
            }
            sM[r]  = mx;
            sL[r]  = sL[r] * alpha + lsum;
            sAl[r] = alpha;
        }
        __syncthreads();

        float al[4];
#pragma unroll
        for (int i = 0; i < 4; i++) al[i] = sAl[ti * 4 + i];
#pragma unroll
        for (int i = 0; i < 4; i++)
#pragma unroll
            for (int j = 0; j < 8; j++) oacc[i][j] *= al[i];

#pragma unroll 4
        for (int c = 0; c < 64; c++) {
            float4 p4 = *(const float4*)(sP + c * 68 + ti * 4);
            float4 v0 = *(const float4*)(sV + c * HDIM + tj * 8);
            float4 v1 = *(const float4*)(sV + c * HDIM + tj * 8 + 4);
            float pv[4] = {p4.x, p4.y, p4.z, p4.w};
            float vv[8] = {v0.x, v0.y, v0.z, v0.w, v1.x, v1.y, v1.z, v1.w};
#pragma unroll
            for (int i = 0; i < 4; i++)
#pragma unroll
                for (int j = 0; j < 8; j++)
                    oacc[i][j] = fmaf(pv[i], vv[j], oacc[i][j]);
        }
    }

#pragma unroll
    for (int i = 0; i < 4; i++) {
        int r = ti * 4 + i;
        float linv = 1.0f / sL[r];
        float* dst = g_o + (size_t)(q0 + r) * HID + h * HDIM + tj * 8;
        *(float4*)(dst)     = make_float4(oacc[i][0] * linv, oacc[i][1] * linv,
                                          oacc[i][2] * linv, oacc[i][3] * linv);
        *(float4*)(dst + 4) = make_float4(oacc[i][4] * linv, oacc[i][5] * linv,
                                          oacc[i][6] * linv, oacc[i][7] * linv);
    }
}

// ============================================================================
// KV eviction
// ============================================================================
__global__ void evict_kernel(float* __restrict__ outk, float* __restrict__ outv)
{
    int idx = blockIdx.x * blockDim.x + threadIdx.x;
    if (idx >= NHEAD * EVLEN * HDIM) return;
    int d = idx & 127;
    int t = (idx >> 7) % EVLEN;
    int h = idx / (EVLEN * HDIM);
    int src = (t < SINKN) ? t : (S_LEN - RECENT) + (t - SINKN);
    size_t si = ((size_t)h * S_LEN + src) * HDIM + d;
    outk[idx] = g_k[si];
    outv[idx] = g_v[si];
}

// ============================================================================
extern "C" void kernel_launch(void* const* d_in, const int* in_sizes, int n_in,
                              void* d_out, int out_size)
{
    const float* X  = (const float*)d_in[0];
    const float* Wq = (const float*)d_in[1];
    const float* Wk = (const float*)d_in[2];
    const float* Wv = (const float*)d_in[3];
    const float* Wo = (const float*)d_in[4];
    float* out = (float*)d_out;

    float *qb, *kb, *vb, *ob;
    __nv_bfloat16 *xp, *wp;
    cudaGetSymbolAddress((void**)&qb, g_q);
    cudaGetSymbolAddress((void**)&kb, g_k);
    cudaGetSymbolAddress((void**)&vb, g_v);
    cudaGetSymbolAddress((void**)&ob, g_o);
    cudaGetSymbolAddress((void**)&xp, g_xp);
    cudaGetSymbolAddress((void**)&wp, g_wp);

    cudaFuncSetAttribute(mma_gemm_kernel<1>,
                         cudaFuncAttributeMaxDynamicSharedMemorySize, GEMM_SMEM);
    cudaFuncSetAttribute(mma_gemm_kernel<0>,
                         cudaFuncAttributeMaxDynamicSharedMemorySize, GEMM_SMEM);
    cudaFuncSetAttribute(flash_attn_kernel,
                         cudaFuncAttributeMaxDynamicSharedMemorySize, FA_SMEM_BYTES);

    const int XQ = S_LEN * 1024;
    const int WQ = HID * 1024;
    dim3 gg(S_LEN / 128, HID / 128);   // (16, 32), m-tiles fastest

    rope_table_kernel<<<(S_LEN * 64 + 255) / 256, 256>>>();

    convert_split_kernel<<<(XQ + 255) / 256, 256>>>(X, xp, XQ, 1);

    convert_split_kernel<<<(WQ + 255) / 256, 256>>>(Wq, wp, WQ, 0);
    mma_gemm_kernel<1><<<gg, 256, GEMM_SMEM>>>(xp, wp, qb);

    convert_split_kernel<<<(WQ + 255) / 256, 256>>>(Wk, wp, WQ, 0);
    mma_gemm_kernel<1><<<gg, 256, GEMM_SMEM>>>(xp, wp, kb);

    convert_split_kernel<<<(WQ + 255) / 256, 256>>>(Wv, wp, WQ, 0);
    mma_gemm_kernel<1><<<gg, 256, GEMM_SMEM>>>(xp, wp, vb);

    rope_kernel<<<(NHEAD * S_LEN * 64) / 256, 256>>>();

    flash_attn_kernel<<<dim3(S_LEN / 64, NHEAD), 256, FA_SMEM_BYTES>>>();

    convert_split_kernel<<<(XQ + 255) / 256, 256>>>(ob, xp, XQ, 1);
    convert_split_kernel<<<(WQ + 255) / 256, 256>>>(Wo, wp, WQ, 0);
    mma_gemm_kernel<0><<<gg, 256, GEMM_SMEM>>>(xp, wp, out);

    size_t attn_elems = (size_t)S_LEN * HID;
    size_t ev_elems   = (size_t)NHEAD * EVLEN * HDIM;
    evict_kernel<<<(int)((ev_elems + 255) / 256), 256>>>(out + attn_elems,
                                                         out + attn_elems + ev_elems);
}

// round 4
// speedup vs baseline: 2.0504x; 1.1099x over previous
#include <cuda_runtime.h>
#include <cuda_bf16.h>
#include <math.h>
#include <stdint.h>

#define S_LEN  2048
#define HID    4096
#define NHEAD  32
#define HDIM   128
#define RECENT 204
#define SINKN  4
#define EVLEN  (SINKN + RECENT)   // 208

#define KP     (3 * HID)     // 12288 split-K
#define NKIT   (KP / 32)     // 384
#define STAGEB (128 * 40 * 2)           // 10240 B per operand per stage
#define GEMM_SMEM (4 * 2 * STAGEB)      // 81920 B

// flash tiles: 272 B per smem row (136 bf16), 64 rows per tile
#define FT     272
#define FTILE  (64 * FT)               // 17408
#define FA_SMEM (11 * FTILE + 1024)    // 192512

// -------- static scratch --------
static __device__ float g_q[NHEAD * S_LEN * HDIM];
static __device__ float g_k[NHEAD * S_LEN * HDIM];
static __device__ float g_v[NHEAD * S_LEN * HDIM];
static __device__ float g_o[S_LEN * HID];
static __device__ __nv_bfloat16 g_xp[(size_t)S_LEN * KP];
static __device__ __nv_bfloat16 g_wp[(size_t)HID * KP];
static __device__ __nv_bfloat16 g_qh[NHEAD * S_LEN * HDIM];
static __device__ __nv_bfloat16 g_ql[NHEAD * S_LEN * HDIM];
static __device__ __nv_bfloat16 g_kh[NHEAD * S_LEN * HDIM];
static __device__ __nv_bfloat16 g_kl[NHEAD * S_LEN * HDIM];
static __device__ __nv_bfloat16 g_vh[NHEAD * S_LEN * HDIM];
static __device__ __nv_bfloat16 g_vl[NHEAD * S_LEN * HDIM];
static __device__ float g_cosT[S_LEN * 64];
static __device__ float g_sinT[S_LEN * 64];

// ============================ helpers =======================================
__device__ __forceinline__ uint32_t smem_u32(const void* p) {
    uint32_t a;
    asm("{ .reg .u64 t; cvta.to.shared.u64 t, %1; cvt.u32.u64 %0, t; }"
        : "=r"(a) : "l"(p));
    return a;
}
#define CP_ASYNC16(dst, src) \
    asm volatile("cp.async.cg.shared.global [%0], [%1], 16;" \
                 :: "r"(dst), "l"(src) : "memory")
#define CP_COMMIT() asm volatile("cp.async.commit_group;" ::: "memory")
#define CP_WAIT2()  asm volatile("cp.async.wait_group 2;" ::: "memory")
#define CP_WAIT0()  asm volatile("cp.async.wait_group 0;" ::: "memory")
#define LDSM4(r0, r1, r2, r3, addr) \
    asm volatile("ldmatrix.sync.aligned.m8n8.x4.shared.b16 {%0,%1,%2,%3}, [%4];" \
                 : "=r"(r0), "=r"(r1), "=r"(r2), "=r"(r3) : "r"(addr))
#define LDSM4T(r0, r1, r2, r3, addr) \
    asm volatile("ldmatrix.sync.aligned.m8n8.x4.trans.shared.b16 {%0,%1,%2,%3}, [%4];" \
                 : "=r"(r0), "=r"(r1), "=r"(r2), "=r"(r3) : "r"(addr))
#define STS32(addr, v) \
    asm volatile("st.shared.b32 [%0], %1;" :: "r"(addr), "r"(v) : "memory")

__device__ __forceinline__ void mma16816(float* c, const uint32_t* a,
                                         const uint32_t* b) {
    asm volatile(
        "mma.sync.aligned.m16n8k16.row.col.f32.bf16.bf16.f32 "
        "{%0,%1,%2,%3}, {%4,%5,%6,%7}, {%8,%9}, {%0,%1,%2,%3};"
        : "+f"(c[0]), "+f"(c[1]), "+f"(c[2]), "+f"(c[3])
        : "r"(a[0]), "r"(a[1]), "r"(a[2]), "r"(a[3]), "r"(b[0]), "r"(b[1]));
}
__device__ __forceinline__ uint32_t packbf2(float x, float y) {
    __nv_bfloat162 t = __halves2bfloat162(__float2bfloat16(x), __float2bfloat16(y));
    return *(uint32_t*)&t;
}

// ============================================================================
// Split conversion for GEMM operands (3-segment layout)
// ============================================================================
__global__ void convert_split_kernel(const float* __restrict__ src,
                                     __nv_bfloat16* __restrict__ dst,
                                     int nquads, int modeA)
{
    int idx = blockIdx.x * blockDim.x + threadIdx.x;
    if (idx >= nquads) return;
    int r  = idx >> 10;
    int c4 = (idx & 1023) * 4;
    float4 x = *(const float4*)(src + (size_t)r * HID + c4);

    __nv_bfloat16 h0 = __float2bfloat16(x.x), h1 = __float2bfloat16(x.y);
    __nv_bfloat16 h2 = __float2bfloat16(x.z), h3 = __float2bfloat16(x.w);
    __nv_bfloat16 l0 = __float2bfloat16(x.x - __bfloat162float(h0));
    __nv_bfloat16 l1 = __float2bfloat16(x.y - __bfloat162float(h1));
    __nv_bfloat16 l2 = __float2bfloat16(x.z - __bfloat162float(h2));
    __nv_bfloat16 l3 = __float2bfloat16(x.w - __bfloat162float(h3));

    __nv_bfloat162 hA = __halves2bfloat162(h0, h1), hB = __halves2bfloat162(h2, h3);
    __nv_bfloat162 lA = __halves2bfloat162(l0, l1), lB = __halves2bfloat162(l2, l3);

    size_t base = (size_t)r * KP + c4;
    __nv_bfloat162* d0 = (__nv_bfloat162*)(dst + base);
    __nv_bfloat162* d1 = (__nv_bfloat162*)(dst + base + HID);
    __nv_bfloat162* d2 = (__nv_bfloat162*)(dst + base + 2 * HID);
    d0[0] = hA; d0[1] = hB;
    if (modeA) { d1[0] = hA; d1[1] = hB; d2[0] = lA; d2[1] = lB; }
    else       { d1[0] = lA; d1[1] = lB; d2[0] = hA; d2[1] = hB; }
}

// ============================================================================
// bf16 mma.sync GEMM (ldmatrix fragments). CTA 128x128, BK=32, 8 warps.
// ============================================================================
template <int HEADS_LAYOUT>
__global__ __launch_bounds__(256, 1)
void mma_gemm_kernel(const __nv_bfloat16* __restrict__ Ap,
                     const __nv_bfloat16* __restrict__ Bp,
                     float* __restrict__ C)
{
    extern __shared__ char smem[];
    uint32_t sb = smem_u32(smem);

    int tid  = threadIdx.x;
    int wid  = tid >> 5, lane = tid & 31;
    int wm   = wid >> 1;
    int wn   = wid & 1;
    int m0   = blockIdx.x * 128;
    int n0   = blockIdx.y * 128;

    const char* Ag = (const char*)(Ap + (size_t)m0 * KP);
    const char* Bg = (const char*)(Bp + (size_t)n0 * KP);

    int r0g = tid >> 2,            c0g = (tid & 3) * 16;
    int r1g = (tid + 256) >> 2,    c1g = ((tid + 256) & 3) * 16;

    auto issue_stage = [&](int kt) {
        int buf = kt & 3;
        uint32_t sA = sb + (uint32_t)buf * (2 * STAGEB);
        uint32_t sB = sA + STAGEB;
        size_t koff = (size_t)kt * 64;
        CP_ASYNC16(sA + r0g * 80 + c0g, Ag + (size_t)r0g * (KP * 2) + koff + c0g);
        CP_ASYNC16(sA + r1g * 80 + c1g, Ag + (size_t)r1g * (KP * 2) + koff + c1g);
        CP_ASYNC16(sB + r0g * 80 + c0g, Bg + (size_t)r0g * (KP * 2) + koff + c0g);
        CP_ASYNC16(sB + r1g * 80 + c1g, Bg + (size_t)r1g * (KP * 2) + koff + c1g);
    };

    float acc[2][8][4];
#pragma unroll
    for (int i = 0; i < 2; i++)
#pragma unroll
        for (int j = 0; j < 8; j++)
#pragma unroll
            for (int q = 0; q < 4; q++) acc[i][j][q] = 0.0f;

    issue_stage(0); CP_COMMIT();
    issue_stage(1); CP_COMMIT();
    issue_stage(2); CP_COMMIT();

    // ldmatrix lane bases (byte offsets within stage buffer)
    uint32_t aL = (uint32_t)((wm * 32 + (lane & 15)) * 80 + (lane >> 4) * 16);
    uint32_t bL = (uint32_t)((wn * 64 + (lane >> 4) * 8 + (lane & 7)) * 80
                             + ((lane >> 3) & 1) * 16);

#pragma unroll 1
    for (int kt = 0; kt < NKIT; kt++) {
        CP_WAIT2();
        __syncthreads();

        int buf = kt & 3;
        uint32_t sA = sb + (uint32_t)buf * (2 * STAGEB);
        uint32_t sB = sA + STAGEB;

#pragma unroll
        for (int ks = 0; ks < 2; ks++) {
            uint32_t kbyte = ks * 32;
            uint32_t a[2][4], b[8][2];
            LDSM4(a[0][0], a[0][1], a[0][2], a[0][3], sA + aL + kbyte);
            LDSM4(a[1][0], a[1][1], a[1][2], a[1][3], sA + aL + 16 * 80 + kbyte);
#pragma unroll
            for (int t = 0; t < 4; t++)
                LDSM4(b[2 * t][0], b[2 * t][1], b[2 * t + 1][0], b[2 * t + 1][1],
                      sB + bL + t * 16 * 80 + kbyte);
#pragma unroll
            for (int mt = 0; mt < 2; mt++)
#pragma unroll
                for (int nt = 0; nt < 8; nt++)
                    mma16816(acc[mt][nt], a[mt], b[nt]);
        }

        if (kt + 3 < NKIT) issue_stage(kt + 3);
        CP_COMMIT();
    }
    CP_WAIT0();

#pragma unroll
    for (int mt = 0; mt < 2; mt++) {
        int row = m0 + wm * 32 + mt * 16 + (lane >> 2);
#pragma unroll
        for (int nt = 0; nt < 8; nt++) {
            int col = n0 + wn * 64 + nt * 8 + (lane & 3) * 2;
            float2 v01 = make_float2(acc[mt][nt][0], acc[mt][nt][1]);
            float2 v23 = make_float2(acc[mt][nt][2], acc[mt][nt][3]);
            if (HEADS_LAYOUT) {
                int hh = col >> 7, cc = col & 127;
                *(float2*)(C + ((size_t)hh * S_LEN + row) * HDIM + cc)     = v01;
                *(float2*)(C + ((size_t)hh * S_LEN + row + 8) * HDIM + cc) = v23;
            } else {
                *(float2*)(C + (size_t)row * HID + col)       = v01;
                *(float2*)(C + (size_t)(row + 8) * HID + col) = v23;
            }
        }
    }
}

// ============================================================================
// RoPE
// ============================================================================
__global__ void rope_table_kernel()
{
    int idx = blockIdx.x * blockDim.x + threadIdx.x;
    if (idx >= S_LEN * 64) return;
    int d = idx & 63;
    int s = idx >> 6;
    double inv = pow(10000.0, -(double)(2 * d) / 128.0);
    double sd, cd;
    sincos((double)s * inv, &sd, &cd);
    g_cosT[idx] = (float)cd;
    g_sinT[idx] = (float)sd;
}

__global__ void rope_kernel()
{
    int idx = blockIdx.x * blockDim.x + threadIdx.x;
    if (idx >= NHEAD * S_LEN * 64) return;
    int t = idx & (S_LEN * 64 - 1);
    int d = idx & 63;
    int s = (idx >> 6) & (S_LEN - 1);
    int h = idx >> 17;
    float c = g_cosT[t], sn = g_sinT[t];

    size_t base = ((size_t)h * S_LEN + s) * HDIM;
    float q1 = g_q[base + d], q2 = g_q[base + d + 64];
    g_q[base + d]      = q1 * c - q2 * sn;
    g_q[base + d + 64] = q2 * c + q1 * sn;
    float k1 = g_k[base + d], k2 = g_k[base + d + 64];
    g_k[base + d]      = k1 * c - k2 * sn;
    g_k[base + d + 64] = k2 * c + k1 * sn;
}

// ============================================================================
// Split q (scaled by 1/sqrt(HD)), k, v into hi/lo bf16 arrays for flash.
// ============================================================================
__global__ void convert_qkv_kernel()
{
    int idx = blockIdx.x * blockDim.x + threadIdx.x;
    if (idx >= NHEAD * S_LEN * HDIM / 4) return;
    size_t e = (size_t)idx * 4;
    const float scale = 0.08838834764831845f;

    float4 q = *(const float4*)(g_q + e);
    q.x *= scale; q.y *= scale; q.z *= scale; q.w *= scale;
    float4 k = *(const float4*)(g_k + e);
    float4 v = *(const float4*)(g_v + e);

    float* qp = &q.x; float* kp = &k.x; float* vp = &v.x;
    __nv_bfloat16 qh[4], ql[4], kh[4], kl[4], vh[4], vl[4];
#pragma unroll
    for (int i = 0; i < 4; i++) {
        qh[i] = __float2bfloat16(qp[i]); ql[i] = __float2bfloat16(qp[i] - __bfloat162float(qh[i]));
        kh[i] = __float2bfloat16(kp[i]); kl[i] = __float2bfloat16(kp[i] - __bfloat162float(kh[i]));
        vh[i] = __float2bfloat16(vp[i]); vl[i] = __float2bfloat16(vp[i] - __bfloat162float(vh[i]));
    }
    *(__nv_bfloat162*)(g_qh + e)     = __halves2bfloat162(qh[0], qh[1]);
    *(__nv_bfloat162*)(g_qh + e + 2) = __halves2bfloat162(qh[2], qh[3]);
    *(__nv_bfloat162*)(g_ql + e)     = __halves2bfloat162(ql[0], ql[1]);
    *(__nv_bfloat162*)(g_ql + e + 2) = __halves2bfloat162(ql[2], ql[3]);
    *(__nv_bfloat162*)(g_kh + e)     = __halves2bfloat162(kh[0], kh[1]);
    *(__nv_bfloat162*)(g_kh + e + 2) = __halves2bfloat162(kh[2], kh[3]);
    *(__nv_bfloat162*)(g_kl + e)     = __halves2bfloat162(kl[0], kl[1]);
    *(__nv_bfloat162*)(g_kl + e + 2) = __halves2bfloat162(kl[2], kl[3]);
    *(__nv_bfloat162*)(g_vh + e)     = __halves2bfloat162(vh[0], vh[1]);
    *(__nv_bfloat162*)(g_vh + e + 2) = __halves2bfloat162(vh[2], vh[3]);
    *(__nv_bfloat162*)(g_vl + e)     = __halves2bfloat162(vl[0], vl[1]);
    *(__nv_bfloat162*)(g_vl + e + 2) = __halves2bfloat162(vl[2], vl[3]);
}

// ============================================================================
// Tensorized flash attention. Br=Bc=64, 8 warps (4 row-strips x 2 col-halves).
// Split-bf16 3-term for both QK^T and P.V; K/V double-buffered cp.async.
// ============================================================================
__global__ __launch_bounds__(256, 1)
void flash_mma_kernel()
{
    extern __shared__ char smem[];
    uint32_t sb   = smem_u32(smem);
    uint32_t sQh  = sb;
    uint32_t sQl  = sb + FTILE;
    uint32_t sKh0 = sb + 2 * FTILE;   // [2]
    uint32_t sKl0 = sb + 4 * FTILE;   // [2]
    uint32_t sVh0 = sb + 6 * FTILE;   // [2]
    uint32_t sVl0 = sb + 8 * FTILE;   // [2]
    uint32_t sP   = sb + 10 * FTILE;
    float* sMx = (float*)(smem + 11 * FTILE);         // [2][64]
    float* sSm = (float*)(smem + 11 * FTILE + 512);   // [2][64]

    int qb  = 31 - blockIdx.x;        // long blocks first
    int h   = blockIdx.y;
    int tid = threadIdx.x, wid = tid >> 5, lane = tid & 31;
    int wm  = wid >> 1, wn = wid & 1;
    int q0  = qb * 64;

    const __nv_bfloat16* qhp = g_qh + ((size_t)h * S_LEN + q0) * HDIM;
    const __nv_bfloat16* qlp = g_ql + ((size_t)h * S_LEN + q0) * HDIM;
    const __nv_bfloat16* khp = g_kh + (size_t)h * S_LEN * HDIM;
    const __nv_bfloat16* klp = g_kl + (size_t)h * S_LEN * HDIM;
    const __nv_bfloat16* vhp = g_vh + (size_t)h * S_LEN * HDIM;
    const __nv_bfloat16* vlp = g_vl + (size_t)h * S_LEN * HDIM;

    auto load_tile = [&](int kt, int bb) {
        uint32_t dKh = sKh0 + (uint32_t)bb * FTILE, dKl = sKl0 + (uint32_t)bb * FTILE;
        uint32_t dVh = sVh0 + (uint32_t)bb * FTILE, dVl = sVl0 + (uint32_t)bb * FTILE;
        const __nv_bfloat16* s1 = khp + (size_t)kt * 64 * HDIM;
        const __nv_bfloat16* s2 = klp + (size_t)kt * 64 * HDIM;
        const __nv_bfloat16* s3 = vhp + (size_t)kt * 64 * HDIM;
        const __nv_bfloat16* s4 = vlp + (size_t)kt * 64 * HDIM;
#pragma unroll
        for (int i = 0; i < 4; i++) {
            int u = tid + i * 256;
            int r = u >> 4, cb = (u & 15) * 16, ce = (u & 15) * 8;
            CP_ASYNC16(dKh + r * FT + cb, s1 + r * HDIM + ce);
            CP_ASYNC16(dKl + r * FT + cb, s2 + r * HDIM + ce);
            CP_ASYNC16(dVh + r * FT + cb, s3 + r * HDIM + ce);
            CP_ASYNC16(dVl + r * FT + cb, s4 + r * HDIM + ce);
        }
    };

    // preload Q and tile 0 (one group)
#pragma unroll
    for (int i = 0; i < 4; i++) {
        int u = tid + i * 256;
        int r = u >> 4, cb = (u & 15) * 16, ce = (u & 15) * 8;
        CP_ASYNC16(sQh + r * FT + cb, qhp + r * HDIM + ce);
        CP_ASYNC16(sQl + r * FT + cb, qlp + r * HDIM + ce);
    }
    load_tile(0, 0);
    CP_COMMIT();

    float oacc[8][4];
#pragma unroll
    for (int i = 0; i < 8; i++)
#pragma unroll
        for (int j = 0; j < 4; j++) oacc[i][j] = 0.0f;
    float m0 = -INFINITY, m1 = -INFINITY, l0 = 0.0f, l1 = 0.0f;

    uint32_t aLq = (uint32_t)((wm * 16 + (lane & 15)) * FT + (lane >> 4) * 16);
    uint32_t bLk = (uint32_t)((wn * 32 + (lane >> 4) * 8 + (lane & 7)) * FT
                              + ((lane >> 3) & 1) * 16);
    uint32_t vLb = (uint32_t)((lane & 15) * FT + wn * 128 + (lane >> 4) * 16);
    int r0 = wm * 16 + (lane >> 2);

#pragma unroll 1
    for (int kt = 0; kt <= qb; kt++) {
        int b = kt & 1;
        CP_WAIT0();
        __syncthreads();
        if (kt < qb) { load_tile(kt + 1, b ^ 1); CP_COMMIT(); }

        uint32_t Kh = sKh0 + (uint32_t)b * FTILE, Kl = sKl0 + (uint32_t)b * FTILE;
        uint32_t Vh = sVh0 + (uint32_t)b * FTILE, Vl = sVl0 + (uint32_t)b * FTILE;

        // ---- scores: 3 split segments x 8 k-steps ----
        float sacc[4][4];
#pragma unroll
        for (int i = 0; i < 4; i++)
#pragma unroll
            for (int j = 0; j < 4; j++) sacc[i][j] = 0.0f;
#pragma unroll
        for (int seg = 0; seg < 3; seg++) {
            uint32_t Ab = (seg < 2 ? sQh : sQl) + aLq;
            uint32_t Bb = (seg == 1 ? Kl : Kh) + bLk;
#pragma unroll
            for (int ks = 0; ks < 8; ks++) {
                uint32_t a[4], x[4], y[4];
                LDSM4(a[0], a[1], a[2], a[3], Ab + ks * 32);
                LDSM4(x[0], x[1], x[2], x[3], Bb + ks * 32);
                LDSM4(y[0], y[1], y[2], y[3], Bb + 16 * FT + ks * 32);
                mma16816(sacc[0], a, &x[0]);
                mma16816(sacc[1], a, &x[2]);
                mma16816(sacc[2], a, &y[0]);
                mma16816(sacc[3], a, &y[2]);
            }
        }

        // ---- causal mask on diagonal tile ----
        if (kt == qb) {
#pragma unroll
            for (int nt = 0; nt < 4; nt++) {
                int lc = wn * 32 + nt * 8 + (lane & 3) * 2;
                int rr0 = r0, rr1 = r0 + 8;
                if (lc     > rr0) sacc[nt][0] = -INFINITY;
                if (lc + 1 > rr0) sacc[nt][1] = -INFINITY;
                if (lc     > rr1) sacc[nt][2] = -INFINITY;
                if (lc + 1 > rr1) sacc[nt][3] = -INFINITY;
            }
        }

        // ---- online softmax ----
        float tm0 = -INFINITY, tm1 = -INFINITY;
#pragma unroll
        for (int nt = 0; nt < 4; nt++) {
            tm0 = fmaxf(tm0, fmaxf(sacc[nt][0], sacc[nt][1]));
            tm1 = fmaxf(tm1, fmaxf(sacc[nt][2], sacc[nt][3]));
        }
        tm0 = fmaxf(tm0, __shfl_xor_sync(0xffffffffu, tm0, 1));
        tm0 = fmaxf(tm0, __shfl_xor_sync(0xffffffffu, tm0, 2));
        tm1 = fmaxf(tm1, __shfl_xor_sync(0xffffffffu, tm1, 1));
        tm1 = fmaxf(tm1, __shfl_xor_sync(0xffffffffu, tm1, 2));
        if ((lane & 3) == 0) {
            sMx[wn * 64 + r0]     = tm0;
            sMx[wn * 64 + r0 + 8] = tm1;
        }
        __syncthreads();

        float mn0 = fmaxf(m0, fmaxf(sMx[r0], sMx[64 + r0]));
        float mn1 = fmaxf(m1, fmaxf(sMx[r0 + 8], sMx[64 + r0 + 8]));
        float al0 = __expf(m0 - mn0), al1 = __expf(m1 - mn1);
        m0 = mn0; m1 = mn1;

        float s0 = 0.0f, s1 = 0.0f;
#pragma unroll
        for (int nt = 0; nt < 4; nt++) {
            float p0 = __expf(sacc[nt][0] - mn0);
            float p1 = __expf(sacc[nt][1] - mn0);
            float p2 = __expf(sacc[nt][2] - mn1);
            float p3 = __expf(sacc[nt][3] - mn1);
            s0 += p0 + p1; s1 += p2 + p3;

            uint32_t hi01 = packbf2(p0, p1);
            uint32_t hi23 = packbf2(p2, p3);
            __nv_bfloat162 th0 = *(__nv_bfloat162*)&hi01;
            __nv_bfloat162 th1 = *(__nv_bfloat162*)&hi23;
            uint32_t lo01 = packbf2(p0 - __bfloat162float(th0.x),
                                    p1 - __bfloat162float(th0.y));
            uint32_t lo23 = packbf2(p2 - __bfloat162float(th1.x),
                                    p3 - __bfloat162float(th1.y));

            uint32_t colb = (uint32_t)((wn * 32 + nt * 8 + (lane & 3) * 2) * 2);
            uint32_t a0 = sP + (uint32_t)r0 * FT + colb;
            uint32_t a1 = sP + (uint32_t)(r0 + 8) * FT + colb;
            STS32(a0, hi01);
            STS32(a0 + 128, lo01);
            STS32(a1, hi23);
            STS32(a1 + 128, lo23);
        }
        s0 += __shfl_xor_sync(0xffffffffu, s0, 1);
        s0 += __shfl_xor_sync(0xffffffffu, s0, 2);
        s1 += __shfl_xor_sync(0xffffffffu, s1, 1);
        s1 += __shfl_xor_sync(0xffffffffu, s1, 2);
        if ((lane & 3) == 0) {
            sSm[wn * 64 + r0]     = s0;
            sSm[wn * 64 + r0 + 8] = s1;
        }
        __syncthreads();

        l0 = l0 * al0 + sSm[r0] + sSm[64 + r0];
        l1 = l1 * al1 + sSm[r0 + 8] + sSm[64 + r0 + 8];

#pragma unroll
        for (int dt = 0; dt < 8; dt++) {
            oacc[dt][0] *= al0; oacc[dt][1] *= al0;
            oacc[dt][2] *= al1; oacc[dt][3] *= al1;
        }

        // ---- P.V: 3 split segments x 4 k-steps ----
#pragma unroll
        for (int seg = 0; seg < 3; seg++) {
            uint32_t Ab = sP + aLq + (seg == 2 ? 128u : 0u);
            uint32_t Bb = (seg == 1 ? Vl : Vh) + vLb;
#pragma unroll
            for (int ks = 0; ks < 4; ks++) {
                uint32_t a[4];
                LDSM4(a[0], a[1], a[2], a[3], Ab + ks * 32);
#pragma unroll
                for (int dp = 0; dp < 4; dp++) {
                    uint32_t bv[4];
                    LDSM4T(bv[0], bv[1], bv[2], bv[3],
                           Bb + (uint32_t)(ks * 16) * FT + dp * 32);
                    mma16816(oacc[2 * dp],     a, &bv[0]);
                    mma16816(oacc[2 * dp + 1], a, &bv[2]);
                }
            }
        }
    }

    // ---- finalize ----
    float inv0 = 1.0f / l0, inv1 = 1.0f / l1;
    int grow0 = q0 + r0;
#pragma unroll
    for (int dt = 0; dt < 8; dt++) {
        int col = h * HDIM + wn * 64 + dt * 8 + (lane & 3) * 2;
        *(float2*)(g_o + (size_t)grow0 * HID + col) =
            make_float2(oacc[dt][0] * inv0, oacc[dt][1] * inv0);
        *(float2*)(g_o + (size_t)(grow0 + 8) * HID + col) =
            make_float2(oacc[dt][2] * inv1, oacc[dt][3] * inv1);
    }
}

// ============================================================================
// KV eviction
// ============================================================================
__global__ void evict_kernel(float* __restrict__ outk, float* __restrict__ outv)
{
    int idx = blockIdx.x * blockDim.x + threadIdx.x;
    if (idx >= NHEAD * EVLEN * HDIM) return;
    int d = idx & 127;
    int t = (idx >> 7) % EVLEN;
    int h = idx / (EVLEN * HDIM);
    int src = (t < SINKN) ? t : (S_LEN - RECENT) + (t - SINKN);
    size_t si = ((size_t)h * S_LEN + src) * HDIM + d;
    outk[idx] = g_k[si];
    outv[idx] = g_v[si];
}

// ============================================================================
extern "C" void kernel_launch(void* const* d_in, const int* in_sizes, int n_in,
                              void* d_out, int out_size)
{
    const float* X  = (const float*)d_in[0];
    const float* Wq = (const float*)d_in[1];
    const float* Wk = (const float*)d_in[2];
    const float* Wv = (const float*)d_in[3];
    const float* Wo = (const float*)d_in[4];
    float* out = (float*)d_out;

    float *qb, *kb, *vb, *ob;
    __nv_bfloat16 *xp, *wp;
    cudaGetSymbolAddress((void**)&qb, g_q);
    cudaGetSymbolAddress((void**)&kb, g_k);
    cudaGetSymbolAddress((void**)&vb, g_v);
    cudaGetSymbolAddress((void**)&ob, g_o);
    cudaGetSymbolAddress((void**)&xp, g_xp);
    cudaGetSymbolAddress((void**)&wp, g_wp);

    cudaFuncSetAttribute(mma_gemm_kernel<1>,
                         cudaFuncAttributeMaxDynamicSharedMemorySize, GEMM_SMEM);
    cudaFuncSetAttribute(mma_gemm_kernel<0>,
                         cudaFuncAttributeMaxDynamicSharedMemorySize, GEMM_SMEM);
    cudaFuncSetAttribute(flash_mma_kernel,
                         cudaFuncAttributeMaxDynamicSharedMemorySize, FA_SMEM);

    const int XQ = S_LEN * 1024;
    const int WQ = HID * 1024;
    const int EQ = NHEAD * S_LEN * HDIM / 4;
    dim3 gg(S_LEN / 128, HID / 128);

    rope_table_kernel<<<(S_LEN * 64 + 255) / 256, 256>>>();

    convert_split_kernel<<<(XQ + 255) / 256, 256>>>(X, xp, XQ, 1);

    convert_split_kernel<<<(WQ + 255) / 256, 256>>>(Wq, wp, WQ, 0);
    mma_gemm_kernel<1><<<gg, 256, GEMM_SMEM>>>(xp, wp, qb);

    convert_split_kernel<<<(WQ + 255) / 256, 256>>>(Wk, wp, WQ, 0);
    mma_gemm_kernel<1><<<gg, 256, GEMM_SMEM>>>(xp, wp, kb);

    convert_split_kernel<<<(WQ + 255) / 256, 256>>>(Wv, wp, WQ, 0);
    mma_gemm_kernel<1><<<gg, 256, GEMM_SMEM>>>(xp, wp, vb);

    rope_kernel<<<(NHEAD * S_LEN * 64) / 256, 256>>>();
    convert_qkv_kernel<<<(EQ + 255) / 256, 256>>>();

    flash_mma_kernel<<<dim3(32, 32), 256, FA_SMEM>>>();

    convert_split_kernel<<<(XQ + 255) / 256, 256>>>(ob, xp, XQ, 1);
    convert_split_kernel<<<(WQ + 255) / 256, 256>>>(Wo, wp, WQ, 0);
    mma_gemm_kernel<0><<<gg, 256, GEMM_SMEM>>>(xp, wp, out);

    size_t attn_elems = (size_t)S_LEN * HID;
    size_t ev_elems   = (size_t)NHEAD * EVLEN * HDIM;
    evict_kernel<<<(int)((ev_elems + 255) / 256), 256>>>(out + attn_elems,
                                                         out + attn_elems + ev_elems);
}

// round 5
// speedup vs baseline: 2.8559x; 1.3928x over previous
#include <cuda_runtime.h>
#include <cuda_bf16.h>
#include <math.h>
#include <stdint.h>

#define S_LEN  2048
#define HID    4096
#define NHEAD  32
#define HDIM   128
#define RECENT 204
#define SINKN  4
#define EVLEN  (SINKN + RECENT)   // 208

#define KP     (3 * HID)     // 12288 split-K
#define NKIT   (KP / 32)     // 384
#define STAGEB (128 * 40 * 2)           // 10240 B per operand per stage
#define GEMM_SMEM (4 * 2 * STAGEB)      // 81920 B

// flash tiles: 272 B per smem row (136 bf16), 64 rows per tile
#define FT     272
#define FTILE  (64 * FT)               // 17408
#define FA_SMEM (11 * FTILE + 1024)    // 192512

// -------- static scratch --------
static __device__ float g_q[NHEAD * S_LEN * HDIM];
static __device__ float g_k[NHEAD * S_LEN * HDIM];
static __device__ float g_v[NHEAD * S_LEN * HDIM];
static __device__ float g_o[S_LEN * HID];
static __device__ __nv_bfloat16 g_xp[(size_t)S_LEN * KP];
static __device__ __nv_bfloat16 g_wp[3ULL * HID * KP];   // QKV weights merged
static __device__ __nv_bfloat16 g_qh[NHEAD * S_LEN * HDIM];
static __device__ __nv_bfloat16 g_ql[NHEAD * S_LEN * HDIM];
static __device__ __nv_bfloat16 g_kh[NHEAD * S_LEN * HDIM];
static __device__ __nv_bfloat16 g_kl[NHEAD * S_LEN * HDIM];
static __device__ __nv_bfloat16 g_vh[NHEAD * S_LEN * HDIM];
static __device__ __nv_bfloat16 g_vl[NHEAD * S_LEN * HDIM];
static __device__ float g_cosT[S_LEN * 64];
static __device__ float g_sinT[S_LEN * 64];

// ============================ helpers =======================================
__device__ __forceinline__ uint32_t smem_u32(const void* p) {
    uint32_t a;
    asm("{ .reg .u64 t; cvta.to.shared.u64 t, %1; cvt.u32.u64 %0, t; }"
        : "=r"(a) : "l"(p));
    return a;
}
#define CP_ASYNC16(dst, src) \
    asm volatile("cp.async.cg.shared.global [%0], [%1], 16;" \
                 :: "r"(dst), "l"(src) : "memory")
#define CP_COMMIT() asm volatile("cp.async.commit_group;" ::: "memory")
#define CP_WAIT2()  asm volatile("cp.async.wait_group 2;" ::: "memory")
#define CP_WAIT0()  asm volatile("cp.async.wait_group 0;" ::: "memory")
#define LDSM4(r0, r1, r2, r3, addr) \
    asm volatile("ldmatrix.sync.aligned.m8n8.x4.shared.b16 {%0,%1,%2,%3}, [%4];" \
                 : "=r"(r0), "=r"(r1), "=r"(r2), "=r"(r3) : "r"(addr))
#define LDSM4T(r0, r1, r2, r3, addr) \
    asm volatile("ldmatrix.sync.aligned.m8n8.x4.trans.shared.b16 {%0,%1,%2,%3}, [%4];" \
                 : "=r"(r0), "=r"(r1), "=r"(r2), "=r"(r3) : "r"(addr))
#define STS32(addr, v) \
    asm volatile("st.shared.b32 [%0], %1;" :: "r"(addr), "r"(v) : "memory")

__device__ __forceinline__ void mma16816(float* c, const uint32_t* a,
                                         const uint32_t* b) {
    asm volatile(
        "mma.sync.aligned.m16n8k16.row.col.f32.bf16.bf16.f32 "
        "{%0,%1,%2,%3}, {%4,%5,%6,%7}, {%8,%9}, {%0,%1,%2,%3};"
        : "+f"(c[0]), "+f"(c[1]), "+f"(c[2]), "+f"(c[3])
        : "r"(a[0]), "r"(a[1]), "r"(a[2]), "r"(a[3]), "r"(b[0]), "r"(b[1]));
}
__device__ __forceinline__ uint32_t packbf2(float x, float y) {
    __nv_bfloat162 t = __halves2bfloat162(__float2bfloat16(x), __float2bfloat16(y));
    return *(uint32_t*)&t;
}

// ============================================================================
// Split conversion for GEMM operands (3-segment layout along K)
// ============================================================================
__global__ void convert_split_kernel(const float* __restrict__ src,
                                     __nv_bfloat16* __restrict__ dst,
                                     int nquads, int modeA)
{
    int idx = blockIdx.x * blockDim.x + threadIdx.x;
    if (idx >= nquads) return;
    int r  = idx >> 10;
    int c4 = (idx & 1023) * 4;
    float4 x = *(const float4*)(src + (size_t)r * HID + c4);

    __nv_bfloat16 h0 = __float2bfloat16(x.x), h1 = __float2bfloat16(x.y);
    __nv_bfloat16 h2 = __float2bfloat16(x.z), h3 = __float2bfloat16(x.w);
    __nv_bfloat16 l0 = __float2bfloat16(x.x - __bfloat162float(h0));
    __nv_bfloat16 l1 = __float2bfloat16(x.y - __bfloat162float(h1));
    __nv_bfloat16 l2 = __float2bfloat16(x.z - __bfloat162float(h2));
    __nv_bfloat16 l3 = __float2bfloat16(x.w - __bfloat162float(h3));

    __nv_bfloat162 hA = __halves2bfloat162(h0, h1), hB = __halves2bfloat162(h2, h3);
    __nv_bfloat162 lA = __halves2bfloat162(l0, l1), lB = __halves2bfloat162(l2, l3);

    size_t base = (size_t)r * KP + c4;
    __nv_bfloat162* d0 = (__nv_bfloat162*)(dst + base);
    __nv_bfloat162* d1 = (__nv_bfloat162*)(dst + base + HID);
    __nv_bfloat162* d2 = (__nv_bfloat162*)(dst + base + 2 * HID);
    d0[0] = hA; d0[1] = hB;
    if (modeA) { d1[0] = hA; d1[1] = hB; d2[0] = lA; d2[1] = lB; }
    else       { d1[0] = lA; d1[1] = lB; d2[0] = hA; d2[1] = hB; }
}

// ============================================================================
// bf16 mma.sync GEMM (ldmatrix fragments). CTA 128x128, BK=32, 8 warps,
// forced 2 CTAs/SM. QKV=1: write heads layout into g_q/g_k/g_v (tile's
// N-block selects buffer+head); QKV=0: row-major C.
// ============================================================================
template <int QKV>
__global__ __launch_bounds__(256, 2)
void mma_gemm_kernel(const __nv_bfloat16* __restrict__ Ap,
                     const __nv_bfloat16* __restrict__ Bp,
                     float* __restrict__ Cq, float* __restrict__ Ck,
                     float* __restrict__ Cv)
{
    extern __shared__ char smem[];
    uint32_t sb = smem_u32(smem);

    int tid  = threadIdx.x;
    int wid  = tid >> 5, lane = tid & 31;
    int wm   = wid >> 1;
    int wn   = wid & 1;
    int m0   = blockIdx.x * 128;
    int n0   = blockIdx.y * 128;

    const char* Ag = (const char*)(Ap + (size_t)m0 * KP);
    const char* Bg = (const char*)(Bp + (size_t)n0 * KP);

    int r0g = tid >> 2,            c0g = (tid & 3) * 16;
    int r1g = (tid + 256) >> 2,    c1g = ((tid + 256) & 3) * 16;

    auto issue_stage = [&](int kt) {
        int buf = kt & 3;
        uint32_t sA = sb + (uint32_t)buf * (2 * STAGEB);
        uint32_t sB = sA + STAGEB;
        size_t koff = (size_t)kt * 64;
        CP_ASYNC16(sA + r0g * 80 + c0g, Ag + (size_t)r0g * (KP * 2) + koff + c0g);
        CP_ASYNC16(sA + r1g * 80 + c1g, Ag + (size_t)r1g * (KP * 2) + koff + c1g);
        CP_ASYNC16(sB + r0g * 80 + c0g, Bg + (size_t)r0g * (KP * 2) + koff + c0g);
        CP_ASYNC16(sB + r1g * 80 + c1g, Bg + (size_t)r1g * (KP * 2) + koff + c1g);
    };

    float acc[2][8][4];
#pragma unroll
    for (int i = 0; i < 2; i++)
#pragma unroll
        for (int j = 0; j < 8; j++)
#pragma unroll
            for (int q = 0; q < 4; q++) acc[i][j][q] = 0.0f;

    issue_stage(0); CP_COMMIT();
    issue_stage(1); CP_COMMIT();
    issue_stage(2); CP_COMMIT();

    uint32_t aL = (uint32_t)((wm * 32 + (lane & 15)) * 80 + (lane >> 4) * 16);
    uint32_t bL = (uint32_t)((wn * 64 + (lane >> 4) * 8 + (lane & 7)) * 80
                             + ((lane >> 3) & 1) * 16);

#pragma unroll 1
    for (int kt = 0; kt < NKIT; kt++) {
        CP_WAIT2();
        __syncthreads();

        int buf = kt & 3;
        uint32_t sA = sb + (uint32_t)buf * (2 * STAGEB);
        uint32_t sB = sA + STAGEB;

#pragma unroll
        for (int ks = 0; ks < 2; ks++) {
            uint32_t kbyte = ks * 32;
            uint32_t a[2][4], b[8][2];
            LDSM4(a[0][0], a[0][1], a[0][2], a[0][3], sA + aL + kbyte);
            LDSM4(a[1][0], a[1][1], a[1][2], a[1][3], sA + aL + 16 * 80 + kbyte);
#pragma unroll
            for (int t = 0; t < 4; t++)
                LDSM4(b[2 * t][0], b[2 * t][1], b[2 * t + 1][0], b[2 * t + 1][1],
                      sB + bL + t * 16 * 80 + kbyte);
#pragma unroll
            for (int mt = 0; mt < 2; mt++)
#pragma unroll
                for (int nt = 0; nt < 8; nt++)
                    mma16816(acc[mt][nt], a[mt], b[nt]);
        }

        if (kt + 3 < NKIT) issue_stage(kt + 3);
        CP_COMMIT();
    }
    CP_WAIT0();

    // epilogue: whole CTA tile maps to one buffer + one head when QKV=1
    float* base;
    int hh = 0;
    if (QKV) {
        int bsel = n0 >> 12;
        base = (bsel == 0) ? Cq : ((bsel == 1) ? Ck : Cv);
        hh = (n0 & 4095) >> 7;
    } else {
        base = Cq;
    }

#pragma unroll
    for (int mt = 0; mt < 2; mt++) {
        int row = m0 + wm * 32 + mt * 16 + (lane >> 2);
#pragma unroll
        for (int nt = 0; nt < 8; nt++) {
            int col = n0 + wn * 64 + nt * 8 + (lane & 3) * 2;
            float2 v01 = make_float2(acc[mt][nt][0], acc[mt][nt][1]);
            float2 v23 = make_float2(acc[mt][nt][2], acc[mt][nt][3]);
            if (QKV) {
                int cc = col & 127;
                *(float2*)(base + ((size_t)hh * S_LEN + row) * HDIM + cc)     = v01;
                *(float2*)(base + ((size_t)hh * S_LEN + row + 8) * HDIM + cc) = v23;
            } else {
                *(float2*)(base + (size_t)row * HID + col)       = v01;
                *(float2*)(base + (size_t)(row + 8) * HID + col) = v23;
            }
        }
    }
}

// ============================================================================
// RoPE table (fp64 angles)
// ============================================================================
__global__ void rope_table_kernel()
{
    int idx = blockIdx.x * blockDim.x + threadIdx.x;
    if (idx >= S_LEN * 64) return;
    int d = idx & 63;
    int s = idx >> 6;
    double inv = pow(10000.0, -(double)(2 * d) / 128.0);
    double sd, cd;
    sincos((double)s * inv, &sd, &cd);
    g_cosT[idx] = (float)cd;
    g_sinT[idx] = (float)sd;
}

// ============================================================================
// Fused rope + split: rotate q (scaled by 1/sqrt(HD)) and k, write k back
// (fp32, for eviction), emit hi/lo bf16 splits of q,k,v for flash.
// ============================================================================
__global__ void rope_split_kernel()
{
    int idx = blockIdx.x * blockDim.x + threadIdx.x;
    if (idx >= NHEAD * S_LEN * 64) return;
    int t = idx & (S_LEN * 64 - 1);
    int d = idx & 63;
    int s = (idx >> 6) & (S_LEN - 1);
    int h = idx >> 17;
    float c = g_cosT[t], sn = g_sinT[t];
    const float scale = 0.08838834764831845f;

    size_t base = ((size_t)h * S_LEN + s) * HDIM;
    float q1 = g_q[base + d], q2 = g_q[base + d + 64];
    float k1 = g_k[base + d], k2 = g_k[base + d + 64];
    float v1 = g_v[base + d], v2 = g_v[base + d + 64];

    float qr1 = (q1 * c - q2 * sn) * scale;
    float qr2 = (q2 * c + q1 * sn) * scale;
    float kr1 = k1 * c - k2 * sn;
    float kr2 = k2 * c + k1 * sn;

    g_k[base + d]      = kr1;     // post-rope k for eviction output
    g_k[base + d + 64] = kr2;

    float vals[6] = {qr1, qr2, kr1, kr2, v1, v2};
    __nv_bfloat16* dsts[6][2] = {
        {g_qh + base + d, g_ql + base + d},
        {g_qh + base + d + 64, g_ql + base + d + 64},
        {g_kh + base + d, g_kl + base + d},
        {g_kh + base + d + 64, g_kl + base + d + 64},
        {g_vh + base + d, g_vl + base + d},
        {g_vh + base + d + 64, g_vl + base + d + 64}};
#pragma unroll
    for (int i = 0; i < 6; i++) {
        __nv_bfloat16 hi = __float2bfloat16(vals[i]);
        __nv_bfloat16 lo = __float2bfloat16(vals[i] - __bfloat162float(hi));
        *dsts[i][0] = hi;
        *dsts[i][1] = lo;
    }
}

// ============================================================================
// Tensorized flash attention (unchanged from R4 — verified).
// ============================================================================
__global__ __launch_bounds__(256, 1)
void flash_mma_kernel()
{
    extern __shared__ char smem[];
    uint32_t sb   = smem_u32(smem);
    uint32_t sQh  = sb;
    uint32_t sQl  = sb + FTILE;
    uint32_t sKh0 = sb + 2 * FTILE;
    uint32_t sKl0 = sb + 4 * FTILE;
    uint32_t sVh0 = sb + 6 * FTILE;
    uint32_t sVl0 = sb + 8 * FTILE;
    uint32_t sP   = sb + 10 * FTILE;
    float* sMx = (float*)(smem + 11 * FTILE);
    float* sSm = (float*)(smem + 11 * FTILE + 512);

    int qb  = 31 - blockIdx.x;
    int h   = blockIdx.y;
    int tid = threadIdx.x, wid = tid >> 5, lane = tid & 31;
    int wm  = wid >> 1, wn = wid & 1;
    int q0  = qb * 64;

    const __nv_bfloat16* qhp = g_qh + ((size_t)h * S_LEN + q0) * HDIM;
    const __nv_bfloat16* qlp = g_ql + ((size_t)h * S_LEN + q0) * HDIM;
    const __nv_bfloat16* khp = g_kh + (size_t)h * S_LEN * HDIM;
    const __nv_bfloat16* klp = g_kl + (size_t)h * S_LEN * HDIM;
    const __nv_bfloat16* vhp = g_vh + (size_t)h * S_LEN * HDIM;
    const __nv_bfloat16* vlp = g_vl + (size_t)h * S_LEN * HDIM;

    auto load_tile = [&](int kt, int bb) {
        uint32_t dKh = sKh0 + (uint32_t)bb * FTILE, dKl = sKl0 + (uint32_t)bb * FTILE;
        uint32_t dVh = sVh0 + (uint32_t)bb * FTILE, dVl = sVl0 + (uint32_t)bb * FTILE;
        const __nv_bfloat16* s1 = khp + (size_t)kt * 64 * HDIM;
        const __nv_bfloat16* s2 = klp + (size_t)kt * 64 * HDIM;
        const __nv_bfloat16* s3 = vhp + (size_t)kt * 64 * HDIM;
        const __nv_bfloat16* s4 = vlp + (size_t)kt * 64 * HDIM;
#pragma unroll
        for (int i = 0; i < 4; i++) {
            int u = tid + i * 256;
            int r = u >> 4, cb = (u & 15) * 16, ce = (u & 15) * 8;
            CP_ASYNC16(dKh + r * FT + cb, s1 + r * HDIM + ce);
            CP_ASYNC16(dKl + r * FT + cb, s2 + r * HDIM + ce);
            CP_ASYNC16(dVh + r * FT + cb, s3 + r * HDIM + ce);
            CP_ASYNC16(dVl + r * FT + cb, s4 + r * HDIM + ce);
        }
    };

#pragma unroll
    for (int i = 0; i < 4; i++) {
        int u = tid + i * 256;
        int r = u >> 4, cb = (u & 15) * 16, ce = (u & 15) * 8;
        CP_ASYNC16(sQh + r * FT + cb, qhp + r * HDIM + ce);
        CP_ASYNC16(sQl + r * FT + cb, qlp + r * HDIM + ce);
    }
    load_tile(0, 0);
    CP_COMMIT();

    float oacc[8][4];
#pragma unroll
    for (int i = 0; i < 8; i++)
#pragma unroll
        for (int j = 0; j < 4; j++) oacc[i][j] = 0.0f;
    float m0 = -INFINITY, m1 = -INFINITY, l0 = 0.0f, l1 = 0.0f;

    uint32_t aLq = (uint32_t)((wm * 16 + (lane & 15)) * FT + (lane >> 4) * 16);
    uint32_t bLk = (uint32_t)((wn * 32 + (lane >> 4) * 8 + (lane & 7)) * FT
                              + ((lane >> 3) & 1) * 16);
    uint32_t vLb = (uint32_t)((lane & 15) * FT + wn * 128 + (lane >> 4) * 16);
    int r0 = wm * 16 + (lane >> 2);

#pragma unroll 1
    for (int kt = 0; kt <= qb; kt++) {
        int b = kt & 1;
        CP_WAIT0();
        __syncthreads();
        if (kt < qb) { load_tile(kt + 1, b ^ 1); CP_COMMIT(); }

        uint32_t Kh = sKh0 + (uint32_t)b * FTILE, Kl = sKl0 + (uint32_t)b * FTILE;
        uint32_t Vh = sVh0 + (uint32_t)b * FTILE, Vl = sVl0 + (uint32_t)b * FTILE;

        float sacc[4][4];
#pragma unroll
        for (int i = 0; i < 4; i++)
#pragma unroll
            for (int j = 0; j < 4; j++) sacc[i][j] = 0.0f;
#pragma unroll
        for (int seg = 0; seg < 3; seg++) {
            uint32_t Ab = (seg < 2 ? sQh : sQl) + aLq;
            uint32_t Bb = (seg == 1 ? Kl : Kh) + bLk;
#pragma unroll
            for (int ks = 0; ks < 8; ks++) {
                uint32_t a[4], x[4], y[4];
                LDSM4(a[0], a[1], a[2], a[3], Ab + ks * 32);
                LDSM4(x[0], x[1], x[2], x[3], Bb + ks * 32);
                LDSM4(y[0], y[1], y[2], y[3], Bb + 16 * FT + ks * 32);
                mma16816(sacc[0], a, &x[0]);
                mma16816(sacc[1], a, &x[2]);
                mma16816(sacc[2], a, &y[0]);
                mma16816(sacc[3], a, &y[2]);
            }
        }

        if (kt == qb) {
#pragma unroll
            for (int nt = 0; nt < 4; nt++) {
                int lc = wn * 32 + nt * 8 + (lane & 3) * 2;
                int rr0 = r0, rr1 = r0 + 8;
                if (lc     > rr0) sacc[nt][0] = -INFINITY;
                if (lc + 1 > rr0) sacc[nt][1] = -INFINITY;
                if (lc     > rr1) sacc[nt][2] = -INFINITY;
                if (lc + 1 > rr1) sacc[nt][3] = -INFINITY;
            }
        }

        float tm0 = -INFINITY, tm1 = -INFINITY;
#pragma unroll
        for (int nt = 0; nt < 4; nt++) {
            tm0 = fmaxf(tm0, fmaxf(sacc[nt][0], sacc[nt][1]));
            tm1 = fmaxf(tm1, fmaxf(sacc[nt][2], sacc[nt][3]));
        }
        tm0 = fmaxf(tm0, __shfl_xor_sync(0xffffffffu, tm0, 1));
        tm0 = fmaxf(tm0, __shfl_xor_sync(0xffffffffu, tm0, 2));
        tm1 = fmaxf(tm1, __shfl_xor_sync(0xffffffffu, tm1, 1));
        tm1 = fmaxf(tm1, __shfl_xor_sync(0xffffffffu, tm1, 2));
        if ((lane & 3) == 0) {
            sMx[wn * 64 + r0]     = tm0;
            sMx[wn * 64 + r0 + 8] = tm1;
        }
        __syncthreads();

        float mn0 = fmaxf(m0, fmaxf(sMx[r0], sMx[64 + r0]));
        float mn1 = fmaxf(m1, fmaxf(sMx[r0 + 8], sMx[64 + r0 + 8]));
        float al0 = __expf(m0 - mn0), al1 = __expf(m1 - mn1);
        m0 = mn0; m1 = mn1;

        float s0 = 0.0f, s1 = 0.0f;
#pragma unroll
        for (int nt = 0; nt < 4; nt++) {
            float p0 = __expf(sacc[nt][0] - mn0);
            float p1 = __expf(sacc[nt][1] - mn0);
            float p2 = __expf(sacc[nt][2] - mn1);
            float p3 = __expf(sacc[nt][3] - mn1);
            s0 += p0 + p1; s1 += p2 + p3;

            uint32_t hi01 = packbf2(p0, p1);
            uint32_t hi23 = packbf2(p2, p3);
            __nv_bfloat162 th0 = *(__nv_bfloat162*)&hi01;
            __nv_bfloat162 th1 = *(__nv_bfloat162*)&hi23;
            uint32_t lo01 = packbf2(p0 - __bfloat162float(th0.x),
                                    p1 - __bfloat162float(th0.y));
            uint32_t lo23 = packbf2(p2 - __bfloat162float(th1.x),
                                    p3 - __bfloat162float(th1.y));

            uint32_t colb = (uint32_t)((wn * 32 + nt * 8 + (lane & 3) * 2) * 2);
            uint32_t a0 = sP + (uint32_t)r0 * FT + colb;
            uint32_t a1 = sP + (uint32_t)(r0 + 8) * FT + colb;
            STS32(a0, hi01);
            STS32(a0 + 128, lo01);
            STS32(a1, hi23);
            STS32(a1 + 128, lo23);
        }
        s0 += __shfl_xor_sync(0xffffffffu, s0, 1);
        s0 += __shfl_xor_sync(0xffffffffu, s0, 2);
        s1 += __shfl_xor_sync(0xffffffffu, s1, 1);
        s1 += __shfl_xor_sync(0xffffffffu, s1, 2);
        if ((lane & 3) == 0) {
            sSm[wn * 64 + r0]     = s0;
            sSm[wn * 64 + r0 + 8] = s1;
        }
        __syncthreads();

        l0 = l0 * al0 + sSm[r0] + sSm[64 + r0];
        l1 = l1 * al1 + sSm[r0 + 8] + sSm[64 + r0 + 8];

#pragma unroll
        for (int dt = 0; dt < 8; dt++) {
            oacc[dt][0] *= al0; oacc[dt][1] *= al0;
            oacc[dt][2] *= al1; oacc[dt][3] *= al1;
        }

#pragma unroll
        for (int seg = 0; seg < 3; seg++) {
            uint32_t Ab = sP + aLq + (seg == 2 ? 128u : 0u);
            uint32_t Bb = (seg == 1 ? Vl : Vh) + vLb;
#pragma unroll
            for (int ks = 0; ks < 4; ks++) {
                uint32_t a[4];
                LDSM4(a[0], a[1], a[2], a[3], Ab + ks * 32);
#pragma unroll
                for (int dp = 0; dp < 4; dp++) {
                    uint32_t bv[4];
                    LDSM4T(bv[0], bv[1], bv[2], bv[3],
                           Bb + (uint32_t)(ks * 16) * FT + dp * 32);
                    mma16816(oacc[2 * dp],     a, &bv[0]);
                    mma16816(oacc[2 * dp + 1], a, &bv[2]);
                }
            }
        }
    }

    float inv0 = 1.0f / l0, inv1 = 1.0f / l1;
    int grow0 = q0 + r0;
#pragma unroll
    for (int dt = 0; dt < 8; dt++) {
        int col = h * HDIM + wn * 64 + dt * 8 + (lane & 3) * 2;
        *(float2*)(g_o + (size_t)grow0 * HID + col) =
            make_float2(oacc[dt][0] * inv0, oacc[dt][1] * inv0);
        *(float2*)(g_o + (size_t)(grow0 + 8) * HID + col) =
            make_float2(oacc[dt][2] * inv1, oacc[dt][3] * inv1);
    }
}

// ============================================================================
// KV eviction
// ============================================================================
__global__ void evict_kernel(float* __restrict__ outk, float* __restrict__ outv)
{
    int idx = blockIdx.x * blockDim.x + threadIdx.x;
    if (idx >= NHEAD * EVLEN * HDIM) return;
    int d = idx & 127;
    int t = (idx >> 7) % EVLEN;
    int h = idx / (EVLEN * HDIM);
    int src = (t < SINKN) ? t : (S_LEN - RECENT) + (t - SINKN);
    size_t si = ((size_t)h * S_LEN + src) * HDIM + d;
    outk[idx] = g_k[si];
    outv[idx] = g_v[si];
}

// ============================================================================
extern "C" void kernel_launch(void* const* d_in, const int* in_sizes, int n_in,
                              void* d_out, int out_size)
{
    const float* X  = (const float*)d_in[0];
    const float* Wq = (const float*)d_in[1];
    const float* Wk = (const float*)d_in[2];
    const float* Wv = (const float*)d_in[3];
    const float* Wo = (const float*)d_in[4];
    float* out = (float*)d_out;

    float *qb, *kb, *vb, *ob;
    __nv_bfloat16 *xp, *wp;
    cudaGetSymbolAddress((void**)&qb, g_q);
    cudaGetSymbolAddress((void**)&kb, g_k);
    cudaGetSymbolAddress((void**)&vb, g_v);
    cudaGetSymbolAddress((void**)&ob, g_o);
    cudaGetSymbolAddress((void**)&xp, g_xp);
    cudaGetSymbolAddress((void**)&wp, g_wp);

    cudaFuncSetAttribute(mma_gemm_kernel<1>,
                         cudaFuncAttributeMaxDynamicSharedMemorySize, GEMM_SMEM);
    cudaFuncSetAttribute(mma_gemm_kernel<0>,
                         cudaFuncAttributeMaxDynamicSharedMemorySize, GEMM_SMEM);
    cudaFuncSetAttribute(flash_mma_kernel,
                         cudaFuncAttributeMaxDynamicSharedMemorySize, FA_SMEM);

    const int XQ = S_LEN * 1024;
    const int WQ = HID * 1024;
    const size_t WSEG = (size_t)HID * KP;

    rope_table_kernel<<<(S_LEN * 64 + 255) / 256, 256>>>();

    // operand conversions
    convert_split_kernel<<<(XQ + 255) / 256, 256>>>(X, xp, XQ, 1);
    convert_split_kernel<<<(WQ + 255) / 256, 256>>>(Wq, wp,            WQ, 0);
    convert_split_kernel<<<(WQ + 255) / 256, 256>>>(Wk, wp + WSEG,     WQ, 0);
    convert_split_kernel<<<(WQ + 255) / 256, 256>>>(Wv, wp + 2 * WSEG, WQ, 0);

    // merged QKV projection: N = 12288
    dim3 gqkv(S_LEN / 128, (3 * HID) / 128);   // (16, 96)
    mma_gemm_kernel<1><<<gqkv, 256, GEMM_SMEM>>>(xp, wp, qb, kb, vb);

    // fused rope + flash-operand split
    rope_split_kernel<<<(NHEAD * S_LEN * 64) / 256, 256>>>();

    flash_mma_kernel<<<dim3(32, 32), 256, FA_SMEM>>>();

    // output projection
    convert_split_kernel<<<(XQ + 255) / 256, 256>>>(ob, xp, XQ, 1);
    convert_split_kernel<<<(WQ + 255) / 256, 256>>>(Wo, wp, WQ, 0);
    dim3 go(S_LEN / 128, HID / 128);           // (16, 32)
    mma_gemm_kernel<0><<<go, 256, GEMM_SMEM>>>(xp, wp, out, out, out);

    size_t attn_elems = (size_t)S_LEN * HID;
    size_t ev_elems   = (size_t)NHEAD * EVLEN * HDIM;
    evict_kernel<<<(int)((ev_elems + 255) / 256), 256>>>(out + attn_elems,
                                                         out + attn_elems + ev_elems);
}

// round 6
// speedup vs baseline: 2.9421x; 1.0302x over previous
#include <cuda_runtime.h>
#include <cuda_bf16.h>
#include <math.h>
#include <stdint.h>

#define S_LEN  2048
#define HID    4096
#define NHEAD  32
#define HDIM   128
#define RECENT 204
#define SINKN  4
#define EVLEN  (SINKN + RECENT)   // 208

#define KP     (3 * HID)     // 12288 split-K
#define NKIT   (KP / 32)     // 384
#define STAGEB (128 * 40 * 2)           // 10240 B per operand per stage
#define GEMM_SMEM (4 * 2 * STAGEB)      // 81920 B

// flash smem: 272 B per row (128 bf16 + pad)
#define FT     272
#define FTILE  (64 * FT)                // 17408 (K/V tiles, 64 rows)
#define FQ     (128 * FT)               // 34816 (Q tiles, 128 rows)
#define FA_SMEM (2 * FQ + 8 * FTILE)    // 208896

// -------- static scratch --------
static __device__ float g_q[NHEAD * S_LEN * HDIM];
static __device__ float g_k[NHEAD * S_LEN * HDIM];
static __device__ float g_v[NHEAD * S_LEN * HDIM];
static __device__ __nv_bfloat16 g_xp[(size_t)S_LEN * KP];
static __device__ __nv_bfloat16 g_wp[4ULL * HID * KP];   // Wq|Wk|Wv|Wo
static __device__ __nv_bfloat16 g_qh[NHEAD * S_LEN * HDIM];
static __device__ __nv_bfloat16 g_ql[NHEAD * S_LEN * HDIM];
static __device__ __nv_bfloat16 g_kh[NHEAD * S_LEN * HDIM];
static __device__ __nv_bfloat16 g_kl[NHEAD * S_LEN * HDIM];
static __device__ __nv_bfloat16 g_vh[NHEAD * S_LEN * HDIM];
static __device__ __nv_bfloat16 g_vl[NHEAD * S_LEN * HDIM];
static __device__ float g_cosT[S_LEN * 64];
static __device__ float g_sinT[S_LEN * 64];

// ============================ helpers =======================================
__device__ __forceinline__ uint32_t smem_u32(const void* p) {
    uint32_t a;
    asm("{ .reg .u64 t; cvta.to.shared.u64 t, %1; cvt.u32.u64 %0, t; }"
        : "=r"(a) : "l"(p));
    return a;
}
#define CP_ASYNC16(dst, src) \
    asm volatile("cp.async.cg.shared.global [%0], [%1], 16;" \
                 :: "r"(dst), "l"(src) : "memory")
#define CP_COMMIT() asm volatile("cp.async.commit_group;" ::: "memory")
#define CP_WAIT2()  asm volatile("cp.async.wait_group 2;" ::: "memory")
#define CP_WAIT0()  asm volatile("cp.async.wait_group 0;" ::: "memory")
#define LDSM4(r0, r1, r2, r3, addr) \
    asm volatile("ldmatrix.sync.aligned.m8n8.x4.shared.b16 {%0,%1,%2,%3}, [%4];" \
                 : "=r"(r0), "=r"(r1), "=r"(r2), "=r"(r3) : "r"(addr))
#define LDSM4T(r0, r1, r2, r3, addr) \
    asm volatile("ldmatrix.sync.aligned.m8n8.x4.trans.shared.b16 {%0,%1,%2,%3}, [%4];" \
                 : "=r"(r0), "=r"(r1), "=r"(r2), "=r"(r3) : "r"(addr))

__device__ __forceinline__ void mma16816(float* c, const uint32_t* a,
                                         const uint32_t* b) {
    asm volatile(
        "mma.sync.aligned.m16n8k16.row.col.f32.bf16.bf16.f32 "
        "{%0,%1,%2,%3}, {%4,%5,%6,%7}, {%8,%9}, {%0,%1,%2,%3};"
        : "+f"(c[0]), "+f"(c[1]), "+f"(c[2]), "+f"(c[3])
        : "r"(a[0]), "r"(a[1]), "r"(a[2]), "r"(a[3]), "r"(b[0]), "r"(b[1]));
}
__device__ __forceinline__ uint32_t packbf2(float x, float y) {
    __nv_bfloat162 t = __halves2bfloat162(__float2bfloat16(x), __float2bfloat16(y));
    return *(uint32_t*)&t;
}

// ============================================================================
// Split conversion for GEMM operands (3-segment layout along K)
// ============================================================================
__global__ void convert_split_kernel(const float* __restrict__ src,
                                     __nv_bfloat16* __restrict__ dst,
                                     int nquads, int modeA)
{
    int idx = blockIdx.x * blockDim.x + threadIdx.x;
    if (idx >= nquads) return;
    int r  = idx >> 10;
    int c4 = (idx & 1023) * 4;
    float4 x = *(const float4*)(src + (size_t)r * HID + c4);

    __nv_bfloat16 h0 = __float2bfloat16(x.x), h1 = __float2bfloat16(x.y);
    __nv_bfloat16 h2 = __float2bfloat16(x.z), h3 = __float2bfloat16(x.w);
    __nv_bfloat16 l0 = __float2bfloat16(x.x - __bfloat162float(h0));
    __nv_bfloat16 l1 = __float2bfloat16(x.y - __bfloat162float(h1));
    __nv_bfloat16 l2 = __float2bfloat16(x.z - __bfloat162float(h2));
    __nv_bfloat16 l3 = __float2bfloat16(x.w - __bfloat162float(h3));

    __nv_bfloat162 hA = __halves2bfloat162(h0, h1), hB = __halves2bfloat162(h2, h3);
    __nv_bfloat162 lA = __halves2bfloat162(l0, l1), lB = __halves2bfloat162(l2, l3);

    size_t base = (size_t)r * KP + c4;
    __nv_bfloat162* d0 = (__nv_bfloat162*)(dst + base);
    __nv_bfloat162* d1 = (__nv_bfloat162*)(dst + base + HID);
    __nv_bfloat162* d2 = (__nv_bfloat162*)(dst + base + 2 * HID);
    d0[0] = hA; d0[1] = hB;
    if (modeA) { d1[0] = hA; d1[1] = hB; d2[0] = lA; d2[1] = lB; }
    else       { d1[0] = lA; d1[1] = lB; d2[0] = hA; d2[1] = hB; }
}

// ============================================================================
// bf16 mma.sync GEMM (unchanged from R5 — verified).
// ============================================================================
template <int QKV>
__global__ __launch_bounds__(256, 2)
void mma_gemm_kernel(const __nv_bfloat16* __restrict__ Ap,
                     const __nv_bfloat16* __restrict__ Bp,
                     float* __restrict__ Cq, float* __restrict__ Ck,
                     float* __restrict__ Cv)
{
    extern __shared__ char smem[];
    uint32_t sb = smem_u32(smem);

    int tid  = threadIdx.x;
    int wid  = tid >> 5, lane = tid & 31;
    int wm   = wid >> 1;
    int wn   = wid & 1;
    int m0   = blockIdx.x * 128;
    int n0   = blockIdx.y * 128;

    const char* Ag = (const char*)(Ap + (size_t)m0 * KP);
    const char* Bg = (const char*)(Bp + (size_t)n0 * KP);

    int r0g = tid >> 2,            c0g = (tid & 3) * 16;
    int r1g = (tid + 256) >> 2,    c1g = ((tid + 256) & 3) * 16;

    auto issue_stage = [&](int kt) {
        int buf = kt & 3;
        uint32_t sA = sb + (uint32_t)buf * (2 * STAGEB);
        uint32_t sB = sA + STAGEB;
        size_t koff = (size_t)kt * 64;
        CP_ASYNC16(sA + r0g * 80 + c0g, Ag + (size_t)r0g * (KP * 2) + koff + c0g);
        CP_ASYNC16(sA + r1g * 80 + c1g, Ag + (size_t)r1g * (KP * 2) + koff + c1g);
        CP_ASYNC16(sB + r0g * 80 + c0g, Bg + (size_t)r0g * (KP * 2) + koff + c0g);
        CP_ASYNC16(sB + r1g * 80 + c1g, Bg + (size_t)r1g * (KP * 2) + koff + c1g);
    };

    float acc[2][8][4];
#pragma unroll
    for (int i = 0; i < 2; i++)
#pragma unroll
        for (int j = 0; j < 8; j++)
#pragma unroll
            for (int q = 0; q < 4; q++) acc[i][j][q] = 0.0f;

    issue_stage(0); CP_COMMIT();
    issue_stage(1); CP_COMMIT();
    issue_stage(2); CP_COMMIT();

    uint32_t aL = (uint32_t)((wm * 32 + (lane & 15)) * 80 + (lane >> 4) * 16);
    uint32_t bL = (uint32_t)((wn * 64 + (lane >> 4) * 8 + (lane & 7)) * 80
                             + ((lane >> 3) & 1) * 16);

#pragma unroll 1
    for (int kt = 0; kt < NKIT; kt++) {
        CP_WAIT2();
        __syncthreads();

        int buf = kt & 3;
        uint32_t sA = sb + (uint32_t)buf * (2 * STAGEB);
        uint32_t sB = sA + STAGEB;

#pragma unroll
        for (int ks = 0; ks < 2; ks++) {
            uint32_t kbyte = ks * 32;
            uint32_t a[2][4], b[8][2];
            LDSM4(a[0][0], a[0][1], a[0][2], a[0][3], sA + aL + kbyte);
            LDSM4(a[1][0], a[1][1], a[1][2], a[1][3], sA + aL + 16 * 80 + kbyte);
#pragma unroll
            for (int t = 0; t < 4; t++)
                LDSM4(b[2 * t][0], b[2 * t][1], b[2 * t + 1][0], b[2 * t + 1][1],
                      sB + bL + t * 16 * 80 + kbyte);
#pragma unroll
            for (int mt = 0; mt < 2; mt++)
#pragma unroll
                for (int nt = 0; nt < 8; nt++)
                    mma16816(acc[mt][nt], a[mt], b[nt]);
        }

        if (kt + 3 < NKIT) issue_stage(kt + 3);
        CP_COMMIT();
    }
    CP_WAIT0();

    float* base;
    int hh = 0;
    if (QKV) {
        int bsel = n0 >> 12;
        base = (bsel == 0) ? Cq : ((bsel == 1) ? Ck : Cv);
        hh = (n0 & 4095) >> 7;
    } else {
        base = Cq;
    }

#pragma unroll
    for (int mt = 0; mt < 2; mt++) {
        int row = m0 + wm * 32 + mt * 16 + (lane >> 2);
#pragma unroll
        for (int nt = 0; nt < 8; nt++) {
            int col = n0 + wn * 64 + nt * 8 + (lane & 3) * 2;
            float2 v01 = make_float2(acc[mt][nt][0], acc[mt][nt][1]);
            float2 v23 = make_float2(acc[mt][nt][2], acc[mt][nt][3]);
            if (QKV) {
                int cc = col & 127;
                *(float2*)(base + ((size_t)hh * S_LEN + row) * HDIM + cc)     = v01;
                *(float2*)(base + ((size_t)hh * S_LEN + row + 8) * HDIM + cc) = v23;
            } else {
                *(float2*)(base + (size_t)row * HID + col)       = v01;
                *(float2*)(base + (size_t)(row + 8) * HID + col) = v23;
            }
        }
    }
}

// ============================================================================
// RoPE table (fp64 angles)
// ============================================================================
__global__ void rope_table_kernel()
{
    int idx = blockIdx.x * blockDim.x + threadIdx.x;
    if (idx >= S_LEN * 64) return;
    int d = idx & 63;
    int s = idx >> 6;
    double inv = pow(10000.0, -(double)(2 * d) / 128.0);
    double sd, cd;
    sincos((double)s * inv, &sd, &cd);
    g_cosT[idx] = (float)cd;
    g_sinT[idx] = (float)sd;
}

// ============================================================================
// Fused rope + split (unchanged from R5 — verified)
// ============================================================================
__global__ void rope_split_kernel()
{
    int idx = blockIdx.x * blockDim.x + threadIdx.x;
    if (idx >= NHEAD * S_LEN * 64) return;
    int t = idx & (S_LEN * 64 - 1);
    int d = idx & 63;
    int s = (idx >> 6) & (S_LEN - 1);
    int h = idx >> 17;
    float c = g_cosT[t], sn = g_sinT[t];
    const float scale = 0.08838834764831845f;

    size_t base = ((size_t)h * S_LEN + s) * HDIM;
    float q1 = g_q[base + d], q2 = g_q[base + d + 64];
    float k1 = g_k[base + d], k2 = g_k[base + d + 64];
    float v1 = g_v[base + d], v2 = g_v[base + d + 64];

    float qr1 = (q1 * c - q2 * sn) * scale;
    float qr2 = (q2 * c + q1 * sn) * scale;
    float kr1 = k1 * c - k2 * sn;
    float kr2 = k2 * c + k1 * sn;

    g_k[base + d]      = kr1;
    g_k[base + d + 64] = kr2;

    float vals[6] = {qr1, qr2, kr1, kr2, v1, v2};
    __nv_bfloat16* dsts[6][2] = {
        {g_qh + base + d, g_ql + base + d},
        {g_qh + base + d + 64, g_ql + base + d + 64},
        {g_kh + base + d, g_kl + base + d},
        {g_kh + base + d + 64, g_kl + base + d + 64},
        {g_vh + base + d, g_vl + base + d},
        {g_vh + base + d + 64, g_vl + base + d + 64}};
#pragma unroll
    for (int i = 0; i < 6; i++) {
        __nv_bfloat16 hi = __float2bfloat16(vals[i]);
        __nv_bfloat16 lo = __float2bfloat16(vals[i] - __bfloat162float(hi));
        *dsts[i][0] = hi;
        *dsts[i][1] = lo;
    }
}

// ============================================================================
// Flash attention v2: Br=128, 8 warps along M, register-resident P (C-frag ==
// A-frag identity), warp-local softmax (no barriers), K/V hi/lo double-buffer.
// Epilogue writes Wo-GEMM activations ([hi|hi|lo] split) directly into g_xp.
// ============================================================================
__global__ __launch_bounds__(256, 1)
void flash_mma_kernel(__nv_bfloat16* __restrict__ xp)
{
    extern __shared__ char smem[];
    uint32_t sb  = smem_u32(smem);
    uint32_t sQh = sb;
    uint32_t sQl = sb + FQ;
    uint32_t sKh = sb + 2 * FQ;            // + b*FTILE
    uint32_t sKl = sKh + 2 * FTILE;
    uint32_t sVh = sKl + 2 * FTILE;
    uint32_t sVl = sVh + 2 * FTILE;

    int qb  = 15 - blockIdx.x;             // long blocks first
    int h   = blockIdx.y;
    int tid = threadIdx.x, wid = tid >> 5, lane = tid & 31;
    int q0  = qb * 128;
    int lastkt = 2 * qb + 1;

    const __nv_bfloat16* qhp = g_qh + ((size_t)h * S_LEN + q0) * HDIM;
    const __nv_bfloat16* qlp = g_ql + ((size_t)h * S_LEN + q0) * HDIM;
    const __nv_bfloat16* khp = g_kh + (size_t)h * S_LEN * HDIM;
    const __nv_bfloat16* klp = g_kl + (size_t)h * S_LEN * HDIM;
    const __nv_bfloat16* vhp = g_vh + (size_t)h * S_LEN * HDIM;
    const __nv_bfloat16* vlp = g_vl + (size_t)h * S_LEN * HDIM;

    auto load_tile = [&](int kt, int bb) {
        uint32_t dKh = sKh + (uint32_t)bb * FTILE, dKl = sKl + (uint32_t)bb * FTILE;
        uint32_t dVh = sVh + (uint32_t)bb * FTILE, dVl = sVl + (uint32_t)bb * FTILE;
        const __nv_bfloat16* s1 = khp + (size_t)kt * 64 * HDIM;
        const __nv_bfloat16* s2 = klp + (size_t)kt * 64 * HDIM;
        const __nv_bfloat16* s3 = vhp + (size_t)kt * 64 * HDIM;
        const __nv_bfloat16* s4 = vlp + (size_t)kt * 64 * HDIM;
#pragma unroll
        for (int i = 0; i < 4; i++) {
            int u = tid + i * 256;
            int r = u >> 4, cb = (u & 15) * 16, ce = (u & 15) * 8;
            CP_ASYNC16(dKh + r * FT + cb, s1 + r * HDIM + ce);
            CP_ASYNC16(dKl + r * FT + cb, s2 + r * HDIM + ce);
            CP_ASYNC16(dVh + r * FT + cb, s3 + r * HDIM + ce);
            CP_ASYNC16(dVl + r * FT + cb, s4 + r * HDIM + ce);
        }
    };

    // preload Q (128 rows) + tile 0 as one cp.async group
#pragma unroll
    for (int i = 0; i < 8; i++) {
        int u = tid + i * 256;
        int r = u >> 4, cb = (u & 15) * 16, ce = (u & 15) * 8;
        CP_ASYNC16(sQh + r * FT + cb, qhp + r * HDIM + ce);
        CP_ASYNC16(sQl + r * FT + cb, qlp + r * HDIM + ce);
    }
    load_tile(0, 0);
    CP_COMMIT();

    float oacc[16][4];
#pragma unroll
    for (int i = 0; i < 16; i++)
#pragma unroll
        for (int j = 0; j < 4; j++) oacc[i][j] = 0.0f;
    float m0 = -INFINITY, m1 = -INFINITY, l0 = 0.0f, l1 = 0.0f;

    uint32_t aLq = (uint32_t)((wid * 16 + (lane & 15)) * FT + (lane >> 4) * 16);
    uint32_t bLk = (uint32_t)(((lane >> 4) * 8 + (lane & 7)) * FT
                              + ((lane >> 3) & 1) * 16);
    uint32_t vLb = (uint32_t)((lane & 15) * FT + (lane >> 4) * 16);
    int r0 = lane >> 2;                    // local row within warp's 16-row strip

#pragma unroll 1
    for (int kt = 0; kt <= lastkt; kt++) {
        int b = kt & 1;
        CP_WAIT0();
        __syncthreads();
        if (kt < lastkt) { load_tile(kt + 1, b ^ 1); CP_COMMIT(); }

        uint32_t Kh = sKh + (uint32_t)b * FTILE, Kl = sKl + (uint32_t)b * FTILE;
        uint32_t Vh = sVh + (uint32_t)b * FTILE, Vl = sVl + (uint32_t)b * FTILE;

        // ---- scores: Qh·Kh + Ql·Kh + Qh·Kl ----
        float sacc[8][4];
#pragma unroll
        for (int i = 0; i < 8; i++)
#pragma unroll
            for (int j = 0; j < 4; j++) sacc[i][j] = 0.0f;
#pragma unroll
        for (int ks = 0; ks < 8; ks++) {
            uint32_t ah[4], al[4];
            LDSM4(ah[0], ah[1], ah[2], ah[3], sQh + aLq + ks * 32);
            LDSM4(al[0], al[1], al[2], al[3], sQl + aLq + ks * 32);
#pragma unroll
            for (int t = 0; t < 4; t++) {
                uint32_t x[4], y[4];
                LDSM4(x[0], x[1], x[2], x[3], Kh + bLk + t * 16 * FT + ks * 32);
                mma16816(sacc[2 * t],     ah, &x[0]);
                mma16816(sacc[2 * t + 1], ah, &x[2]);
                mma16816(sacc[2 * t],     al, &x[0]);
                mma16816(sacc[2 * t + 1], al, &x[2]);
                LDSM4(y[0], y[1], y[2], y[3], Kl + bLk + t * 16 * FT + ks * 32);
                mma16816(sacc[2 * t],     ah, &y[0]);
                mma16816(sacc[2 * t + 1], ah, &y[2]);
            }
        }

        // ---- causal mask (only tiles crossing the diagonal) ----
        if (kt >= 2 * qb) {
            int gr0 = q0 + wid * 16 + r0;
            int gr1 = gr0 + 8;
            int gcb = kt * 64 + (lane & 3) * 2;
#pragma unroll
            for (int nt = 0; nt < 8; nt++) {
                int gc = gcb + nt * 8;
                if (gc     > gr0) sacc[nt][0] = -INFINITY;
                if (gc + 1 > gr0) sacc[nt][1] = -INFINITY;
                if (gc     > gr1) sacc[nt][2] = -INFINITY;
                if (gc + 1 > gr1) sacc[nt][3] = -INFINITY;
            }
        }

        // ---- warp-local online softmax ----
        float tm0 = -INFINITY, tm1 = -INFINITY;
#pragma unroll
        for (int nt = 0; nt < 8; nt++) {
            tm0 = fmaxf(tm0, fmaxf(sacc[nt][0], sacc[nt][1]));
            tm1 = fmaxf(tm1, fmaxf(sacc[nt][2], sacc[nt][3]));
        }
        tm0 = fmaxf(tm0, __shfl_xor_sync(0xffffffffu, tm0, 1));
        tm0 = fmaxf(tm0, __shfl_xor_sync(0xffffffffu, tm0, 2));
        tm1 = fmaxf(tm1, __shfl_xor_sync(0xffffffffu, tm1, 1));
        tm1 = fmaxf(tm1, __shfl_xor_sync(0xffffffffu, tm1, 2));

        float mn0 = fmaxf(m0, tm0), mn1 = fmaxf(m1, tm1);
        float al0 = __expf(m0 - mn0), al1 = __expf(m1 - mn1);
        m0 = mn0; m1 = mn1;

        float s0 = 0.0f, s1 = 0.0f;
#pragma unroll
        for (int nt = 0; nt < 8; nt++) {
            sacc[nt][0] = __expf(sacc[nt][0] - mn0);
            sacc[nt][1] = __expf(sacc[nt][1] - mn0);
            sacc[nt][2] = __expf(sacc[nt][2] - mn1);
            sacc[nt][3] = __expf(sacc[nt][3] - mn1);
            s0 += sacc[nt][0] + sacc[nt][1];
            s1 += sacc[nt][2] + sacc[nt][3];
        }
        s0 += __shfl_xor_sync(0xffffffffu, s0, 1);
        s0 += __shfl_xor_sync(0xffffffffu, s0, 2);
        s1 += __shfl_xor_sync(0xffffffffu, s1, 1);
        s1 += __shfl_xor_sync(0xffffffffu, s1, 2);
        l0 = l0 * al0 + s0;
        l1 = l1 * al1 + s1;

#pragma unroll
        for (int dt = 0; dt < 16; dt++) {
            oacc[dt][0] *= al0; oacc[dt][1] *= al0;
            oacc[dt][2] *= al1; oacc[dt][3] *= al1;
        }

        // ---- pack P into A-fragments (hi + lo), straight from registers ----
        uint32_t aPh[4][4], aPl[4][4];
#pragma unroll
        for (int ks = 0; ks < 4; ks++) {
            float p00 = sacc[2 * ks][0],     p01 = sacc[2 * ks][1];
            float p02 = sacc[2 * ks][2],     p03 = sacc[2 * ks][3];
            float p10 = sacc[2 * ks + 1][0], p11 = sacc[2 * ks + 1][1];
            float p12 = sacc[2 * ks + 1][2], p13 = sacc[2 * ks + 1][3];
            aPh[ks][0] = packbf2(p00, p01);
            aPh[ks][1] = packbf2(p02, p03);
            aPh[ks][2] = packbf2(p10, p11);
            aPh[ks][3] = packbf2(p12, p13);
            __nv_bfloat162 t0 = *(__nv_bfloat162*)&aPh[ks][0];
            __nv_bfloat162 t1 = *(__nv_bfloat162*)&aPh[ks][1];
            __nv_bfloat162 t2 = *(__nv_bfloat162*)&aPh[ks][2];
            __nv_bfloat162 t3 = *(__nv_bfloat162*)&aPh[ks][3];
            aPl[ks][0] = packbf2(p00 - __bfloat162float(t0.x),
                                 p01 - __bfloat162float(t0.y));
            aPl[ks][1] = packbf2(p02 - __bfloat162float(t1.x),
                                 p03 - __bfloat162float(t1.y));
            aPl[ks][2] = packbf2(p10 - __bfloat162float(t2.x),
                                 p11 - __bfloat162float(t2.y));
            aPl[ks][3] = packbf2(p12 - __bfloat162float(t3.x),
                                 p13 - __bfloat162float(t3.y));
        }

        // ---- P.V: Ph·Vh + Pl·Vh + Ph·Vl (Vh frags shared) ----
#pragma unroll
        for (int ks = 0; ks < 4; ks++) {
#pragma unroll
            for (int dp = 0; dp < 8; dp++) {
                uint32_t bh[4], bl[4];
                LDSM4T(bh[0], bh[1], bh[2], bh[3],
                       Vh + vLb + (uint32_t)(ks * 16) * FT + dp * 32);
                mma16816(oacc[2 * dp],     aPh[ks], &bh[0]);
                mma16816(oacc[2 * dp + 1], aPh[ks], &bh[2]);
                mma16816(oacc[2 * dp],     aPl[ks], &bh[0]);
                mma16816(oacc[2 * dp + 1], aPl[ks], &bh[2]);
                LDSM4T(bl[0], bl[1], bl[2], bl[3],
                       Vl + vLb + (uint32_t)(ks * 16) * FT + dp * 32);
                mma16816(oacc[2 * dp],     aPh[ks], &bl[0]);
                mma16816(oacc[2 * dp + 1], aPh[ks], &bl[2]);
            }
        }
    }

    // ---- epilogue: normalize and write split activations into g_xp ----
    float inv0 = 1.0f / l0, inv1 = 1.0f / l1;
    int grow = q0 + wid * 16 + r0;
#pragma unroll
    for (int dt = 0; dt < 16; dt++) {
        int col = h * HDIM + dt * 8 + (lane & 3) * 2;
        float v0 = oacc[dt][0] * inv0, v1 = oacc[dt][1] * inv0;
        float v2 = oacc[dt][2] * inv1, v3 = oacc[dt][3] * inv1;

        uint32_t hiA = packbf2(v0, v1);
        __nv_bfloat162 hA = *(__nv_bfloat162*)&hiA;
        uint32_t loA = packbf2(v0 - __bfloat162float(hA.x),
                               v1 - __bfloat162float(hA.y));
        uint32_t hiB = packbf2(v2, v3);
        __nv_bfloat162 hB = *(__nv_bfloat162*)&hiB;
        uint32_t loB = packbf2(v2 - __bfloat162float(hB.x),
                               v3 - __bfloat162float(hB.y));

        uint32_t* pA = (uint32_t*)(xp + (size_t)grow * KP + col);
        pA[0]                = hiA;
        pA[HID / 2]          = hiA;
        pA[HID]              = loA;
        uint32_t* pB = (uint32_t*)(xp + (size_t)(grow + 8) * KP + col);
        pB[0]                = hiB;
        pB[HID / 2]          = hiB;
        pB[HID]              = loB;
    }
}

// ============================================================================
// KV eviction
// ============================================================================
__global__ void evict_kernel(float* __restrict__ outk, float* __restrict__ outv)
{
    int idx = blockIdx.x * blockDim.x + threadIdx.x;
    if (idx >= NHEAD * EVLEN * HDIM) return;
    int d = idx & 127;
    int t = (idx >> 7) % EVLEN;
    int h = idx / (EVLEN * HDIM);
    int src = (t < SINKN) ? t : (S_LEN - RECENT) + (t - SINKN);
    size_t si = ((size_t)h * S_LEN + src) * HDIM + d;
    outk[idx] = g_k[si];
    outv[idx] = g_v[si];
}

// ============================================================================
extern "C" void kernel_launch(void* const* d_in, const int* in_sizes, int n_in,
                              void* d_out, int out_size)
{
    const float* X  = (const float*)d_in[0];
    const float* Wq = (const float*)d_in[1];
    const float* Wk = (const float*)d_in[2];
    const float* Wv = (const float*)d_in[3];
    const float* Wo = (const float*)d_in[4];
    float* out = (float*)d_out;

    float *qb, *kb, *vb;
    __nv_bfloat16 *xp, *wp;
    cudaGetSymbolAddress((void**)&qb, g_q);
    cudaGetSymbolAddress((void**)&kb, g_k);
    cudaGetSymbolAddress((void**)&vb, g_v);
    cudaGetSymbolAddress((void**)&xp, g_xp);
    cudaGetSymbolAddress((void**)&wp, g_wp);

    cudaFuncSetAttribute(mma_gemm_kernel<1>,
                         cudaFuncAttributeMaxDynamicSharedMemorySize, GEMM_SMEM);
    cudaFuncSetAttribute(mma_gemm_kernel<0>,
                         cudaFuncAttributeMaxDynamicSharedMemorySize, GEMM_SMEM);
    cudaFuncSetAttribute(flash_mma_kernel,
                         cudaFuncAttributeMaxDynamicSharedMemorySize, FA_SMEM);

    const int XQ = S_LEN * 1024;
    const int WQ = HID * 1024;
    const size_t WSEG = (size_t)HID * KP;

    rope_table_kernel<<<(S_LEN * 64 + 255) / 256, 256>>>();

    // all operand conversions up front
    convert_split_kernel<<<(XQ + 255) / 256, 256>>>(X, xp, XQ, 1);
    convert_split_kernel<<<(WQ + 255) / 256, 256>>>(Wq, wp,            WQ, 0);
    convert_split_kernel<<<(WQ + 255) / 256, 256>>>(Wk, wp + WSEG,     WQ, 0);
    convert_split_kernel<<<(WQ + 255) / 256, 256>>>(Wv, wp + 2 * WSEG, WQ, 0);
    convert_split_kernel<<<(WQ + 255) / 256, 256>>>(Wo, wp + 3 * WSEG, WQ, 0);

    // merged QKV projection: N = 12288
    dim3 gqkv(S_LEN / 128, (3 * HID) / 128);   // (16, 96)
    mma_gemm_kernel<1><<<gqkv, 256, GEMM_SMEM>>>(xp, wp, qb, kb, vb);

    // fused rope + flash-operand split
    rope_split_kernel<<<(NHEAD * S_LEN * 64) / 256, 256>>>();

    // flash attention; writes Wo activations (split layout) into xp
    flash_mma_kernel<<<dim3(16, 32), 256, FA_SMEM>>>(xp);

    // output projection
    dim3 go(S_LEN / 128, HID / 128);           // (16, 32)
    mma_gemm_kernel<0><<<go, 256, GEMM_SMEM>>>(xp, wp + 3 * WSEG, out, out, out);

    size_t attn_elems = (size_t)S_LEN * HID;
    size_t ev_elems   = (size_t)NHEAD * EVLEN * HDIM;
    evict_kernel<<<(int)((ev_elems + 255) / 256), 256>>>(out + attn_elems,
                                                         out + attn_elems + ev_elems);
}

// round 7
// speedup vs baseline: 3.3679x; 1.1447x over previous
#include <cuda_runtime.h>
#include <cuda_bf16.h>
#include <math.h>
#include <stdint.h>

#define S_LEN  2048
#define HID    4096
#define NHEAD  32
#define HDIM   128
#define RECENT 204
#define SINKN  4
#define EVLEN  (SINKN + RECENT)   // 208

#define KP     (3 * HID)     // 12288 split-K
#define BK2    64            // K per stage (128 B rows)
#define NK2    (KP / BK2)    // 192
#define STG    16384         // bytes per operand per stage (128 rows x 128 B)
#define GEMM_SMEM (3 * 2 * STG)   // 98304 (3 stages x (A+B))

// flash smem: 272 B per row (128 bf16 + pad)
#define FT     272
#define FTILE  (64 * FT)                // 17408 (K/V tiles, 64 rows)
#define FQ     (128 * FT)               // 34816 (Q tiles, 128 rows)
#define FA_SMEM (2 * FQ + 8 * FTILE)    // 208896

// -------- static scratch --------
static __device__ float g_q[NHEAD * S_LEN * HDIM];
static __device__ float g_k[NHEAD * S_LEN * HDIM];
static __device__ float g_v[NHEAD * S_LEN * HDIM];
static __device__ __nv_bfloat16 g_xp[(size_t)S_LEN * KP];
static __device__ __nv_bfloat16 g_wp[4ULL * HID * KP];   // Wq|Wk|Wv|Wo
static __device__ __nv_bfloat16 g_qh[NHEAD * S_LEN * HDIM];
static __device__ __nv_bfloat16 g_ql[NHEAD * S_LEN * HDIM];
static __device__ __nv_bfloat16 g_kh[NHEAD * S_LEN * HDIM];
static __device__ __nv_bfloat16 g_kl[NHEAD * S_LEN * HDIM];
static __device__ __nv_bfloat16 g_vh[NHEAD * S_LEN * HDIM];
static __device__ __nv_bfloat16 g_vl[NHEAD * S_LEN * HDIM];
static __device__ float g_cosT[S_LEN * 64];
static __device__ float g_sinT[S_LEN * 64];

// ============================ helpers =======================================
__device__ __forceinline__ uint32_t smem_u32(const void* p) {
    uint32_t a;
    asm("{ .reg .u64 t; cvta.to.shared.u64 t, %1; cvt.u32.u64 %0, t; }"
        : "=r"(a) : "l"(p));
    return a;
}
#define CP_ASYNC16(dst, src) \
    asm volatile("cp.async.cg.shared.global [%0], [%1], 16;" \
                 :: "r"(dst), "l"(src) : "memory")
#define CP_COMMIT() asm volatile("cp.async.commit_group;" ::: "memory")
#define CP_WAIT1()  asm volatile("cp.async.wait_group 1;" ::: "memory")
#define CP_WAIT0()  asm volatile("cp.async.wait_group 0;" ::: "memory")
#define LDSM4(r0, r1, r2, r3, addr) \
    asm volatile("ldmatrix.sync.aligned.m8n8.x4.shared.b16 {%0,%1,%2,%3}, [%4];" \
                 : "=r"(r0), "=r"(r1), "=r"(r2), "=r"(r3) : "r"(addr))
#define LDSM4T(r0, r1, r2, r3, addr) \
    asm volatile("ldmatrix.sync.aligned.m8n8.x4.trans.shared.b16 {%0,%1,%2,%3}, [%4];" \
                 : "=r"(r0), "=r"(r1), "=r"(r2), "=r"(r3) : "r"(addr))

__device__ __forceinline__ void mma16816(float* c, const uint32_t* a,
                                         const uint32_t* b) {
    asm volatile(
        "mma.sync.aligned.m16n8k16.row.col.f32.bf16.bf16.f32 "
        "{%0,%1,%2,%3}, {%4,%5,%6,%7}, {%8,%9}, {%0,%1,%2,%3};"
        : "+f"(c[0]), "+f"(c[1]), "+f"(c[2]), "+f"(c[3])
        : "r"(a[0]), "r"(a[1]), "r"(a[2]), "r"(a[3]), "r"(b[0]), "r"(b[1]));
}
__device__ __forceinline__ uint32_t packbf2(float x, float y) {
    __nv_bfloat162 t = __halves2bfloat162(__float2bfloat16(x), __float2bfloat16(y));
    return *(uint32_t*)&t;
}

// ============================================================================
// Split conversion for GEMM operands (3-segment layout along K)
// ============================================================================
__global__ void convert_split_kernel(const float* __restrict__ src,
                                     __nv_bfloat16* __restrict__ dst,
                                     int nquads, int modeA)
{
    int idx = blockIdx.x * blockDim.x + threadIdx.x;
    if (idx >= nquads) return;
    int r  = idx >> 10;
    int c4 = (idx & 1023) * 4;
    float4 x = *(const float4*)(src + (size_t)r * HID + c4);

    __nv_bfloat16 h0 = __float2bfloat16(x.x), h1 = __float2bfloat16(x.y);
    __nv_bfloat16 h2 = __float2bfloat16(x.z), h3 = __float2bfloat16(x.w);
    __nv_bfloat16 l0 = __float2bfloat16(x.x - __bfloat162float(h0));
    __nv_bfloat16 l1 = __float2bfloat16(x.y - __bfloat162float(h1));
    __nv_bfloat16 l2 = __float2bfloat16(x.z - __bfloat162float(h2));
    __nv_bfloat16 l3 = __float2bfloat16(x.w - __bfloat162float(h3));

    __nv_bfloat162 hA = __halves2bfloat162(h0, h1), hB = __halves2bfloat162(h2, h3);
    __nv_bfloat162 lA = __halves2bfloat162(l0, l1), lB = __halves2bfloat162(l2, l3);

    size_t base = (size_t)r * KP + c4;
    __nv_bfloat162* d0 = (__nv_bfloat162*)(dst + base);
    __nv_bfloat162* d1 = (__nv_bfloat162*)(dst + base + HID);
    __nv_bfloat162* d2 = (__nv_bfloat162*)(dst + base + 2 * HID);
    d0[0] = hA; d0[1] = hB;
    if (modeA) { d1[0] = hA; d1[1] = hB; d2[0] = lA; d2[1] = lB; }
    else       { d1[0] = lA; d1[1] = lB; d2[0] = hA; d2[1] = hB; }
}

// ============================================================================
// bf16 mma.sync GEMM v2: CTA 128x128, BK=64 SW128-swizzled stages, 3-stage
// ring with issue-before-compute, 8 warps, 2 CTAs/SM.
// ============================================================================
template <int QKV>
__global__ __launch_bounds__(256, 2)
void mma_gemm_kernel(const __nv_bfloat16* __restrict__ Ap,
                     const __nv_bfloat16* __restrict__ Bp,
                     float* __restrict__ Cq, float* __restrict__ Ck,
                     float* __restrict__ Cv)
{
    extern __shared__ __align__(1024) char smem[];
    uint32_t sb = smem_u32(smem);

    int tid  = threadIdx.x;
    int wid  = tid >> 5, lane = tid & 31;
    int wm   = wid >> 1;
    int wn   = wid & 1;
    int m0   = blockIdx.x * 128;
    int n0   = blockIdx.y * 128;

    const char* Ag = (const char*)(Ap + (size_t)m0 * KP);
    const char* Bg = (const char*)(Bp + (size_t)n0 * KP);

    auto issue_stage = [&](int kt) {
        int buf = kt % 3;
        uint32_t sA = sb + (uint32_t)buf * (2 * STG);
        uint32_t sB = sA + STG;
        size_t koff = (size_t)kt * 128;     // BK=64 bf16 = 128 B
#pragma unroll
        for (int i = 0; i < 4; i++) {
            int u = tid + i * 256;
            int r = u >> 3, c = (u & 7) * 16;
            uint32_t sw = (uint32_t)(r * 128 + (c ^ ((r & 7) << 4)));
            CP_ASYNC16(sA + sw, Ag + (size_t)r * (KP * 2) + koff + c);
            CP_ASYNC16(sB + sw, Bg + (size_t)r * (KP * 2) + koff + c);
        }
    };

    float acc[2][8][4];
#pragma unroll
    for (int i = 0; i < 2; i++)
#pragma unroll
        for (int j = 0; j < 8; j++)
#pragma unroll
            for (int q = 0; q < 4; q++) acc[i][j][q] = 0.0f;

    issue_stage(0); CP_COMMIT();
    issue_stage(1); CP_COMMIT();

    // swizzled fragment lane bases (strip offsets +2048 keep row&7 invariant)
    int arow = wm * 32 + (lane & 15);
    uint32_t aL = (uint32_t)(arow * 128 + (((lane >> 4) * 16) ^ ((arow & 7) << 4)));
    int brow = wn * 64 + (lane >> 4) * 8 + (lane & 7);
    uint32_t bL = (uint32_t)(brow * 128 + ((((lane >> 3) & 1) * 16) ^ ((brow & 7) << 4)));

#pragma unroll 1
    for (int kt = 0; kt < NK2; kt++) {
        CP_WAIT1();            // stage kt resident
        __syncthreads();       // all warps done with buffer (kt+2)%3 == (kt-1)%3
        if (kt + 2 < NK2) { issue_stage(kt + 2); CP_COMMIT(); }

        uint32_t sA = sb + (uint32_t)(kt % 3) * (2 * STG);
        uint32_t sB = sA + STG;

#pragma unroll
        for (int ks = 0; ks < 4; ks++) {
            uint32_t kx = (uint32_t)(ks << 5);
            uint32_t a[2][4], b[8][2];
            LDSM4(a[0][0], a[0][1], a[0][2], a[0][3], (sA + aL) ^ kx);
            LDSM4(a[1][0], a[1][1], a[1][2], a[1][3], (sA + aL + 2048) ^ kx);
#pragma unroll
            for (int t = 0; t < 4; t++)
                LDSM4(b[2 * t][0], b[2 * t][1], b[2 * t + 1][0], b[2 * t + 1][1],
                      (sB + bL + (uint32_t)(t * 2048)) ^ kx);
#pragma unroll
            for (int mt = 0; mt < 2; mt++)
#pragma unroll
                for (int nt = 0; nt < 8; nt++)
                    mma16816(acc[mt][nt], a[mt], b[nt]);
        }
    }
    CP_WAIT0();

    float* base;
    int hh = 0;
    if (QKV) {
        int bsel = n0 >> 12;
        base = (bsel == 0) ? Cq : ((bsel == 1) ? Ck : Cv);
        hh = (n0 & 4095) >> 7;
    } else {
        base = Cq;
    }

#pragma unroll
    for (int mt = 0; mt < 2; mt++) {
        int row = m0 + wm * 32 + mt * 16 + (lane >> 2);
#pragma unroll
        for (int nt = 0; nt < 8; nt++) {
            int col = n0 + wn * 64 + nt * 8 + (lane & 3) * 2;
            float2 v01 = make_float2(acc[mt][nt][0], acc[mt][nt][1]);
            float2 v23 = make_float2(acc[mt][nt][2], acc[mt][nt][3]);
            if (QKV) {
                int cc = col & 127;
                *(float2*)(base + ((size_t)hh * S_LEN + row) * HDIM + cc)     = v01;
                *(float2*)(base + ((size_t)hh * S_LEN + row + 8) * HDIM + cc) = v23;
            } else {
                *(float2*)(base + (size_t)row * HID + col)       = v01;
                *(float2*)(base + (size_t)(row + 8) * HID + col) = v23;
            }
        }
    }
}

// ============================================================================
// RoPE table (fp64 angles)
// ============================================================================
__global__ void rope_table_kernel()
{
    int idx = blockIdx.x * blockDim.x + threadIdx.x;
    if (idx >= S_LEN * 64) return;
    int d = idx & 63;
    int s = idx >> 6;
    double inv = pow(10000.0, -(double)(2 * d) / 128.0);
    double sd, cd;
    sincos((double)s * inv, &sd, &cd);
    g_cosT[idx] = (float)cd;
    g_sinT[idx] = (float)sd;
}

// ============================================================================
// Fused rope + split (verified)
// ============================================================================
__global__ void rope_split_kernel()
{
    int idx = blockIdx.x * blockDim.x + threadIdx.x;
    if (idx >= NHEAD * S_LEN * 64) return;
    int t = idx & (S_LEN * 64 - 1);
    int d = idx & 63;
    int s = (idx >> 6) & (S_LEN - 1);
    int h = idx >> 17;
    float c = g_cosT[t], sn = g_sinT[t];
    const float scale = 0.08838834764831845f;

    size_t base = ((size_t)h * S_LEN + s) * HDIM;
    float q1 = g_q[base + d], q2 = g_q[base + d + 64];
    float k1 = g_k[base + d], k2 = g_k[base + d + 64];
    float v1 = g_v[base + d], v2 = g_v[base + d + 64];

    float qr1 = (q1 * c - q2 * sn) * scale;
    float qr2 = (q2 * c + q1 * sn) * scale;
    float kr1 = k1 * c - k2 * sn;
    float kr2 = k2 * c + k1 * sn;

    g_k[base + d]      = kr1;
    g_k[base + d + 64] = kr2;

    float vals[6] = {qr1, qr2, kr1, kr2, v1, v2};
    __nv_bfloat16* dsts[6][2] = {
        {g_qh + base + d, g_ql + base + d},
        {g_qh + base + d + 64, g_ql + base + d + 64},
        {g_kh + base + d, g_kl + base + d},
        {g_kh + base + d + 64, g_kl + base + d + 64},
        {g_vh + base + d, g_vl + base + d},
        {g_vh + base + d + 64, g_vl + base + d + 64}};
#pragma unroll
    for (int i = 0; i < 6; i++) {
        __nv_bfloat16 hi = __float2bfloat16(vals[i]);
        __nv_bfloat16 lo = __float2bfloat16(vals[i] - __bfloat162float(hi));
        *dsts[i][0] = hi;
        *dsts[i][1] = lo;
    }
}

// ============================================================================
// Flash attention v2 (unchanged from R6 — verified)
// ============================================================================
__global__ __launch_bounds__(256, 1)
void flash_mma_kernel(__nv_bfloat16* __restrict__ xp)
{
    extern __shared__ char fsm_raw[];
    char* smem = fsm_raw;
    uint32_t sb  = smem_u32(smem);
    uint32_t sQh = sb;
    uint32_t sQl = sb + FQ;
    uint32_t sKh = sb + 2 * FQ;
    uint32_t sKl = sKh + 2 * FTILE;
    uint32_t sVh = sKl + 2 * FTILE;
    uint32_t sVl = sVh + 2 * FTILE;

    int qb  = 15 - blockIdx.x;
    int h   = blockIdx.y;
    int tid = threadIdx.x, wid = tid >> 5, lane = tid & 31;
    int q0  = qb * 128;
    int lastkt = 2 * qb + 1;

    const __nv_bfloat16* qhp = g_qh + ((size_t)h * S_LEN + q0) * HDIM;
    const __nv_bfloat16* qlp = g_ql + ((size_t)h * S_LEN + q0) * HDIM;
    const __nv_bfloat16* khp = g_kh + (size_t)h * S_LEN * HDIM;
    const __nv_bfloat16* klp = g_kl + (size_t)h * S_LEN * HDIM;
    const __nv_bfloat16* vhp = g_vh + (size_t)h * S_LEN * HDIM;
    const __nv_bfloat16* vlp = g_vl + (size_t)h * S_LEN * HDIM;

    auto load_tile = [&](int kt, int bb) {
        uint32_t dKh = sKh + (uint32_t)bb * FTILE, dKl = sKl + (uint32_t)bb * FTILE;
        uint32_t dVh = sVh + (uint32_t)bb * FTILE, dVl = sVl + (uint32_t)bb * FTILE;
        const __nv_bfloat16* s1 = khp + (size_t)kt * 64 * HDIM;
        const __nv_bfloat16* s2 = klp + (size_t)kt * 64 * HDIM;
        const __nv_bfloat16* s3 = vhp + (size_t)kt * 64 * HDIM;
        const __nv_bfloat16* s4 = vlp + (size_t)kt * 64 * HDIM;
#pragma unroll
        for (int i = 0; i < 4; i++) {
            int u = tid + i * 256;
            int r = u >> 4, cb = (u & 15) * 16, ce = (u & 15) * 8;
            CP_ASYNC16(dKh + r * FT + cb, s1 + r * HDIM + ce);
            CP_ASYNC16(dKl + r * FT + cb, s2 + r * HDIM + ce);
            CP_ASYNC16(dVh + r * FT + cb, s3 + r * HDIM + ce);
            CP_ASYNC16(dVl + r * FT + cb, s4 + r * HDIM + ce);
        }
    };

#pragma unroll
    for (int i = 0; i < 8; i++) {
        int u = tid + i * 256;
        int r = u >> 4, cb = (u & 15) * 16, ce = (u & 15) * 8;
        CP_ASYNC16(sQh + r * FT + cb, qhp + r * HDIM + ce);
        CP_ASYNC16(sQl + r * FT + cb, qlp + r * HDIM + ce);
    }
    load_tile(0, 0);
    CP_COMMIT();

    float oacc[16][4];
#pragma unroll
    for (int i = 0; i < 16; i++)
#pragma unroll
        for (int j = 0; j < 4; j++) oacc[i][j] = 0.0f;
    float m0 = -INFINITY, m1 = -INFINITY, l0 = 0.0f, l1 = 0.0f;

    uint32_t aLq = (uint32_t)((wid * 16 + (lane & 15)) * FT + (lane >> 4) * 16);
    uint32_t bLk = (uint32_t)(((lane >> 4) * 8 + (lane & 7)) * FT
                              + ((lane >> 3) & 1) * 16);
    uint32_t vLb = (uint32_t)((lane & 15) * FT + (lane >> 4) * 16);
    int r0 = lane >> 2;

#pragma unroll 1
    for (int kt = 0; kt <= lastkt; kt++) {
        int b = kt & 1;
        CP_WAIT0();
        __syncthreads();
        if (kt < lastkt) { load_tile(kt + 1, b ^ 1); CP_COMMIT(); }

        uint32_t Kh = sKh + (uint32_t)b * FTILE, Kl = sKl + (uint32_t)b * FTILE;
        uint32_t Vh = sVh + (uint32_t)b * FTILE, Vl = sVl + (uint32_t)b * FTILE;

        float sacc[8][4];
#pragma unroll
        for (int i = 0; i < 8; i++)
#pragma unroll
            for (int j = 0; j < 4; j++) sacc[i][j] = 0.0f;
#pragma unroll
        for (int ks = 0; ks < 8; ks++) {
            uint32_t ah[4], al[4];
            LDSM4(ah[0], ah[1], ah[2], ah[3], sQh + aLq + ks * 32);
            LDSM4(al[0], al[1], al[2], al[3], sQl + aLq + ks * 32);
#pragma unroll
            for (int t = 0; t < 4; t++) {
                uint32_t x[4], y[4];
                LDSM4(x[0], x[1], x[2], x[3], Kh + bLk + t * 16 * FT + ks * 32);
                mma16816(sacc[2 * t],     ah, &x[0]);
                mma16816(sacc[2 * t + 1], ah, &x[2]);
                mma16816(sacc[2 * t],     al, &x[0]);
                mma16816(sacc[2 * t + 1], al, &x[2]);
                LDSM4(y[0], y[1], y[2], y[3], Kl + bLk + t * 16 * FT + ks * 32);
                mma16816(sacc[2 * t],     ah, &y[0]);
                mma16816(sacc[2 * t + 1], ah, &y[2]);
            }
        }

        if (kt >= 2 * qb) {
            int gr0 = q0 + wid * 16 + r0;
            int gr1 = gr0 + 8;
            int gcb = kt * 64 + (lane & 3) * 2;
#pragma unroll
            for (int nt = 0; nt < 8; nt++) {
                int gc = gcb + nt * 8;
                if (gc     > gr0) sacc[nt][0] = -INFINITY;
                if (gc + 1 > gr0) sacc[nt][1] = -INFINITY;
                if (gc     > gr1) sacc[nt][2] = -INFINITY;
                if (gc + 1 > gr1) sacc[nt][3] = -INFINITY;
            }
        }

        float tm0 = -INFINITY, tm1 = -INFINITY;
#pragma unroll
        for (int nt = 0; nt < 8; nt++) {
            tm0 = fmaxf(tm0, fmaxf(sacc[nt][0], sacc[nt][1]));
            tm1 = fmaxf(tm1, fmaxf(sacc[nt][2], sacc[nt][3]));
        }
        tm0 = fmaxf(tm0, __shfl_xor_sync(0xffffffffu, tm0, 1));
        tm0 = fmaxf(tm0, __shfl_xor_sync(0xffffffffu, tm0, 2));
        tm1 = fmaxf(tm1, __shfl_xor_sync(0xffffffffu, tm1, 1));
        tm1 = fmaxf(tm1, __shfl_xor_sync(0xffffffffu, tm1, 2));

        float mn0 = fmaxf(m0, tm0), mn1 = fmaxf(m1, tm1);
        float al0 = __expf(m0 - mn0), al1 = __expf(m1 - mn1);
        m0 = mn0; m1 = mn1;

        float s0 = 0.0f, s1 = 0.0f;
#pragma unroll
        for (int nt = 0; nt < 8; nt++) {
            sacc[nt][0] = __expf(sacc[nt][0] - mn0);
            sacc[nt][1] = __expf(sacc[nt][1] - mn0);
            sacc[nt][2] = __expf(sacc[nt][2] - mn1);
            sacc[nt][3] = __expf(sacc[nt][3] - mn1);
            s0 += sacc[nt][0] + sacc[nt][1];
            s1 += sacc[nt][2] + sacc[nt][3];
        }
        s0 += __shfl_xor_sync(0xffffffffu, s0, 1);
        s0 += __shfl_xor_sync(0xffffffffu, s0, 2);
        s1 += __shfl_xor_sync(0xffffffffu, s1, 1);
        s1 += __shfl_xor_sync(0xffffffffu, s1, 2);
        l0 = l0 * al0 + s0;
        l1 = l1 * al1 + s1;

#pragma unroll
        for (int dt = 0; dt < 16; dt++) {
            oacc[dt][0] *= al0; oacc[dt][1] *= al0;
            oacc[dt][2] *= al1; oacc[dt][3] *= al1;
        }

        uint32_t aPh[4][4], aPl[4][4];
#pragma unroll
        for (int ks = 0; ks < 4; ks++) {
            float p00 = sacc[2 * ks][0],     p01 = sacc[2 * ks][1];
            float p02 = sacc[2 * ks][2],     p03 = sacc[2 * ks][3];
            float p10 = sacc[2 * ks + 1][0], p11 = sacc[2 * ks + 1][1];
            float p12 = sacc[2 * ks + 1][2], p13 = sacc[2 * ks + 1][3];
            aPh[ks][0] = packbf2(p00, p01);
            aPh[ks][1] = packbf2(p02, p03);
            aPh[ks][2] = packbf2(p10, p11);
            aPh[ks][3] = packbf2(p12, p13);
            __nv_bfloat162 t0 = *(__nv_bfloat162*)&aPh[ks][0];
            __nv_bfloat162 t1 = *(__nv_bfloat162*)&aPh[ks][1];
            __nv_bfloat162 t2 = *(__nv_bfloat162*)&aPh[ks][2];
            __nv_bfloat162 t3 = *(__nv_bfloat162*)&aPh[ks][3];
            aPl[ks][0] = packbf2(p00 - __bfloat162float(t0.x),
                                 p01 - __bfloat162float(t0.y));
            aPl[ks][1] = packbf2(p02 - __bfloat162float(t1.x),
                                 p03 - __bfloat162float(t1.y));
            aPl[ks][2] = packbf2(p10 - __bfloat162float(t2.x),
                                 p11 - __bfloat162float(t2.y));
            aPl[ks][3] = packbf2(p12 - __bfloat162float(t3.x),
                                 p13 - __bfloat162float(t3.y));
        }

#pragma unroll
        for (int ks = 0; ks < 4; ks++) {
#pragma unroll
            for (int dp = 0; dp < 8; dp++) {
                uint32_t bh[4], bl[4];
                LDSM4T(bh[0], bh[1], bh[2], bh[3],
                       Vh + vLb + (uint32_t)(ks * 16) * FT + dp * 32);
                mma16816(oacc[2 * dp],     aPh[ks], &bh[0]);
                mma16816(oacc[2 * dp + 1], aPh[ks], &bh[2]);
                mma16816(oacc[2 * dp],     aPl[ks], &bh[0]);
                mma16816(oacc[2 * dp + 1], aPl[ks], &bh[2]);
                LDSM4T(bl[0], bl[1], bl[2], bl[3],
                       Vl + vLb + (uint32_t)(ks * 16) * FT + dp * 32);
                mma16816(oacc[2 * dp],     aPh[ks], &bl[0]);
                mma16816(oacc[2 * dp + 1], aPh[ks], &bl[2]);
            }
        }
    }

    float inv0 = 1.0f / l0, inv1 = 1.0f / l1;
    int grow = q0 + wid * 16 + r0;
#pragma unroll
    for (int dt = 0; dt < 16; dt++) {
        int col = h * HDIM + dt * 8 + (lane & 3) * 2;
        float v0 = oacc[dt][0] * inv0, v1 = oacc[dt][1] * inv0;
        float v2 = oacc[dt][2] * inv1, v3 = oacc[dt][3] * inv1;

        uint32_t hiA = packbf2(v0, v1);
        __nv_bfloat162 hA = *(__nv_bfloat162*)&hiA;
        uint32_t loA = packbf2(v0 - __bfloat162float(hA.x),
                               v1 - __bfloat162float(hA.y));
        uint32_t hiB = packbf2(v2, v3);
        __nv_bfloat162 hB = *(__nv_bfloat162*)&hiB;
        uint32_t loB = packbf2(v2 - __bfloat162float(hB.x),
                               v3 - __bfloat162float(hB.y));

        uint32_t* pA = (uint32_t*)(xp + (size_t)grow * KP + col);
        pA[0]       = hiA;
        pA[HID / 2] = hiA;
        pA[HID]     = loA;
        uint32_t* pB = (uint32_t*)(xp + (size_t)(grow + 8) * KP + col);
        pB[0]       = hiB;
        pB[HID / 2] = hiB;
        pB[HID]     = loB;
    }
}

// ============================================================================
// KV eviction
// ============================================================================
__global__ void evict_kernel(float* __restrict__ outk, float* __restrict__ outv)
{
    int idx = blockIdx.x * blockDim.x + threadIdx.x;
    if (idx >= NHEAD * EVLEN * HDIM) return;
    int d = idx & 127;
    int t = (idx >> 7) % EVLEN;
    int h = idx / (EVLEN * HDIM);
    int src = (t < SINKN) ? t : (S_LEN - RECENT) + (t - SINKN);
    size_t si = ((size_t)h * S_LEN + src) * HDIM + d;
    outk[idx] = g_k[si];
    outv[idx] = g_v[si];
}

// ============================================================================
extern "C" void kernel_launch(void* const* d_in, const int* in_sizes, int n_in,
                              void* d_out, int out_size)
{
    const float* X  = (const float*)d_in[0];
    const float* Wq = (const float*)d_in[1];
    const float* Wk = (const float*)d_in[2];
    const float* Wv = (const float*)d_in[3];
    const float* Wo = (const float*)d_in[4];
    float* out = (float*)d_out;

    float *qb, *kb, *vb;
    __nv_bfloat16 *xp, *wp;
    cudaGetSymbolAddress((void**)&qb, g_q);
    cudaGetSymbolAddress((void**)&kb, g_k);
    cudaGetSymbolAddress((void**)&vb, g_v);
    cudaGetSymbolAddress((void**)&xp, g_xp);
    cudaGetSymbolAddress((void**)&wp, g_wp);

    cudaFuncSetAttribute(mma_gemm_kernel<1>,
                         cudaFuncAttributeMaxDynamicSharedMemorySize, GEMM_SMEM);
    cudaFuncSetAttribute(mma_gemm_kernel<0>,
                         cudaFuncAttributeMaxDynamicSharedMemorySize, GEMM_SMEM);
    cudaFuncSetAttribute(flash_mma_kernel,
                         cudaFuncAttributeMaxDynamicSharedMemorySize, FA_SMEM);

    const int XQ = S_LEN * 1024;
    const int WQ = HID * 1024;
    const size_t WSEG = (size_t)HID * KP;

    rope_table_kernel<<<(S_LEN * 64 + 255) / 256, 256>>>();

    convert_split_kernel<<<(XQ + 255) / 256, 256>>>(X, xp, XQ, 1);
    convert_split_kernel<<<(WQ + 255) / 256, 256>>>(Wq, wp,            WQ, 0);
    convert_split_kernel<<<(WQ + 255) / 256, 256>>>(Wk, wp + WSEG,     WQ, 0);
    convert_split_kernel<<<(WQ + 255) / 256, 256>>>(Wv, wp + 2 * WSEG, WQ, 0);
    convert_split_kernel<<<(WQ + 255) / 256, 256>>>(Wo, wp + 3 * WSEG, WQ, 0);

    dim3 gqkv(S_LEN / 128, (3 * HID) / 128);   // (16, 96)
    mma_gemm_kernel<1><<<gqkv, 256, GEMM_SMEM>>>(xp, wp, qb, kb, vb);

    rope_split_kernel<<<(NHEAD * S_LEN * 64) / 256, 256>>>();

    flash_mma_kernel<<<dim3(16, 32), 256, FA_SMEM>>>(xp);

    dim3 go(S_LEN / 128, HID / 128);           // (16, 32)
    mma_gemm_kernel<0><<<go, 256, GEMM_SMEM>>>(xp, wp + 3 * WSEG, out, out, out);

    size_t attn_elems = (size_t)S_LEN * HID;
    size_t ev_elems   = (size_t)NHEAD * EVLEN * HDIM;
    evict_kernel<<<(int)((ev_elems + 255) / 256), 256>>>(out + attn_elems,
                                                         out + attn_elems + ev_elems);
}

// round 8
// speedup vs baseline: 4.0182x; 1.1931x over previous
#include <cuda_runtime.h>
#include <cuda_fp16.h>
#include <math.h>
#include <stdint.h>

#define S_LEN  2048
#define HID    4096
#define NHEAD  32
#define HDIM   128
#define RECENT 204
#define SINKN  4
#define EVLEN  (SINKN + RECENT)   // 208

#define KP3    (3 * HID)     // 12288 (3-term split K)
#define STG    16384         // bytes per operand per stage (128 rows x 128 B)
#define GEMM_SMEM (3 * 2 * STG)   // 98304

// flash smem: 272 B per row (128 fp16 + pad)
#define FT     272
#define FTILE  (64 * FT)                // 17408
#define FQ     (128 * FT)               // 34816
#define FA_SMEM (2 * FQ + 6 * FTILE)    // 174080

// -------- static scratch --------
static __device__ float g_q[NHEAD * S_LEN * HDIM];
static __device__ float g_k[NHEAD * S_LEN * HDIM];
static __device__ float g_v[NHEAD * S_LEN * HDIM];
static __device__ __half g_xp3[(size_t)S_LEN * KP3];     // X  [hi|hi|lo]
static __device__ __half g_xp2[(size_t)S_LEN * 2 * HID]; // O  [hi|lo]
static __device__ __half g_wqk[2ULL * HID * KP3];        // Wq|Wk [hi|lo|hi]
static __device__ __half g_wv[(size_t)HID * HID];        // Wv hi
static __device__ __half g_wo[(size_t)HID * HID];        // Wo hi
static __device__ __half g_qh[NHEAD * S_LEN * HDIM];
static __device__ __half g_ql[NHEAD * S_LEN * HDIM];
static __device__ __half g_kh[NHEAD * S_LEN * HDIM];
static __device__ __half g_kl[NHEAD * S_LEN * HDIM];
static __device__ __half g_vh[NHEAD * S_LEN * HDIM];
static __device__ float g_cosT[S_LEN * 64];
static __device__ float g_sinT[S_LEN * 64];

// ============================ helpers =======================================
__device__ __forceinline__ uint32_t smem_u32(const void* p) {
    uint32_t a;
    asm("{ .reg .u64 t; cvta.to.shared.u64 t, %1; cvt.u32.u64 %0, t; }"
        : "=r"(a) : "l"(p));
    return a;
}
#define CP_ASYNC16(dst, src) \
    asm volatile("cp.async.cg.shared.global [%0], [%1], 16;" \
                 :: "r"(dst), "l"(src) : "memory")
#define CP_COMMIT() asm volatile("cp.async.commit_group;" ::: "memory")
#define CP_WAIT1()  asm volatile("cp.async.wait_group 1;" ::: "memory")
#define CP_WAIT0()  asm volatile("cp.async.wait_group 0;" ::: "memory")
#define LDSM4(r0, r1, r2, r3, addr) \
    asm volatile("ldmatrix.sync.aligned.m8n8.x4.shared.b16 {%0,%1,%2,%3}, [%4];" \
                 : "=r"(r0), "=r"(r1), "=r"(r2), "=r"(r3) : "r"(addr))
#define LDSM4T(r0, r1, r2, r3, addr) \
    asm volatile("ldmatrix.sync.aligned.m8n8.x4.trans.shared.b16 {%0,%1,%2,%3}, [%4];" \
                 : "=r"(r0), "=r"(r1), "=r"(r2), "=r"(r3) : "r"(addr))

__device__ __forceinline__ void mma16816(float* c, const uint32_t* a,
                                         const uint32_t* b) {
    asm volatile(
        "mma.sync.aligned.m16n8k16.row.col.f32.f16.f16.f32 "
        "{%0,%1,%2,%3}, {%4,%5,%6,%7}, {%8,%9}, {%0,%1,%2,%3};"
        : "+f"(c[0]), "+f"(c[1]), "+f"(c[2]), "+f"(c[3])
        : "r"(a[0]), "r"(a[1]), "r"(a[2]), "r"(a[3]), "r"(b[0]), "r"(b[1]));
}
__device__ __forceinline__ uint32_t packh2(float x, float y) {
    __half2 t = __halves2half2(__float2half(x), __float2half(y));
    return *(uint32_t*)&t;
}

// ============================================================================
// 3-segment fp16 split: src [rows][4096] f32 -> dst [rows][12288] fp16
// modeA=1 (X): [hi|hi|lo]; modeA=0 (W): [hi|lo|hi]
// ============================================================================
__global__ void convert_split3h_kernel(const float* __restrict__ src,
                                       __half* __restrict__ dst,
                                       int nquads, int modeA)
{
    int idx = blockIdx.x * blockDim.x + threadIdx.x;
    if (idx >= nquads) return;
    int r  = idx >> 10;
    int c4 = (idx & 1023) * 4;
    float4 x = *(const float4*)(src + (size_t)r * HID + c4);

    __half h0 = __float2half(x.x), h1 = __float2half(x.y);
    __half h2 = __float2half(x.z), h3 = __float2half(x.w);
    __half l0 = __float2half(x.x - __half2float(h0));
    __half l1 = __float2half(x.y - __half2float(h1));
    __half l2 = __float2half(x.z - __half2float(h2));
    __half l3 = __float2half(x.w - __half2float(h3));

    __half2 hA = __halves2half2(h0, h1), hB = __halves2half2(h2, h3);
    __half2 lA = __halves2half2(l0, l1), lB = __halves2half2(l2, l3);

    size_t base = (size_t)r * KP3 + c4;
    __half2* d0 = (__half2*)(dst + base);
    __half2* d1 = (__half2*)(dst + base + HID);
    __half2* d2 = (__half2*)(dst + base + 2 * HID);
    d0[0] = hA; d0[1] = hB;
    if (modeA) { d1[0] = hA; d1[1] = hB; d2[0] = lA; d2[1] = lB; }
    else       { d1[0] = lA; d1[1] = lB; d2[0] = hA; d2[1] = hB; }
}

// Single-segment fp16 rounding (Wv / Wo)
__global__ void convert_roundh_kernel(const float* __restrict__ src,
                                      __half* __restrict__ dst, int nquads)
{
    int idx = blockIdx.x * blockDim.x + threadIdx.x;
    if (idx >= nquads) return;
    float4 x = *(const float4*)(src + (size_t)idx * 4);
    __half2* d = (__half2*)(dst + (size_t)idx * 4);
    d[0] = __halves2half2(__float2half(x.x), __float2half(x.y));
    d[1] = __halves2half2(__float2half(x.z), __float2half(x.w));
}

// ============================================================================
// fp16 mma.sync GEMM. CTA 128x128, BK=64 swizzled, 3-stage ring, 2 CTAs/SM.
// MODE 0: QK proj  (NK=192, A row 24576B straight, B row 24576B straight,
//                   heads out -> C0 (q) / C1 (k) by n0>>12)
// MODE 1: V proj   (NK=128, A row 24576B skip-dup-seg, B row 8192B wrap,
//                   heads out -> C0)
// MODE 2: Wo proj  (NK=128, A row 16384B straight, B row 8192B wrap,
//                   row-major out -> C0)
// ============================================================================
template <int MODE>
__global__ __launch_bounds__(256, 2)
void mma_gemm_kernel(const __half* __restrict__ Ap,
                     const __half* __restrict__ Bp,
                     float* __restrict__ C0, float* __restrict__ C1)
{
    constexpr int NK    = (MODE == 0) ? 192 : 128;
    constexpr int AROWB = (MODE == 2) ? 16384 : 24576;
    constexpr int BROWB = (MODE == 0) ? 24576 : 8192;

    extern __shared__ __align__(1024) char smem[];
    uint32_t sb = smem_u32(smem);

    int tid  = threadIdx.x;
    int wid  = tid >> 5, lane = tid & 31;
    int wm   = wid >> 1;
    int wn   = wid & 1;
    int m0   = blockIdx.x * 128;
    int n0   = blockIdx.y * 128;

    const char* Ag = (const char*)Ap + (size_t)m0 * AROWB;
    const char* Bg = (const char*)Bp + (size_t)n0 * BROWB;

    auto issue_stage = [&](int kt) {
        int buf = kt % 3;
        uint32_t sA = sb + (uint32_t)buf * (2 * STG);
        uint32_t sB = sA + STG;
        size_t akoff = (size_t)kt * 128;
        if (MODE == 1) akoff += (size_t)(kt >> 6) << 13;   // skip duplicate seg
        size_t bkoff = (MODE == 0) ? (size_t)kt * 128 : (size_t)(kt & 63) * 128;
#pragma unroll
        for (int i = 0; i < 4; i++) {
            int u = tid + i * 256;
            int r = u >> 3, c = (u & 7) * 16;
            uint32_t sw = (uint32_t)(r * 128 + (c ^ ((r & 7) << 4)));
            CP_ASYNC16(sA + sw, Ag + (size_t)r * AROWB + akoff + c);
            CP_ASYNC16(sB + sw, Bg + (size_t)r * BROWB + bkoff + c);
        }
    };

    float acc[2][8][4];
#pragma unroll
    for (int i = 0; i < 2; i++)
#pragma unroll
        for (int j = 0; j < 8; j++)
#pragma unroll
            for (int q = 0; q < 4; q++) acc[i][j][q] = 0.0f;

    issue_stage(0); CP_COMMIT();
    issue_stage(1); CP_COMMIT();

    int arow = wm * 32 + (lane & 15);
    uint32_t aL = (uint32_t)(arow * 128 + (((lane >> 4) * 16) ^ ((arow & 7) << 4)));
    int brow = wn * 64 + (lane >> 4) * 8 + (lane & 7);
    uint32_t bL = (uint32_t)(brow * 128 + ((((lane >> 3) & 1) * 16) ^ ((brow & 7) << 4)));

#pragma unroll 1
    for (int kt = 0; kt < NK; kt++) {
        CP_WAIT1();
        __syncthreads();
        if (kt + 2 < NK) { issue_stage(kt + 2); CP_COMMIT(); }

        uint32_t sA = sb + (uint32_t)(kt % 3) * (2 * STG);
        uint32_t sB = sA + STG;

#pragma unroll
        for (int ks = 0; ks < 4; ks++) {
            uint32_t kx = (uint32_t)(ks << 5);
            uint32_t a[2][4], b[8][2];
            LDSM4(a[0][0], a[0][1], a[0][2], a[0][3], (sA + aL) ^ kx);
            LDSM4(a[1][0], a[1][1], a[1][2], a[1][3], (sA + aL + 2048) ^ kx);
#pragma unroll
            for (int t = 0; t < 4; t++)
                LDSM4(b[2 * t][0], b[2 * t][1], b[2 * t + 1][0], b[2 * t + 1][1],
                      (sB + bL + (uint32_t)(t * 2048)) ^ kx);
#pragma unroll
            for (int mt = 0; mt < 2; mt++)
#pragma unroll
                for (int nt = 0; nt < 8; nt++)
                    mma16816(acc[mt][nt], a[mt], b[nt]);
        }
    }
    CP_WAIT0();

    float* base;
    int hh = 0;
    if (MODE == 0) {
        base = (n0 >> 12) ? C1 : C0;
        hh = (n0 & 4095) >> 7;
    } else if (MODE == 1) {
        base = C0;
        hh = n0 >> 7;
    } else {
        base = C0;
    }

#pragma unroll
    for (int mt = 0; mt < 2; mt++) {
        int row = m0 + wm * 32 + mt * 16 + (lane >> 2);
#pragma unroll
        for (int nt = 0; nt < 8; nt++) {
            int col = n0 + wn * 64 + nt * 8 + (lane & 3) * 2;
            float2 v01 = make_float2(acc[mt][nt][0], acc[mt][nt][1]);
            float2 v23 = make_float2(acc[mt][nt][2], acc[mt][nt][3]);
            if (MODE != 2) {
                int cc = col & 127;
                *(float2*)(base + ((size_t)hh * S_LEN + row) * HDIM + cc)     = v01;
                *(float2*)(base + ((size_t)hh * S_LEN + row + 8) * HDIM + cc) = v23;
            } else {
                *(float2*)(base + (size_t)row * HID + col)       = v01;
                *(float2*)(base + (size_t)(row + 8) * HID + col) = v23;
            }
        }
    }
}

// ============================================================================
// RoPE table (fp64 angles)
// ============================================================================
__global__ void rope_table_kernel()
{
    int idx = blockIdx.x * blockDim.x + threadIdx.x;
    if (idx >= S_LEN * 64) return;
    int d = idx & 63;
    int s = idx >> 6;
    double inv = pow(10000.0, -(double)(2 * d) / 128.0);
    double sd, cd;
    sincos((double)s * inv, &sd, &cd);
    g_cosT[idx] = (float)cd;
    g_sinT[idx] = (float)sd;
}

// ============================================================================
// Fused rope + fp16 split: q scaled+split (hi/lo), k split (hi/lo), v rounded.
// Post-rope k written back fp32 for eviction.
// ============================================================================
__global__ void rope_split_kernel()
{
    int idx = blockIdx.x * blockDim.x + threadIdx.x;
    if (idx >= NHEAD * S_LEN * 64) return;
    int t = idx & (S_LEN * 64 - 1);
    int d = idx & 63;
    int s = (idx >> 6) & (S_LEN - 1);
    int h = idx >> 17;
    float c = g_cosT[t], sn = g_sinT[t];
    const float scale = 0.08838834764831845f;

    size_t base = ((size_t)h * S_LEN + s) * HDIM;
    float q1 = g_q[base + d], q2 = g_q[base + d + 64];
    float k1 = g_k[base + d], k2 = g_k[base + d + 64];
    float v1 = g_v[base + d], v2 = g_v[base + d + 64];

    float qr1 = (q1 * c - q2 * sn) * scale;
    float qr2 = (q2 * c + q1 * sn) * scale;
    float kr1 = k1 * c - k2 * sn;
    float kr2 = k2 * c + k1 * sn;

    g_k[base + d]      = kr1;
    g_k[base + d + 64] = kr2;

    __half qh1 = __float2half(qr1), qh2 = __float2half(qr2);
    __half kh1 = __float2half(kr1), kh2 = __float2half(kr2);
    g_qh[base + d]      = qh1;
    g_qh[base + d + 64] = qh2;
    g_ql[base + d]      = __float2half(qr1 - __half2float(qh1));
    g_ql[base + d + 64] = __float2half(qr2 - __half2float(qh2));
    g_kh[base + d]      = kh1;
    g_kh[base + d + 64] = kh2;
    g_kl[base + d]      = __float2half(kr1 - __half2float(kh1));
    g_kl[base + d + 64] = __float2half(kr2 - __half2float(kh2));
    g_vh[base + d]      = __float2half(v1);
    g_vh[base + d + 64] = __float2half(v2);
}

// ============================================================================
// Flash attention fp16: QK 3-term exact, PV 2-term (P exact, V rounded).
// Br=128, 8 warps along M, register P, warp-local softmax.
// Epilogue writes Wo activations [hi|lo] fp16 into g_xp2.
// ============================================================================
__global__ __launch_bounds__(256, 1)
void flash_mma_kernel(__half* __restrict__ xp2)
{
    extern __shared__ char fsm_raw[];
    uint32_t sb  = smem_u32(fsm_raw);
    uint32_t sQh = sb;
    uint32_t sQl = sb + FQ;
    uint32_t sKh = sb + 2 * FQ;          // + b*FTILE
    uint32_t sKl = sKh + 2 * FTILE;
    uint32_t sVh = sKl + 2 * FTILE;

    int qb  = 15 - blockIdx.x;
    int h   = blockIdx.y;
    int tid = threadIdx.x, wid = tid >> 5, lane = tid & 31;
    int q0  = qb * 128;
    int lastkt = 2 * qb + 1;

    const __half* qhp = g_qh + ((size_t)h * S_LEN + q0) * HDIM;
    const __half* qlp = g_ql + ((size_t)h * S_LEN + q0) * HDIM;
    const __half* khp = g_kh + (size_t)h * S_LEN * HDIM;
    const __half* klp = g_kl + (size_t)h * S_LEN * HDIM;
    const __half* vhp = g_vh + (size_t)h * S_LEN * HDIM;

    auto load_tile = [&](int kt, int bb) {
        uint32_t dKh = sKh + (uint32_t)bb * FTILE;
        uint32_t dKl = sKl + (uint32_t)bb * FTILE;
        uint32_t dVh = sVh + (uint32_t)bb * FTILE;
        const __half* s1 = khp + (size_t)kt * 64 * HDIM;
        const __half* s2 = klp + (size_t)kt * 64 * HDIM;
        const __half* s3 = vhp + (size_t)kt * 64 * HDIM;
#pragma unroll
        for (int i = 0; i < 4; i++) {
            int u = tid + i * 256;
            int r = u >> 4, cb = (u & 15) * 16, ce = (u & 15) * 8;
            CP_ASYNC16(dKh + r * FT + cb, s1 + r * HDIM + ce);
            CP_ASYNC16(dKl + r * FT + cb, s2 + r * HDIM + ce);
            CP_ASYNC16(dVh + r * FT + cb, s3 + r * HDIM + ce);
        }
    };

#pragma unroll
    for (int i = 0; i < 8; i++) {
        int u = tid + i * 256;
        int r = u >> 4, cb = (u & 15) * 16, ce = (u & 15) * 8;
        CP_ASYNC16(sQh + r * FT + cb, qhp + r * HDIM + ce);
        CP_ASYNC16(sQl + r * FT + cb, qlp + r * HDIM + ce);
    }
    load_tile(0, 0);
    CP_COMMIT();

    float oacc[16][4];
#pragma unroll
    for (int i = 0; i < 16; i++)
#pragma unroll
        for (int j = 0; j < 4; j++) oacc[i][j] = 0.0f;
    float m0 = -INFINITY, m1 = -INFINITY, l0 = 0.0f, l1 = 0.0f;

    uint32_t aLq = (uint32_t)((wid * 16 + (lane & 15)) * FT + (lane >> 4) * 16);
    uint32_t bLk = (uint32_t)(((lane >> 4) * 8 + (lane & 7)) * FT
                              + ((lane >> 3) & 1) * 16);
    uint32_t vLb = (uint32_t)((lane & 15) * FT + (lane >> 4) * 16);
    int r0 = lane >> 2;

#pragma unroll 1
    for (int kt = 0; kt <= lastkt; kt++) {
        int b = kt & 1;
        CP_WAIT0();
        __syncthreads();
        if (kt < lastkt) { load_tile(kt + 1, b ^ 1); CP_COMMIT(); }

        uint32_t Kh = sKh + (uint32_t)b * FTILE;
        uint32_t Kl = sKl + (uint32_t)b * FTILE;
        uint32_t Vh = sVh + (uint32_t)b * FTILE;

        // ---- scores: Qh·Kh + Ql·Kh + Qh·Kl (drop Ql·Kl ~2^-22) ----
        float sacc[8][4];
#pragma unroll
        for (int i = 0; i < 8; i++)
#pragma unroll
            for (int j = 0; j < 4; j++) sacc[i][j] = 0.0f;
#pragma unroll
        for (int ks = 0; ks < 8; ks++) {
            uint32_t ah[4], al[4];
            LDSM4(ah[0], ah[1], ah[2], ah[3], sQh + aLq + ks * 32);
            LDSM4(al[0], al[1], al[2], al[3], sQl + aLq + ks * 32);
#pragma unroll
            for (int t = 0; t < 4; t++) {
                uint32_t x[4], y[4];
                LDSM4(x[0], x[1], x[2], x[3], Kh + bLk + t * 16 * FT + ks * 32);
                mma16816(sacc[2 * t],     ah, &x[0]);
                mma16816(sacc[2 * t + 1], ah, &x[2]);
                mma16816(sacc[2 * t],     al, &x[0]);
                mma16816(sacc[2 * t + 1], al, &x[2]);
                LDSM4(y[0], y[1], y[2], y[3], Kl + bLk + t * 16 * FT + ks * 32);
                mma16816(sacc[2 * t],     ah, &y[0]);
                mma16816(sacc[2 * t + 1], ah, &y[2]);
            }
        }

        if (kt >= 2 * qb) {
            int gr0 = q0 + wid * 16 + r0;
            int gr1 = gr0 + 8;
            int gcb = kt * 64 + (lane & 3) * 2;
#pragma unroll
            for (int nt = 0; nt < 8; nt++) {
                int gc = gcb + nt * 8;
                if (gc     > gr0) sacc[nt][0] = -INFINITY;
                if (gc + 1 > gr0) sacc[nt][1] = -INFINITY;
                if (gc     > gr1) sacc[nt][2] = -INFINITY;
                if (gc + 1 > gr1) sacc[nt][3] = -INFINITY;
            }
        }

        float tm0 = -INFINITY, tm1 = -INFINITY;
#pragma unroll
        for (int nt = 0; nt < 8; nt++) {
            tm0 = fmaxf(tm0, fmaxf(sacc[nt][0], sacc[nt][1]));
            tm1 = fmaxf(tm1, fmaxf(sacc[nt][2], sacc[nt][3]));
        }
        tm0 = fmaxf(tm0, __shfl_xor_sync(0xffffffffu, tm0, 1));
        tm0 = fmaxf(tm0, __shfl_xor_sync(0xffffffffu, tm0, 2));
        tm1 = fmaxf(tm1, __shfl_xor_sync(0xffffffffu, tm1, 1));
        tm1 = fmaxf(tm1, __shfl_xor_sync(0xffffffffu, tm1, 2));

        float mn0 = fmaxf(m0, tm0), mn1 = fmaxf(m1, tm1);
        float al0 = __expf(m0 - mn0), al1 = __expf(m1 - mn1);
        m0 = mn0; m1 = mn1;

        float s0 = 0.0f, s1 = 0.0f;
#pragma unroll
        for (int nt = 0; nt < 8; nt++) {
            sacc[nt][0] = __expf(sacc[nt][0] - mn0);
            sacc[nt][1] = __expf(sacc[nt][1] - mn0);
            sacc[nt][2] = __expf(sacc[nt][2] - mn1);
            sacc[nt][3] = __expf(sacc[nt][3] - mn1);
            s0 += sacc[nt][0] + sacc[nt][1];
            s1 += sacc[nt][2] + sacc[nt][3];
        }
        s0 += __shfl_xor_sync(0xffffffffu, s0, 1);
        s0 += __shfl_xor_sync(0xffffffffu, s0, 2);
        s1 += __shfl_xor_sync(0xffffffffu, s1, 1);
        s1 += __shfl_xor_sync(0xffffffffu, s1, 2);
        l0 = l0 * al0 + s0;
        l1 = l1 * al1 + s1;

#pragma unroll
        for (int dt = 0; dt < 16; dt++) {
            oacc[dt][0] *= al0; oacc[dt][1] *= al0;
            oacc[dt][2] *= al1; oacc[dt][3] *= al1;
        }

        // ---- pack P into fp16 hi/lo A-fragments ----
        uint32_t aPh[4][4], aPl[4][4];
#pragma unroll
        for (int ks = 0; ks < 4; ks++) {
            float p00 = sacc[2 * ks][0],     p01 = sacc[2 * ks][1];
            float p02 = sacc[2 * ks][2],     p03 = sacc[2 * ks][3];
            float p10 = sacc[2 * ks + 1][0], p11 = sacc[2 * ks + 1][1];
            float p12 = sacc[2 * ks + 1][2], p13 = sacc[2 * ks + 1][3];
            aPh[ks][0] = packh2(p00, p01);
            aPh[ks][1] = packh2(p02, p03);
            aPh[ks][2] = packh2(p10, p11);
            aPh[ks][3] = packh2(p12, p13);
            __half2 t0 = *(__half2*)&aPh[ks][0];
            __half2 t1 = *(__half2*)&aPh[ks][1];
            __half2 t2 = *(__half2*)&aPh[ks][2];
            __half2 t3 = *(__half2*)&aPh[ks][3];
            aPl[ks][0] = packh2(p00 - __half2float(__low2half(t0)),
                                p01 - __half2float(__high2half(t0)));
            aPl[ks][1] = packh2(p02 - __half2float(__low2half(t1)),
                                p03 - __half2float(__high2half(t1)));
            aPl[ks][2] = packh2(p10 - __half2float(__low2half(t2)),
                                p11 - __half2float(__high2half(t2)));
            aPl[ks][3] = packh2(p12 - __half2float(__low2half(t3)),
                                p13 - __half2float(__high2half(t3)));
        }

        // ---- P.V: Ph·Vh + Pl·Vh (V rounded; drop P·Vl ~2e-4) ----
#pragma unroll
        for (int ks = 0; ks < 4; ks++) {
#pragma unroll
            for (int dp = 0; dp < 8; dp++) {
                uint32_t bh[4];
                LDSM4T(bh[0], bh[1], bh[2], bh[3],
                       Vh + vLb + (uint32_t)(ks * 16) * FT + dp * 32);
                mma16816(oacc[2 * dp],     aPh[ks], &bh[0]);
                mma16816(oacc[2 * dp + 1], aPh[ks], &bh[2]);
                mma16816(oacc[2 * dp],     aPl[ks], &bh[0]);
                mma16816(oacc[2 * dp + 1], aPl[ks], &bh[2]);
            }
        }
    }

    // ---- epilogue: write [hi|lo] fp16 activations for Wo GEMM ----
    float inv0 = 1.0f / l0, inv1 = 1.0f / l1;
    int grow = q0 + wid * 16 + r0;
#pragma unroll
    for (int dt = 0; dt < 16; dt++) {
        int col = h * HDIM + dt * 8 + (lane & 3) * 2;
        float v0 = oacc[dt][0] * inv0, v1 = oacc[dt][1] * inv0;
        float v2 = oacc[dt][2] * inv1, v3 = oacc[dt][3] * inv1;

        __half h0 = __float2half(v0), h1 = __float2half(v1);
        __half h2 = __float2half(v2), h3 = __float2half(v3);
        __half2 hi01 = __halves2half2(h0, h1);
        __half2 hi23 = __halves2half2(h2, h3);
        uint32_t lo01 = packh2(v0 - __half2float(h0), v1 - __half2float(h1));
        uint32_t lo23 = packh2(v2 - __half2float(h2), v3 - __half2float(h3));

        uint32_t* pA = (uint32_t*)(xp2 + (size_t)grow * (2 * HID) + col);
        pA[0]       = *(uint32_t*)&hi01;
        pA[HID / 2] = lo01;
        uint32_t* pB = (uint32_t*)(xp2 + (size_t)(grow + 8) * (2 * HID) + col);
        pB[0]       = *(uint32_t*)&hi23;
        pB[HID / 2] = lo23;
    }
}

// ============================================================================
// KV eviction
// ============================================================================
__global__ void evict_kernel(float* __restrict__ outk, float* __restrict__ outv)
{
    int idx = blockIdx.x * blockDim.x + threadIdx.x;
    if (idx >= NHEAD * EVLEN * HDIM) return;
    int d = idx & 127;
    int t = (idx >> 7) % EVLEN;
    int h = idx / (EVLEN * HDIM);
    int src = (t < SINKN) ? t : (S_LEN - RECENT) + (t - SINKN);
    size_t si = ((size_t)h * S_LEN + src) * HDIM + d;
    outk[idx] = g_k[si];
    outv[idx] = g_v[si];
}

// ============================================================================
extern "C" void kernel_launch(void* const* d_in, const int* in_sizes, int n_in,
                              void* d_out, int out_size)
{
    const float* X  = (const float*)d_in[0];
    const float* Wq = (const float*)d_in[1];
    const float* Wk = (const float*)d_in[2];
    const float* Wv = (const float*)d_in[3];
    const float* Wo = (const float*)d_in[4];
    float* out = (float*)d_out;

    float *qb, *kb, *vb;
    __half *xp3, *xp2, *wqk, *wv, *wo;
    cudaGetSymbolAddress((void**)&qb,  g_q);
    cudaGetSymbolAddress((void**)&kb,  g_k);
    cudaGetSymbolAddress((void**)&vb,  g_v);
    cudaGetSymbolAddress((void**)&xp3, g_xp3);
    cudaGetSymbolAddress((void**)&xp2, g_xp2);
    cudaGetSymbolAddress((void**)&wqk, g_wqk);
    cudaGetSymbolAddress((void**)&wv,  g_wv);
    cudaGetSymbolAddress((void**)&wo,  g_wo);

    cudaFuncSetAttribute(mma_gemm_kernel<0>,
                         cudaFuncAttributeMaxDynamicSharedMemorySize, GEMM_SMEM);
    cudaFuncSetAttribute(mma_gemm_kernel<1>,
                         cudaFuncAttributeMaxDynamicSharedMemorySize, GEMM_SMEM);
    cudaFuncSetAttribute(mma_gemm_kernel<2>,
                         cudaFuncAttributeMaxDynamicSharedMemorySize, GEMM_SMEM);
    cudaFuncSetAttribute(flash_mma_kernel,
                         cudaFuncAttributeMaxDynamicSharedMemorySize, FA_SMEM);

    const int XQ = S_LEN * 1024;
    const int WQ = HID * 1024;
    const size_t WSEG3 = (size_t)HID * KP3;

    rope_table_kernel<<<(S_LEN * 64 + 255) / 256, 256>>>();

    convert_split3h_kernel<<<(XQ + 255) / 256, 256>>>(X, xp3, XQ, 1);
    convert_split3h_kernel<<<(WQ + 255) / 256, 256>>>(Wq, wqk,         WQ, 0);
    convert_split3h_kernel<<<(WQ + 255) / 256, 256>>>(Wk, wqk + WSEG3, WQ, 0);
    convert_roundh_kernel<<<(WQ + 255) / 256, 256>>>(Wv, wv, WQ);
    convert_roundh_kernel<<<(WQ + 255) / 256, 256>>>(Wo, wo, WQ);

    // Q,K projections (fp16 3-term, N=8192)
    dim3 gqk(S_LEN / 128, (2 * HID) / 128);    // (16, 64)
    mma_gemm_kernel<0><<<gqk, 256, GEMM_SMEM>>>(xp3, wqk, qb, kb);

    // V projection (fp16 2-term, N=4096)
    dim3 gv(S_LEN / 128, HID / 128);           // (16, 32)
    mma_gemm_kernel<1><<<gv, 256, GEMM_SMEM>>>(xp3, wv, vb, vb);

    rope_split_kernel<<<(NHEAD * S_LEN * 64) / 256, 256>>>();

    flash_mma_kernel<<<dim3(16, 32), 256, FA_SMEM>>>(xp2);

    // output projection (fp16 2-term)
    mma_gemm_kernel<2><<<gv, 256, GEMM_SMEM>>>(xp2, wo, out, out);

    size_t attn_elems = (size_t)S_LEN * HID;
    size_t ev_elems   = (size_t)NHEAD * EVLEN * HDIM;
    evict_kernel<<<(int)((ev_elems + 255) / 256), 256>>>(out + attn_elems,
                                                         out + attn_elems + ev_elems);
}

// round 9
// speedup vs baseline: 4.0689x; 1.0126x over previous
#include <cuda_runtime.h>
#include <cuda_fp16.h>
#include <math.h>
#include <stdint.h>

#define S_LEN  2048
#define HID    4096
#define NHEAD  32
#define HDIM   128
#define RECENT 204
#define SINKN  4
#define EVLEN  (SINKN + RECENT)   // 208

#define KP3    (3 * HID)     // 12288 (3-term split K)
#define STG    16384         // bytes per operand per stage (128 rows x 128 B)
#define GEMM_SMEM (3 * 2 * STG)   // 98304

// flash smem: 272 B per row (128 fp16 + pad)
#define FT     272
#define FTILE  (64 * FT)                // 17408
#define FQ     (128 * FT)               // 34816
#define FA_SMEM (2 * FQ + 6 * FTILE)    // 174080

// -------- static scratch --------
static __device__ float g_q[NHEAD * S_LEN * HDIM];
static __device__ float g_k[NHEAD * S_LEN * HDIM];
static __device__ float g_v[NHEAD * S_LEN * HDIM];
static __device__ __half g_xp3[(size_t)S_LEN * KP3];     // X  [hi|hi|lo]
static __device__ __half g_xp2[(size_t)S_LEN * 2 * HID]; // O  [hi|lo]
static __device__ __half g_wqk[2ULL * HID * KP3];        // Wq|Wk [hi|lo|hi]
static __device__ __half g_wv[(size_t)HID * HID];        // Wv hi
static __device__ __half g_wo[(size_t)HID * HID];        // Wo hi
static __device__ __half g_qh[NHEAD * S_LEN * HDIM];
static __device__ __half g_ql[NHEAD * S_LEN * HDIM];
static __device__ __half g_kh[NHEAD * S_LEN * HDIM];
static __device__ __half g_kl[NHEAD * S_LEN * HDIM];
static __device__ __half g_vh[NHEAD * S_LEN * HDIM];
static __device__ float g_cosT[S_LEN * 64];
static __device__ float g_sinT[S_LEN * 64];

// ============================ helpers =======================================
__device__ __forceinline__ uint32_t smem_u32(const void* p) {
    uint32_t a;
    asm("{ .reg .u64 t; cvta.to.shared.u64 t, %1; cvt.u32.u64 %0, t; }"
        : "=r"(a) : "l"(p));
    return a;
}
#define CP_ASYNC16(dst, src) \
    asm volatile("cp.async.cg.shared.global [%0], [%1], 16;" \
                 :: "r"(dst), "l"(src) : "memory")
#define CP_COMMIT() asm volatile("cp.async.commit_group;" ::: "memory")
#define CP_WAIT1()  asm volatile("cp.async.wait_group 1;" ::: "memory")
#define CP_WAIT0()  asm volatile("cp.async.wait_group 0;" ::: "memory")
#define LDSM4(r0, r1, r2, r3, addr) \
    asm volatile("ldmatrix.sync.aligned.m8n8.x4.shared.b16 {%0,%1,%2,%3}, [%4];" \
                 : "=r"(r0), "=r"(r1), "=r"(r2), "=r"(r3) : "r"(addr))
#define LDSM4T(r0, r1, r2, r3, addr) \
    asm volatile("ldmatrix.sync.aligned.m8n8.x4.trans.shared.b16 {%0,%1,%2,%3}, [%4];" \
                 : "=r"(r0), "=r"(r1), "=r"(r2), "=r"(r3) : "r"(addr))

__device__ __forceinline__ void mma16816(float* c, const uint32_t* a,
                                         const uint32_t* b) {
    asm volatile(
        "mma.sync.aligned.m16n8k16.row.col.f32.f16.f16.f32 "
        "{%0,%1,%2,%3}, {%4,%5,%6,%7}, {%8,%9}, {%0,%1,%2,%3};"
        : "+f"(c[0]), "+f"(c[1]), "+f"(c[2]), "+f"(c[3])
        : "r"(a[0]), "r"(a[1]), "r"(a[2]), "r"(a[3]), "r"(b[0]), "r"(b[1]));
}
__device__ __forceinline__ uint32_t packh2(float x, float y) {
    __half2 t = __halves2half2(__float2half(x), __float2half(y));
    return *(uint32_t*)&t;
}

// ============================================================================
// 3-segment fp16 split, 8 elements/thread, 16B stores.
// modeA=1 (X): [hi|hi|lo]; modeA=0 (W): [hi|lo|hi]
// ============================================================================
__global__ void convert_split3h_kernel(const float* __restrict__ src,
                                       __half* __restrict__ dst,
                                       int nocts, int modeA)
{
    int idx = blockIdx.x * blockDim.x + threadIdx.x;
    if (idx >= nocts) return;
    int r  = idx >> 9;
    int c8 = (idx & 511) * 8;
    const float* s = src + (size_t)r * HID + c8;
    float4 x0 = *(const float4*)(s);
    float4 x1 = *(const float4*)(s + 4);

    float xs[8] = {x0.x, x0.y, x0.z, x0.w, x1.x, x1.y, x1.z, x1.w};
    __half hv[8], lv[8];
#pragma unroll
    for (int i = 0; i < 8; i++) {
        hv[i] = __float2half(xs[i]);
        lv[i] = __float2half(xs[i] - __half2float(hv[i]));
    }
    uint4 hi4, lo4;
    ((__half2*)&hi4)[0] = __halves2half2(hv[0], hv[1]);
    ((__half2*)&hi4)[1] = __halves2half2(hv[2], hv[3]);
    ((__half2*)&hi4)[2] = __halves2half2(hv[4], hv[5]);
    ((__half2*)&hi4)[3] = __halves2half2(hv[6], hv[7]);
    ((__half2*)&lo4)[0] = __halves2half2(lv[0], lv[1]);
    ((__half2*)&lo4)[1] = __halves2half2(lv[2], lv[3]);
    ((__half2*)&lo4)[2] = __halves2half2(lv[4], lv[5]);
    ((__half2*)&lo4)[3] = __halves2half2(lv[6], lv[7]);

    size_t base = (size_t)r * KP3 + c8;
    *(uint4*)(dst + base) = hi4;
    if (modeA) {
        *(uint4*)(dst + base + HID)     = hi4;
        *(uint4*)(dst + base + 2 * HID) = lo4;
    } else {
        *(uint4*)(dst + base + HID)     = lo4;
        *(uint4*)(dst + base + 2 * HID) = hi4;
    }
}

// Single-segment fp16 rounding (Wv / Wo), 8 elements/thread
__global__ void convert_roundh_kernel(const float* __restrict__ src,
                                      __half* __restrict__ dst, int nocts)
{
    int idx = blockIdx.x * blockDim.x + threadIdx.x;
    if (idx >= nocts) return;
    const float* s = src + (size_t)idx * 8;
    float4 x0 = *(const float4*)(s);
    float4 x1 = *(const float4*)(s + 4);
    uint4 o;
    ((__half2*)&o)[0] = __halves2half2(__float2half(x0.x), __float2half(x0.y));
    ((__half2*)&o)[1] = __halves2half2(__float2half(x0.z), __float2half(x0.w));
    ((__half2*)&o)[2] = __halves2half2(__float2half(x1.x), __float2half(x1.y));
    ((__half2*)&o)[3] = __halves2half2(__float2half(x1.z), __float2half(x1.w));
    *(uint4*)(dst + (size_t)idx * 8) = o;
}

// ============================================================================
// Merged QKV GEMM: one launch, 1536 CTAs.
//  bid < 1024 : QK tile  (NK=192, A=[hi|hi|lo] straight, B=wqk row 24576B,
//                          out q/k heads by n0)
//  bid >= 1024: V tile   (NK=128, A skips dup seg -> [hi|lo], B=wv wrap 8192B,
//                          out v heads)
// QK (1.5x-cost) tiles dispatched first so V tiles backfill the tail wave.
// ============================================================================
__global__ __launch_bounds__(256, 2)
void mma_gemm_qkv_kernel(const __half* __restrict__ Ap,
                         const __half* __restrict__ Bqk,
                         const __half* __restrict__ Bv,
                         float* __restrict__ Cq, float* __restrict__ Ck,
                         float* __restrict__ Cv)
{
    extern __shared__ __align__(1024) char smem[];
    uint32_t sb = smem_u32(smem);

    int bid = blockIdx.x;
    bool isQK = bid < 1024;
    int t = isQK ? bid : bid - 1024;
    int m0 = (t & 15) * 128;       // m fastest for L2 reuse of A
    int n0 = (t >> 4) * 128;
    int NK = isQK ? 192 : 128;
    int BROWB = isQK ? 24576 : 8192;

    int tid  = threadIdx.x;
    int wid  = tid >> 5, lane = tid & 31;
    int wm   = wid >> 1;
    int wn   = wid & 1;

    const char* Ag = (const char*)Ap + (size_t)m0 * 24576;
    const char* Bg = isQK ? (const char*)Bqk + (size_t)n0 * 24576
                          : (const char*)Bv  + (size_t)n0 * 8192;

    auto issue_stage = [&](int kt) {
        int buf = kt % 3;
        uint32_t sA = sb + (uint32_t)buf * (2 * STG);
        uint32_t sB = sA + STG;
        size_t akoff = (size_t)kt * 128;
        if (!isQK) akoff += (size_t)(kt >> 6) << 13;   // skip duplicate hi seg
        size_t bkoff = isQK ? (size_t)kt * 128 : (size_t)(kt & 63) * 128;
#pragma unroll
        for (int i = 0; i < 4; i++) {
            int u = tid + i * 256;
            int r = u >> 3, c = (u & 7) * 16;
            uint32_t sw = (uint32_t)(r * 128 + (c ^ ((r & 7) << 4)));
            CP_ASYNC16(sA + sw, Ag + (size_t)r * 24576 + akoff + c);
            CP_ASYNC16(sB + sw, Bg + (size_t)r * BROWB + bkoff + c);
        }
    };

    float acc[2][8][4];
#pragma unroll
    for (int i = 0; i < 2; i++)
#pragma unroll
        for (int j = 0; j < 8; j++)
#pragma unroll
            for (int q = 0; q < 4; q++) acc[i][j][q] = 0.0f;

    issue_stage(0); CP_COMMIT();
    issue_stage(1); CP_COMMIT();

    int arow = wm * 32 + (lane & 15);
    uint32_t aL = (uint32_t)(arow * 128 + (((lane >> 4) * 16) ^ ((arow & 7) << 4)));
    int brow = wn * 64 + (lane >> 4) * 8 + (lane & 7);
    uint32_t bL = (uint32_t)(brow * 128 + ((((lane >> 3) & 1) * 16) ^ ((brow & 7) << 4)));

#pragma unroll 1
    for (int kt = 0; kt < NK; kt++) {
        CP_WAIT1();
        __syncthreads();
        if (kt + 2 < NK) { issue_stage(kt + 2); CP_COMMIT(); }

        uint32_t sA = sb + (uint32_t)(kt % 3) * (2 * STG);
        uint32_t sB = sA + STG;

#pragma unroll
        for (int ks = 0; ks < 4; ks++) {
            uint32_t kx = (uint32_t)(ks << 5);
            uint32_t a[2][4], b[8][2];
            LDSM4(a[0][0], a[0][1], a[0][2], a[0][3], (sA + aL) ^ kx);
            LDSM4(a[1][0], a[1][1], a[1][2], a[1][3], (sA + aL + 2048) ^ kx);
#pragma unroll
            for (int tt = 0; tt < 4; tt++)
                LDSM4(b[2 * tt][0], b[2 * tt][1], b[2 * tt + 1][0], b[2 * tt + 1][1],
                      (sB + bL + (uint32_t)(tt * 2048)) ^ kx);
#pragma unroll
            for (int mt = 0; mt < 2; mt++)
#pragma unroll
                for (int nt = 0; nt < 8; nt++)
                    mma16816(acc[mt][nt], a[mt], b[nt]);
        }
    }
    CP_WAIT0();

    float* base;
    int hh;
    if (isQK) {
        base = (n0 >= 4096) ? Ck : Cq;
        hh = (n0 & 4095) >> 7;
    } else {
        base = Cv;
        hh = n0 >> 7;
    }

#pragma unroll
    for (int mt = 0; mt < 2; mt++) {
        int row = m0 + wm * 32 + mt * 16 + (lane >> 2);
#pragma unroll
        for (int nt = 0; nt < 8; nt++) {
            int col = wn * 64 + nt * 8 + (lane & 3) * 2;   // within 128-wide head
            float2 v01 = make_float2(acc[mt][nt][0], acc[mt][nt][1]);
            float2 v23 = make_float2(acc[mt][nt][2], acc[mt][nt][3]);
            *(float2*)(base + ((size_t)hh * S_LEN + row) * HDIM + col)     = v01;
            *(float2*)(base + ((size_t)hh * S_LEN + row + 8) * HDIM + col) = v23;
        }
    }
}

// ============================================================================
// Wo GEMM (2-term fp16, NK=128), row-major out. Same pipeline as merged.
// ============================================================================
__global__ __launch_bounds__(256, 2)
void mma_gemm_wo_kernel(const __half* __restrict__ Ap,
                        const __half* __restrict__ Bp,
                        float* __restrict__ C)
{
    extern __shared__ __align__(1024) char smem[];
    uint32_t sb = smem_u32(smem);

    int tid  = threadIdx.x;
    int wid  = tid >> 5, lane = tid & 31;
    int wm   = wid >> 1;
    int wn   = wid & 1;
    int m0   = blockIdx.x * 128;
    int n0   = blockIdx.y * 128;

    const char* Ag = (const char*)Ap + (size_t)m0 * 16384;
    const char* Bg = (const char*)Bp + (size_t)n0 * 8192;

    auto issue_stage = [&](int kt) {
        int buf = kt % 3;
        uint32_t sA = sb + (uint32_t)buf * (2 * STG);
        uint32_t sB = sA + STG;
        size_t akoff = (size_t)kt * 128;
        size_t bkoff = (size_t)(kt & 63) * 128;
#pragma unroll
        for (int i = 0; i < 4; i++) {
            int u = tid + i * 256;
            int r = u >> 3, c = (u & 7) * 16;
            uint32_t sw = (uint32_t)(r * 128 + (c ^ ((r & 7) << 4)));
            CP_ASYNC16(sA + sw, Ag + (size_t)r * 16384 + akoff + c);
            CP_ASYNC16(sB + sw, Bg + (size_t)r * 8192 + bkoff + c);
        }
    };

    float acc[2][8][4];
#pragma unroll
    for (int i = 0; i < 2; i++)
#pragma unroll
        for (int j = 0; j < 8; j++)
#pragma unroll
            for (int q = 0; q < 4; q++) acc[i][j][q] = 0.0f;

    issue_stage(0); CP_COMMIT();
    issue_stage(1); CP_COMMIT();

    int arow = wm * 32 + (lane & 15);
    uint32_t aL = (uint32_t)(arow * 128 + (((lane >> 4) * 16) ^ ((arow & 7) << 4)));
    int brow = wn * 64 + (lane >> 4) * 8 + (lane & 7);
    uint32_t bL = (uint32_t)(brow * 128 + ((((lane >> 3) & 1) * 16) ^ ((brow & 7) << 4)));

#pragma unroll 1
    for (int kt = 0; kt < 128; kt++) {
        CP_WAIT1();
        __syncthreads();
        if (kt + 2 < 128) { issue_stage(kt + 2); CP_COMMIT(); }

        uint32_t sA = sb + (uint32_t)(kt % 3) * (2 * STG);
        uint32_t sB = sA + STG;

#pragma unroll
        for (int ks = 0; ks < 4; ks++) {
            uint32_t kx = (uint32_t)(ks << 5);
            uint32_t a[2][4], b[8][2];
            LDSM4(a[0][0], a[0][1], a[0][2], a[0][3], (sA + aL) ^ kx);
            LDSM4(a[1][0], a[1][1], a[1][2], a[1][3], (sA + aL + 2048) ^ kx);
#pragma unroll
            for (int tt = 0; tt < 4; tt++)
                LDSM4(b[2 * tt][0], b[2 * tt][1], b[2 * tt + 1][0], b[2 * tt + 1][1],
                      (sB + bL + (uint32_t)(tt * 2048)) ^ kx);
#pragma unroll
            for (int mt = 0; mt < 2; mt++)
#pragma unroll
                for (int nt = 0; nt < 8; nt++)
                    mma16816(acc[mt][nt], a[mt], b[nt]);
        }
    }
    CP_WAIT0();

#pragma unroll
    for (int mt = 0; mt < 2; mt++) {
        int row = m0 + wm * 32 + mt * 16 + (lane >> 2);
#pragma unroll
        for (int nt = 0; nt < 8; nt++) {
            int col = n0 + wn * 64 + nt * 8 + (lane & 3) * 2;
            *(float2*)(C + (size_t)row * HID + col) =
                make_float2(acc[mt][nt][0], acc[mt][nt][1]);
            *(float2*)(C + (size_t)(row + 8) * HID + col) =
                make_float2(acc[mt][nt][2], acc[mt][nt][3]);
        }
    }
}

// ============================================================================
// RoPE table (fp64 angles)
// ============================================================================
__global__ void rope_table_kernel()
{
    int idx = blockIdx.x * blockDim.x + threadIdx.x;
    if (idx >= S_LEN * 64) return;
    int d = idx & 63;
    int s = idx >> 6;
    double inv = pow(10000.0, -(double)(2 * d) / 128.0);
    double sd, cd;
    sincos((double)s * inv, &sd, &cd);
    g_cosT[idx] = (float)cd;
    g_sinT[idx] = (float)sd;
}

// ============================================================================
// Fused rope + fp16 split (verified R8)
// ============================================================================
__global__ void rope_split_kernel()
{
    int idx = blockIdx.x * blockDim.x + threadIdx.x;
    if (idx >= NHEAD * S_LEN * 64) return;
    int t = idx & (S_LEN * 64 - 1);
    int d = idx & 63;
    int s = (idx >> 6) & (S_LEN - 1);
    int h = idx >> 17;
    float c = g_cosT[t], sn = g_sinT[t];
    const float scale = 0.08838834764831845f;

    size_t base = ((size_t)h * S_LEN + s) * HDIM;
    float q1 = g_q[base + d], q2 = g_q[base + d + 64];
    float k1 = g_k[base + d], k2 = g_k[base + d + 64];
    float v1 = g_v[base + d], v2 = g_v[base + d + 64];

    float qr1 = (q1 * c - q2 * sn) * scale;
    float qr2 = (q2 * c + q1 * sn) * scale;
    float kr1 = k1 * c - k2 * sn;
    float kr2 = k2 * c + k1 * sn;

    g_k[base + d]      = kr1;
    g_k[base + d + 64] = kr2;

    __half qh1 = __float2half(qr1), qh2 = __float2half(qr2);
    __half kh1 = __float2half(kr1), kh2 = __float2half(kr2);
    g_qh[base + d]      = qh1;
    g_qh[base + d + 64] = qh2;
    g_ql[base + d]      = __float2half(qr1 - __half2float(qh1));
    g_ql[base + d + 64] = __float2half(qr2 - __half2float(qh2));
    g_kh[base + d]      = kh1;
    g_kh[base + d + 64] = kh2;
    g_kl[base + d]      = __float2half(kr1 - __half2float(kh1));
    g_kl[base + d + 64] = __float2half(kr2 - __half2float(kh2));
    g_vh[base + d]      = __float2half(v1);
    g_vh[base + d + 64] = __float2half(v2);
}

// ============================================================================
// Flash attention fp16 (verified R8): QK 3-term, PV 2-term, register P.
// ============================================================================
__global__ __launch_bounds__(256, 1)
void flash_mma_kernel(__half* __restrict__ xp2)
{
    extern __shared__ char fsm_raw[];
    uint32_t sb  = smem_u32(fsm_raw);
    uint32_t sQh = sb;
    uint32_t sQl = sb + FQ;
    uint32_t sKh = sb + 2 * FQ;
    uint32_t sKl = sKh + 2 * FTILE;
    uint32_t sVh = sKl + 2 * FTILE;

    int qb  = 15 - blockIdx.x;
    int h   = blockIdx.y;
    int tid = threadIdx.x, wid = tid >> 5, lane = tid & 31;
    int q0  = qb * 128;
    int lastkt = 2 * qb + 1;

    const __half* qhp = g_qh + ((size_t)h * S_LEN + q0) * HDIM;
    const __half* qlp = g_ql + ((size_t)h * S_LEN + q0) * HDIM;
    const __half* khp = g_kh + (size_t)h * S_LEN * HDIM;
    const __half* klp = g_kl + (size_t)h * S_LEN * HDIM;
    const __half* vhp = g_vh + (size_t)h * S_LEN * HDIM;

    auto load_tile = [&](int kt, int bb) {
        uint32_t dKh = sKh + (uint32_t)bb * FTILE;
        uint32_t dKl = sKl + (uint32_t)bb * FTILE;
        uint32_t dVh = sVh + (uint32_t)bb * FTILE;
        const __half* s1 = khp + (size_t)kt * 64 * HDIM;
        const __half* s2 = klp + (size_t)kt * 64 * HDIM;
        const __half* s3 = vhp + (size_t)kt * 64 * HDIM;
#pragma unroll
        for (int i = 0; i < 4; i++) {
            int u = tid + i * 256;
            int r = u >> 4, cb = (u & 15) * 16, ce = (u & 15) * 8;
            CP_ASYNC16(dKh + r * FT + cb, s1 + r * HDIM + ce);
            CP_ASYNC16(dKl + r * FT + cb, s2 + r * HDIM + ce);
            CP_ASYNC16(dVh + r * FT + cb, s3 + r * HDIM + ce);
        }
    };

#pragma unroll
    for (int i = 0; i < 8; i++) {
        int u = tid + i * 256;
        int r = u >> 4, cb = (u & 15) * 16, ce = (u & 15) * 8;
        CP_ASYNC16(sQh + r * FT + cb, qhp + r * HDIM + ce);
        CP_ASYNC16(sQl + r * FT + cb, qlp + r * HDIM + ce);
    }
    load_tile(0, 0);
    CP_COMMIT();

    float oacc[16][4];
#pragma unroll
    for (int i = 0; i < 16; i++)
#pragma unroll
        for (int j = 0; j < 4; j++) oacc[i][j] = 0.0f;
    float m0 = -INFINITY, m1 = -INFINITY, l0 = 0.0f, l1 = 0.0f;

    uint32_t aLq = (uint32_t)((wid * 16 + (lane & 15)) * FT + (lane >> 4) * 16);
    uint32_t bLk = (uint32_t)(((lane >> 4) * 8 + (lane & 7)) * FT
                              + ((lane >> 3) & 1) * 16);
    uint32_t vLb = (uint32_t)((lane & 15) * FT + (lane >> 4) * 16);
    int r0 = lane >> 2;

#pragma unroll 1
    for (int kt = 0; kt <= lastkt; kt++) {
        int b = kt & 1;
        CP_WAIT0();
        __syncthreads();
        if (kt < lastkt) { load_tile(kt + 1, b ^ 1); CP_COMMIT(); }

        uint32_t Kh = sKh + (uint32_t)b * FTILE;
        uint32_t Kl = sKl + (uint32_t)b * FTILE;
        uint32_t Vh = sVh + (uint32_t)b * FTILE;

        float sacc[8][4];
#pragma unroll
        for (int i = 0; i < 8; i++)
#pragma unroll
            for (int j = 0; j < 4; j++) sacc[i][j] = 0.0f;
#pragma unroll
        for (int ks = 0; ks < 8; ks++) {
            uint32_t ah[4], al[4];
            LDSM4(ah[0], ah[1], ah[2], ah[3], sQh + aLq + ks * 32);
            LDSM4(al[0], al[1], al[2], al[3], sQl + aLq + ks * 32);
#pragma unroll
            for (int t = 0; t < 4; t++) {
                uint32_t x[4], y[4];
                LDSM4(x[0], x[1], x[2], x[3], Kh + bLk + t * 16 * FT + ks * 32);
                mma16816(sacc[2 * t],     ah, &x[0]);
                mma16816(sacc[2 * t + 1], ah, &x[2]);
                mma16816(sacc[2 * t],     al, &x[0]);
                mma16816(sacc[2 * t + 1], al, &x[2]);
                LDSM4(y[0], y[1], y[2], y[3], Kl + bLk + t * 16 * FT + ks * 32);
                mma16816(sacc[2 * t],     ah, &y[0]);
                mma16816(sacc[2 * t + 1], ah, &y[2]);
            }
        }

        if (kt >= 2 * qb) {
            int gr0 = q0 + wid * 16 + r0;
            int gr1 = gr0 + 8;
            int gcb = kt * 64 + (lane & 3) * 2;
#pragma unroll
            for (int nt = 0; nt < 8; nt++) {
                int gc = gcb + nt * 8;
                if (gc     > gr0) sacc[nt][0] = -INFINITY;
                if (gc + 1 > gr0) sacc[nt][1] = -INFINITY;
                if (gc     > gr1) sacc[nt][2] = -INFINITY;
                if (gc + 1 > gr1) sacc[nt][3] = -INFINITY;
            }
        }

        float tm0 = -INFINITY, tm1 = -INFINITY;
#pragma unroll
        for (int nt = 0; nt < 8; nt++) {
            tm0 = fmaxf(tm0, fmaxf(sacc[nt][0], sacc[nt][1]));
            tm1 = fmaxf(tm1, fmaxf(sacc[nt][2], sacc[nt][3]));
        }
        tm0 = fmaxf(tm0, __shfl_xor_sync(0xffffffffu, tm0, 1));
        tm0 = fmaxf(tm0, __shfl_xor_sync(0xffffffffu, tm0, 2));
        tm1 = fmaxf(tm1, __shfl_xor_sync(0xffffffffu, tm1, 1));
        tm1 = fmaxf(tm1, __shfl_xor_sync(0xffffffffu, tm1, 2));

        float mn0 = fmaxf(m0, tm0), mn1 = fmaxf(m1, tm1);
        float al0 = __expf(m0 - mn0), al1 = __expf(m1 - mn1);
        m0 = mn0; m1 = mn1;

        float s0 = 0.0f, s1 = 0.0f;
#pragma unroll
        for (int nt = 0; nt < 8; nt++) {
            sacc[nt][0] = __expf(sacc[nt][0] - mn0);
            sacc[nt][1] = __expf(sacc[nt][1] - mn0);
            sacc[nt][2] = __expf(sacc[nt][2] - mn1);
            sacc[nt][3] = __expf(sacc[nt][3] - mn1);
            s0 += sacc[nt][0] + sacc[nt][1];
            s1 += sacc[nt][2] + sacc[nt][3];
        }
        s0 += __shfl_xor_sync(0xffffffffu, s0, 1);
        s0 += __shfl_xor_sync(0xffffffffu, s0, 2);
        s1 += __shfl_xor_sync(0xffffffffu, s1, 1);
        s1 += __shfl_xor_sync(0xffffffffu, s1, 2);
        l0 = l0 * al0 + s0;
        l1 = l1 * al1 + s1;

#pragma unroll
        for (int dt = 0; dt < 16; dt++) {
            oacc[dt][0] *= al0; oacc[dt][1] *= al0;
            oacc[dt][2] *= al1; oacc[dt][3] *= al1;
        }

        uint32_t aPh[4][4], aPl[4][4];
#pragma unroll
        for (int ks = 0; ks < 4; ks++) {
            float p00 = sacc[2 * ks][0],     p01 = sacc[2 * ks][1];
            float p02 = sacc[2 * ks][2],     p03 = sacc[2 * ks][3];
            float p10 = sacc[2 * ks + 1][0], p11 = sacc[2 * ks + 1][1];
            float p12 = sacc[2 * ks + 1][2], p13 = sacc[2 * ks + 1][3];
            aPh[ks][0] = packh2(p00, p01);
            aPh[ks][1] = packh2(p02, p03);
            aPh[ks][2] = packh2(p10, p11);
            aPh[ks][3] = packh2(p12, p13);
            __half2 t0 = *(__half2*)&aPh[ks][0];
            __half2 t1 = *(__half2*)&aPh[ks][1];
            __half2 t2 = *(__half2*)&aPh[ks][2];
            __half2 t3 = *(__half2*)&aPh[ks][3];
            aPl[ks][0] = packh2(p00 - __half2float(__low2half(t0)),
                                p01 - __half2float(__high2half(t0)));
            aPl[ks][1] = packh2(p02 - __half2float(__low2half(t1)),
                                p03 - __half2float(__high2half(t1)));
            aPl[ks][2] = packh2(p10 - __half2float(__low2half(t2)),
                                p11 - __half2float(__high2half(t2)));
            aPl[ks][3] = packh2(p12 - __half2float(__low2half(t3)),
                                p13 - __half2float(__high2half(t3)));
        }

#pragma unroll
        for (int ks = 0; ks < 4; ks++) {
#pragma unroll
            for (int dp = 0; dp < 8; dp++) {
                uint32_t bh[4];
                LDSM4T(bh[0], bh[1], bh[2], bh[3],
                       Vh + vLb + (uint32_t)(ks * 16) * FT + dp * 32);
                mma16816(oacc[2 * dp],     aPh[ks], &bh[0]);
                mma16816(oacc[2 * dp + 1], aPh[ks], &bh[2]);
                mma16816(oacc[2 * dp],     aPl[ks], &bh[0]);
                mma16816(oacc[2 * dp + 1], aPl[ks], &bh[2]);
            }
        }
    }

    float inv0 = 1.0f / l0, inv1 = 1.0f / l1;
    int grow = q0 + wid * 16 + r0;
#pragma unroll
    for (int dt = 0; dt < 16; dt++) {
        int col = h * HDIM + dt * 8 + (lane & 3) * 2;
        float v0 = oacc[dt][0] * inv0, v1 = oacc[dt][1] * inv0;
        float v2 = oacc[dt][2] * inv1, v3 = oacc[dt][3] * inv1;

        __half h0 = __float2half(v0), h1 = __float2half(v1);
        __half h2 = __float2half(v2), h3 = __float2half(v3);
        __half2 hi01 = __halves2half2(h0, h1);
        __half2 hi23 = __halves2half2(h2, h3);
        uint32_t lo01 = packh2(v0 - __half2float(h0), v1 - __half2float(h1));
        uint32_t lo23 = packh2(v2 - __half2float(h2), v3 - __half2float(h3));

        uint32_t* pA = (uint32_t*)(xp2 + (size_t)grow * (2 * HID) + col);
        pA[0]       = *(uint32_t*)&hi01;
        pA[HID / 2] = lo01;
        uint32_t* pB = (uint32_t*)(xp2 + (size_t)(grow + 8) * (2 * HID) + col);
        pB[0]       = *(uint32_t*)&hi23;
        pB[HID / 2] = lo23;
    }
}

// ============================================================================
// KV eviction
// ============================================================================
__global__ void evict_kernel(float* __restrict__ outk, float* __restrict__ outv)
{
    int idx = blockIdx.x * blockDim.x + threadIdx.x;
    if (idx >= NHEAD * EVLEN * HDIM) return;
    int d = idx & 127;
    int t = (idx >> 7) % EVLEN;
    int h = idx / (EVLEN * HDIM);
    int src = (t < SINKN) ? t : (S_LEN - RECENT) + (t - SINKN);
    size_t si = ((size_t)h * S_LEN + src) * HDIM + d;
    outk[idx] = g_k[si];
    outv[idx] = g_v[si];
}

// ============================================================================
extern "C" void kernel_launch(void* const* d_in, const int* in_sizes, int n_in,
                              void* d_out, int out_size)
{
    const float* X  = (const float*)d_in[0];
    const float* Wq = (const float*)d_in[1];
    const float* Wk = (const float*)d_in[2];
    const float* Wv = (const float*)d_in[3];
    const float* Wo = (const float*)d_in[4];
    float* out = (float*)d_out;

    float *qb, *kb, *vb;
    __half *xp3, *xp2, *wqk, *wv, *wo;
    cudaGetSymbolAddress((void**)&qb,  g_q);
    cudaGetSymbolAddress((void**)&kb,  g_k);
    cudaGetSymbolAddress((void**)&vb,  g_v);
    cudaGetSymbolAddress((void**)&xp3, g_xp3);
    cudaGetSymbolAddress((void**)&xp2, g_xp2);
    cudaGetSymbolAddress((void**)&wqk, g_wqk);
    cudaGetSymbolAddress((void**)&wv,  g_wv);
    cudaGetSymbolAddress((void**)&wo,  g_wo);

    cudaFuncSetAttribute(mma_gemm_qkv_kernel,
                         cudaFuncAttributeMaxDynamicSharedMemorySize, GEMM_SMEM);
    cudaFuncSetAttribute(mma_gemm_wo_kernel,
                         cudaFuncAttributeMaxDynamicSharedMemorySize, GEMM_SMEM);
    cudaFuncSetAttribute(flash_mma_kernel,
                         cudaFuncAttributeMaxDynamicSharedMemorySize, FA_SMEM);

    const int XO = S_LEN * 512;    // octs in X
    const int WO = HID * 512;      // octs in a weight
    const size_t WSEG3 = (size_t)HID * KP3;

    rope_table_kernel<<<(S_LEN * 64 + 255) / 256, 256>>>();

    convert_split3h_kernel<<<(XO + 255) / 256, 256>>>(X, xp3, XO, 1);
    convert_split3h_kernel<<<(WO + 255) / 256, 256>>>(Wq, wqk,         WO, 0);
    convert_split3h_kernel<<<(WO + 255) / 256, 256>>>(Wk, wqk + WSEG3, WO, 0);
    convert_roundh_kernel<<<(WO + 255) / 256, 256>>>(Wv, wv, WO);
    convert_roundh_kernel<<<(WO + 255) / 256, 256>>>(Wo, wo, WO);

    // merged Q,K,V projections — QK tiles first, V tiles backfill the tail
    mma_gemm_qkv_kernel<<<1536, 256, GEMM_SMEM>>>(xp3, wqk, wv, qb, kb, vb);

    rope_split_kernel<<<(NHEAD * S_LEN * 64) / 256, 256>>>();

    flash_mma_kernel<<<dim3(16, 32), 256, FA_SMEM>>>(xp2);

    // output projection (fp16 2-term)
    dim3 go(S_LEN / 128, HID / 128);           // (16, 32)
    mma_gemm_wo_kernel<<<go, 256, GEMM_SMEM>>>(xp2, wo, out);

    size_t attn_elems = (size_t)S_LEN * HID;
    size_t ev_elems   = (size_t)NHEAD * EVLEN * HDIM;
    evict_kernel<<<(int)((ev_elems + 255) / 256), 256>>>(out + attn_elems,
                                                         out + attn_elems + ev_elems);
}

// round 10
// speedup vs baseline: 4.3469x; 1.0683x over previous
#include <cuda_runtime.h>
#include <cuda_fp16.h>
#include <math.h>
#include <stdint.h>

#define S_LEN  2048
#define HID    4096
#define NHEAD  32
#define HDIM   128
#define RECENT 204
#define SINKN  4
#define EVLEN  (SINKN + RECENT)   // 208

#define STG    16384         // bytes per operand per stage (128 rows x 128 B)
#define GEMM_SMEM (3 * 2 * STG)   // 98304

// flash smem: 272 B per row (128 fp16 + pad)
#define FT     272
#define FTILE  (64 * FT)                // 17408
#define FQ     (128 * FT)               // 34816
#define FA_SMEM (2 * FQ + 4 * FTILE)    // 139264

// -------- static scratch --------
static __device__ float g_q[NHEAD * S_LEN * HDIM];
static __device__ float g_k[NHEAD * S_LEN * HDIM];
static __device__ float g_v[NHEAD * S_LEN * HDIM];
static __device__ __half g_xpA[(size_t)S_LEN * 2 * HID];   // X  [hi|lo]
static __device__ __half g_xp2[(size_t)S_LEN * 2 * HID];   // O  [hi|lo]
static __device__ __half g_wqk[2ULL * HID * 2 * HID];      // Wq|Wk, each [hi|lo]
static __device__ __half g_wv[(size_t)HID * HID];          // Wv hi
static __device__ __half g_wo[(size_t)HID * HID];          // Wo hi
static __device__ __half g_qh[NHEAD * S_LEN * HDIM];
static __device__ __half g_ql[NHEAD * S_LEN * HDIM];
static __device__ __half g_kh[NHEAD * S_LEN * HDIM];
static __device__ __half g_vh[NHEAD * S_LEN * HDIM];
static __device__ float g_cosT[S_LEN * 64];
static __device__ float g_sinT[S_LEN * 64];

// ============================ helpers =======================================
__device__ __forceinline__ uint32_t smem_u32(const void* p) {
    uint32_t a;
    asm("{ .reg .u64 t; cvta.to.shared.u64 t, %1; cvt.u32.u64 %0, t; }"
        : "=r"(a) : "l"(p));
    return a;
}
#define CP_ASYNC16(dst, src) \
    asm volatile("cp.async.cg.shared.global [%0], [%1], 16;" \
                 :: "r"(dst), "l"(src) : "memory")
#define CP_COMMIT() asm volatile("cp.async.commit_group;" ::: "memory")
#define CP_WAIT1()  asm volatile("cp.async.wait_group 1;" ::: "memory")
#define CP_WAIT0()  asm volatile("cp.async.wait_group 0;" ::: "memory")
#define LDSM4(r0, r1, r2, r3, addr) \
    asm volatile("ldmatrix.sync.aligned.m8n8.x4.shared.b16 {%0,%1,%2,%3}, [%4];" \
                 : "=r"(r0), "=r"(r1), "=r"(r2), "=r"(r3) : "r"(addr))
#define LDSM4T(r0, r1, r2, r3, addr) \
    asm volatile("ldmatrix.sync.aligned.m8n8.x4.trans.shared.b16 {%0,%1,%2,%3}, [%4];" \
                 : "=r"(r0), "=r"(r1), "=r"(r2), "=r"(r3) : "r"(addr))

__device__ __forceinline__ void mma16816(float* c, const uint32_t* a,
                                         const uint32_t* b) {
    asm volatile(
        "mma.sync.aligned.m16n8k16.row.col.f32.f16.f16.f32 "
        "{%0,%1,%2,%3}, {%4,%5,%6,%7}, {%8,%9}, {%0,%1,%2,%3};"
        : "+f"(c[0]), "+f"(c[1]), "+f"(c[2]), "+f"(c[3])
        : "r"(a[0]), "r"(a[1]), "r"(a[2]), "r"(a[3]), "r"(b[0]), "r"(b[1]));
}
__device__ __forceinline__ uint32_t packh2(float x, float y) {
    __half2 t = __halves2half2(__float2half(x), __float2half(y));
    return *(uint32_t*)&t;
}

// ============================================================================
// 2-segment fp16 split [hi|lo], 8 elements/thread, 16B stores.
// src [rows][4096] f32 -> dst [rows][8192] fp16
// ============================================================================
__global__ void convert_split2h_kernel(const float* __restrict__ src,
                                       __half* __restrict__ dst, int nocts)
{
    int idx = blockIdx.x * blockDim.x + threadIdx.x;
    if (idx >= nocts) return;
    int r  = idx >> 9;
    int c8 = (idx & 511) * 8;
    const float* s = src + (size_t)r * HID + c8;
    float4 x0 = *(const float4*)(s);
    float4 x1 = *(const float4*)(s + 4);

    float xs[8] = {x0.x, x0.y, x0.z, x0.w, x1.x, x1.y, x1.z, x1.w};
    __half hv[8], lv[8];
#pragma unroll
    for (int i = 0; i < 8; i++) {
        hv[i] = __float2half(xs[i]);
        lv[i] = __float2half(xs[i] - __half2float(hv[i]));
    }
    uint4 hi4, lo4;
    ((__half2*)&hi4)[0] = __halves2half2(hv[0], hv[1]);
    ((__half2*)&hi4)[1] = __halves2half2(hv[2], hv[3]);
    ((__half2*)&hi4)[2] = __halves2half2(hv[4], hv[5]);
    ((__half2*)&hi4)[3] = __halves2half2(hv[6], hv[7]);
    ((__half2*)&lo4)[0] = __halves2half2(lv[0], lv[1]);
    ((__half2*)&lo4)[1] = __halves2half2(lv[2], lv[3]);
    ((__half2*)&lo4)[2] = __halves2half2(lv[4], lv[5]);
    ((__half2*)&lo4)[3] = __halves2half2(lv[6], lv[7]);

    size_t base = (size_t)r * (2 * HID) + c8;
    *(uint4*)(dst + base)       = hi4;
    *(uint4*)(dst + base + HID) = lo4;
}

// Single-segment fp16 rounding (Wv / Wo), 8 elements/thread
__global__ void convert_roundh_kernel(const float* __restrict__ src,
                                      __half* __restrict__ dst, int nocts)
{
    int idx = blockIdx.x * blockDim.x + threadIdx.x;
    if (idx >= nocts) return;
    const float* s = src + (size_t)idx * 8;
    float4 x0 = *(const float4*)(s);
    float4 x1 = *(const float4*)(s + 4);
    uint4 o;
    ((__half2*)&o)[0] = __halves2half2(__float2half(x0.x), __float2half(x0.y));
    ((__half2*)&o)[1] = __halves2half2(__float2half(x0.z), __float2half(x0.w));
    ((__half2*)&o)[2] = __halves2half2(__float2half(x1.x), __float2half(x1.y));
    ((__half2*)&o)[3] = __halves2half2(__float2half(x1.z), __float2half(x1.w));
    *(uint4*)(dst + (size_t)idx * 8) = o;
}

// ============================================================================
// Merged QKV GEMM: one launch, 1536 CTAs. A and B both stored [hi|lo];
// split-term sequence realized by per-stage offset mapping:
//  QK (bid<1024, NK=192): terms Xh·Wh (kt<64), Xh·Wl (64..127), Xl·Wh (128..191)
//    akoff = (kt&63)*128 + (kt>=128 ? 8192 : 0)
//    bkoff = (kt&63)*128 + (64<=kt<128 ? 8192 : 0)
//  V  (bid>=1024, NK=128): Xh·Wv (kt<64) + Xl·Wv (64..127)
//    akoff = kt*128 ; bkoff = (kt&63)*128
// ============================================================================
__global__ __launch_bounds__(256, 2)
void mma_gemm_qkv_kernel(const __half* __restrict__ Ap,
                         const __half* __restrict__ Bqk,
                         const __half* __restrict__ Bv,
                         float* __restrict__ Cq, float* __restrict__ Ck,
                         float* __restrict__ Cv)
{
    extern __shared__ __align__(1024) char smem[];
    uint32_t sb = smem_u32(smem);

    int bid = blockIdx.x;
    bool isQK = bid < 1024;
    int t = isQK ? bid : bid - 1024;
    int m0 = (t & 15) * 128;
    int n0 = (t >> 4) * 128;
    int NK = isQK ? 192 : 128;
    int BROWB = isQK ? 16384 : 8192;

    int tid  = threadIdx.x;
    int wid  = tid >> 5, lane = tid & 31;
    int wm   = wid >> 1;
    int wn   = wid & 1;

    const char* Ag = (const char*)Ap + (size_t)m0 * 16384;
    const char* Bg = isQK ? (const char*)Bqk + (size_t)n0 * 16384
                          : (const char*)Bv  + (size_t)n0 * 8192;

    auto issue_stage = [&](int kt) {
        int buf = kt % 3;
        uint32_t sA = sb + (uint32_t)buf * (2 * STG);
        uint32_t sB = sA + STG;
        size_t akoff, bkoff;
        if (isQK) {
            akoff = (size_t)(kt & 63) * 128 + ((kt >= 128) ? 8192 : 0);
            bkoff = (size_t)(kt & 63) * 128 + ((kt >= 64 && kt < 128) ? 8192 : 0);
        } else {
            akoff = (size_t)kt * 128;
            bkoff = (size_t)(kt & 63) * 128;
        }
#pragma unroll
        for (int i = 0; i < 4; i++) {
            int u = tid + i * 256;
            int r = u >> 3, c = (u & 7) * 16;
            uint32_t sw = (uint32_t)(r * 128 + (c ^ ((r & 7) << 4)));
            CP_ASYNC16(sA + sw, Ag + (size_t)r * 16384 + akoff + c);
            CP_ASYNC16(sB + sw, Bg + (size_t)r * BROWB + bkoff + c);
        }
    };

    float acc[2][8][4];
#pragma unroll
    for (int i = 0; i < 2; i++)
#pragma unroll
        for (int j = 0; j < 8; j++)
#pragma unroll
            for (int q = 0; q < 4; q++) acc[i][j][q] = 0.0f;

    issue_stage(0); CP_COMMIT();
    issue_stage(1); CP_COMMIT();

    int arow = wm * 32 + (lane & 15);
    uint32_t aL = (uint32_t)(arow * 128 + (((lane >> 4) * 16) ^ ((arow & 7) << 4)));
    int brow = wn * 64 + (lane >> 4) * 8 + (lane & 7);
    uint32_t bL = (uint32_t)(brow * 128 + ((((lane >> 3) & 1) * 16) ^ ((brow & 7) << 4)));

#pragma unroll 1
    for (int kt = 0; kt < NK; kt++) {
        CP_WAIT1();
        __syncthreads();
        if (kt + 2 < NK) { issue_stage(kt + 2); CP_COMMIT(); }

        uint32_t sA = sb + (uint32_t)(kt % 3) * (2 * STG);
        uint32_t sB = sA + STG;

#pragma unroll
        for (int ks = 0; ks < 4; ks++) {
            uint32_t kx = (uint32_t)(ks << 5);
            uint32_t a[2][4], b[8][2];
            LDSM4(a[0][0], a[0][1], a[0][2], a[0][3], (sA + aL) ^ kx);
            LDSM4(a[1][0], a[1][1], a[1][2], a[1][3], (sA + aL + 2048) ^ kx);
#pragma unroll
            for (int tt = 0; tt < 4; tt++)
                LDSM4(b[2 * tt][0], b[2 * tt][1], b[2 * tt + 1][0], b[2 * tt + 1][1],
                      (sB + bL + (uint32_t)(tt * 2048)) ^ kx);
#pragma unroll
            for (int mt = 0; mt < 2; mt++)
#pragma unroll
                for (int nt = 0; nt < 8; nt++)
                    mma16816(acc[mt][nt], a[mt], b[nt]);
        }
    }
    CP_WAIT0();

    float* base;
    int hh;
    if (isQK) {
        base = (n0 >= 4096) ? Ck : Cq;
        hh = (n0 & 4095) >> 7;
    } else {
        base = Cv;
        hh = n0 >> 7;
    }

#pragma unroll
    for (int mt = 0; mt < 2; mt++) {
        int row = m0 + wm * 32 + mt * 16 + (lane >> 2);
#pragma unroll
        for (int nt = 0; nt < 8; nt++) {
            int col = wn * 64 + nt * 8 + (lane & 3) * 2;
            float2 v01 = make_float2(acc[mt][nt][0], acc[mt][nt][1]);
            float2 v23 = make_float2(acc[mt][nt][2], acc[mt][nt][3]);
            *(float2*)(base + ((size_t)hh * S_LEN + row) * HDIM + col)     = v01;
            *(float2*)(base + ((size_t)hh * S_LEN + row + 8) * HDIM + col) = v23;
        }
    }
}

// ============================================================================
// Wo GEMM (2-term fp16, NK=128), row-major out.
// ============================================================================
__global__ __launch_bounds__(256, 2)
void mma_gemm_wo_kernel(const __half* __restrict__ Ap,
                        const __half* __restrict__ Bp,
                        float* __restrict__ C)
{
    extern __shared__ __align__(1024) char smem[];
    uint32_t sb = smem_u32(smem);

    int tid  = threadIdx.x;
    int wid  = tid >> 5, lane = tid & 31;
    int wm   = wid >> 1;
    int wn   = wid & 1;
    int m0   = blockIdx.x * 128;
    int n0   = blockIdx.y * 128;

    const char* Ag = (const char*)Ap + (size_t)m0 * 16384;
    const char* Bg = (const char*)Bp + (size_t)n0 * 8192;

    auto issue_stage = [&](int kt) {
        int buf = kt % 3;
        uint32_t sA = sb + (uint32_t)buf * (2 * STG);
        uint32_t sB = sA + STG;
        size_t akoff = (size_t)kt * 128;
        size_t bkoff = (size_t)(kt & 63) * 128;
#pragma unroll
        for (int i = 0; i < 4; i++) {
            int u = tid + i * 256;
            int r = u >> 3, c = (u & 7) * 16;
            uint32_t sw = (uint32_t)(r * 128 + (c ^ ((r & 7) << 4)));
            CP_ASYNC16(sA + sw, Ag + (size_t)r * 16384 + akoff + c);
            CP_ASYNC16(sB + sw, Bg + (size_t)r * 8192 + bkoff + c);
        }
    };

    float acc[2][8][4];
#pragma unroll
    for (int i = 0; i < 2; i++)
#pragma unroll
        for (int j = 0; j < 8; j++)
#pragma unroll
            for (int q = 0; q < 4; q++) acc[i][j][q] = 0.0f;

    issue_stage(0); CP_COMMIT();
    issue_stage(1); CP_COMMIT();

    int arow = wm * 32 + (lane & 15);
    uint32_t aL = (uint32_t)(arow * 128 + (((lane >> 4) * 16) ^ ((arow & 7) << 4)));
    int brow = wn * 64 + (lane >> 4) * 8 + (lane & 7);
    uint32_t bL = (uint32_t)(brow * 128 + ((((lane >> 3) & 1) * 16) ^ ((brow & 7) << 4)));

#pragma unroll 1
    for (int kt = 0; kt < 128; kt++) {
        CP_WAIT1();
        __syncthreads();
        if (kt + 2 < 128) { issue_stage(kt + 2); CP_COMMIT(); }

        uint32_t sA = sb + (uint32_t)(kt % 3) * (2 * STG);
        uint32_t sB = sA + STG;

#pragma unroll
        for (int ks = 0; ks < 4; ks++) {
            uint32_t kx = (uint32_t)(ks << 5);
            uint32_t a[2][4], b[8][2];
            LDSM4(a[0][0], a[0][1], a[0][2], a[0][3], (sA + aL) ^ kx);
            LDSM4(a[1][0], a[1][1], a[1][2], a[1][3], (sA + aL + 2048) ^ kx);
#pragma unroll
            for (int tt = 0; tt < 4; tt++)
                LDSM4(b[2 * tt][0], b[2 * tt][1], b[2 * tt + 1][0], b[2 * tt + 1][1],
                      (sB + bL + (uint32_t)(tt * 2048)) ^ kx);
#pragma unroll
            for (int mt = 0; mt < 2; mt++)
#pragma unroll
                for (int nt = 0; nt < 8; nt++)
                    mma16816(acc[mt][nt], a[mt], b[nt]);
        }
    }
    CP_WAIT0();

#pragma unroll
    for (int mt = 0; mt < 2; mt++) {
        int row = m0 + wm * 32 + mt * 16 + (lane >> 2);
#pragma unroll
        for (int nt = 0; nt < 8; nt++) {
            int col = n0 + wn * 64 + nt * 8 + (lane & 3) * 2;
            *(float2*)(C + (size_t)row * HID + col) =
                make_float2(acc[mt][nt][0], acc[mt][nt][1]);
            *(float2*)(C + (size_t)(row + 8) * HID + col) =
                make_float2(acc[mt][nt][2], acc[mt][nt][3]);
        }
    }
}

// ============================================================================
// RoPE table (fp64 angles)
// ============================================================================
__global__ void rope_table_kernel()
{
    int idx = blockIdx.x * blockDim.x + threadIdx.x;
    if (idx >= S_LEN * 64) return;
    int d = idx & 63;
    int s = idx >> 6;
    double inv = pow(10000.0, -(double)(2 * d) / 128.0);
    double sd, cd;
    sincos((double)s * inv, &sd, &cd);
    g_cosT[idx] = (float)cd;
    g_sinT[idx] = (float)sd;
}

// ============================================================================
// Fused rope + fp16 split: q scaled+split (hi/lo), k rounded (hi only),
// v rounded. Post-rope k written back fp32 for eviction.
// ============================================================================
__global__ void rope_split_kernel()
{
    int idx = blockIdx.x * blockDim.x + threadIdx.x;
    if (idx >= NHEAD * S_LEN * 64) return;
    int t = idx & (S_LEN * 64 - 1);
    int d = idx & 63;
    int s = (idx >> 6) & (S_LEN - 1);
    int h = idx >> 17;
    float c = g_cosT[t], sn = g_sinT[t];
    const float scale = 0.08838834764831845f;

    size_t base = ((size_t)h * S_LEN + s) * HDIM;
    float q1 = g_q[base + d], q2 = g_q[base + d + 64];
    float k1 = g_k[base + d], k2 = g_k[base + d + 64];
    float v1 = g_v[base + d], v2 = g_v[base + d + 64];

    float qr1 = (q1 * c - q2 * sn) * scale;
    float qr2 = (q2 * c + q1 * sn) * scale;
    float kr1 = k1 * c - k2 * sn;
    float kr2 = k2 * c + k1 * sn;

    g_k[base + d]      = kr1;
    g_k[base + d + 64] = kr2;

    __half qh1 = __float2half(qr1), qh2 = __float2half(qr2);
    g_qh[base + d]      = qh1;
    g_qh[base + d + 64] = qh2;
    g_ql[base + d]      = __float2half(qr1 - __half2float(qh1));
    g_ql[base + d + 64] = __float2half(qr2 - __half2float(qh2));
    g_kh[base + d]      = __float2half(kr1);
    g_kh[base + d + 64] = __float2half(kr2);
    g_vh[base + d]      = __float2half(v1);
    g_vh[base + d + 64] = __float2half(v2);
}

// ============================================================================
// Flash attention fp16: QK 2-term ((Qh+Ql)·Kh), PV 2-term ((Ph+Pl)·Vh).
// Br=128, 8 warps along M, register P, warp-local softmax.
// Epilogue writes Wo activations [hi|lo] fp16 into g_xp2.
// ============================================================================
__global__ __launch_bounds__(256, 1)
void flash_mma_kernel(__half* __restrict__ xp2)
{
    extern __shared__ char fsm_raw[];
    uint32_t sb  = smem_u32(fsm_raw);
    uint32_t sQh = sb;
    uint32_t sQl = sb + FQ;
    uint32_t sKh = sb + 2 * FQ;          // + b*FTILE
    uint32_t sVh = sKh + 2 * FTILE;

    int qb  = 15 - blockIdx.x;
    int h   = blockIdx.y;
    int tid = threadIdx.x, wid = tid >> 5, lane = tid & 31;
    int q0  = qb * 128;
    int lastkt = 2 * qb + 1;

    const __half* qhp = g_qh + ((size_t)h * S_LEN + q0) * HDIM;
    const __half* qlp = g_ql + ((size_t)h * S_LEN + q0) * HDIM;
    const __half* khp = g_kh + (size_t)h * S_LEN * HDIM;
    const __half* vhp = g_vh + (size_t)h * S_LEN * HDIM;

    auto load_tile = [&](int kt, int bb) {
        uint32_t dKh = sKh + (uint32_t)bb * FTILE;
        uint32_t dVh = sVh + (uint32_t)bb * FTILE;
        const __half* s1 = khp + (size_t)kt * 64 * HDIM;
        const __half* s3 = vhp + (size_t)kt * 64 * HDIM;
#pragma unroll
        for (int i = 0; i < 4; i++) {
            int u = tid + i * 256;
            int r = u >> 4, cb = (u & 15) * 16, ce = (u & 15) * 8;
            CP_ASYNC16(dKh + r * FT + cb, s1 + r * HDIM + ce);
            CP_ASYNC16(dVh + r * FT + cb, s3 + r * HDIM + ce);
        }
    };

#pragma unroll
    for (int i = 0; i < 8; i++) {
        int u = tid + i * 256;
        int r = u >> 4, cb = (u & 15) * 16, ce = (u & 15) * 8;
        CP_ASYNC16(sQh + r * FT + cb, qhp + r * HDIM + ce);
        CP_ASYNC16(sQl + r * FT + cb, qlp + r * HDIM + ce);
    }
    load_tile(0, 0);
    CP_COMMIT();

    float oacc[16][4];
#pragma unroll
    for (int i = 0; i < 16; i++)
#pragma unroll
        for (int j = 0; j < 4; j++) oacc[i][j] = 0.0f;
    float m0 = -INFINITY, m1 = -INFINITY, l0 = 0.0f, l1 = 0.0f;

    uint32_t aLq = (uint32_t)((wid * 16 + (lane & 15)) * FT + (lane >> 4) * 16);
    uint32_t bLk = (uint32_t)(((lane >> 4) * 8 + (lane & 7)) * FT
                              + ((lane >> 3) & 1) * 16);
    uint32_t vLb = (uint32_t)((lane & 15) * FT + (lane >> 4) * 16);
    int r0 = lane >> 2;

#pragma unroll 1
    for (int kt = 0; kt <= lastkt; kt++) {
        int b = kt & 1;
        CP_WAIT0();
        __syncthreads();
        if (kt < lastkt) { load_tile(kt + 1, b ^ 1); CP_COMMIT(); }

        uint32_t Kh = sKh + (uint32_t)b * FTILE;
        uint32_t Vh = sVh + (uint32_t)b * FTILE;

        // ---- scores: (Qh + Ql)·Kh ----
        float sacc[8][4];
#pragma unroll
        for (int i = 0; i < 8; i++)
#pragma unroll
            for (int j = 0; j < 4; j++) sacc[i][j] = 0.0f;
#pragma unroll
        for (int ks = 0; ks < 8; ks++) {
            uint32_t ah[4], al[4];
            LDSM4(ah[0], ah[1], ah[2], ah[3], sQh + aLq + ks * 32);
            LDSM4(al[0], al[1], al[2], al[3], sQl + aLq + ks * 32);
#pragma unroll
            for (int t = 0; t < 4; t++) {
                uint32_t x[4];
                LDSM4(x[0], x[1], x[2], x[3], Kh + bLk + t * 16 * FT + ks * 32);
                mma16816(sacc[2 * t],     ah, &x[0]);
                mma16816(sacc[2 * t + 1], ah, &x[2]);
                mma16816(sacc[2 * t],     al, &x[0]);
                mma16816(sacc[2 * t + 1], al, &x[2]);
            }
        }

        if (kt >= 2 * qb) {
            int gr0 = q0 + wid * 16 + r0;
            int gr1 = gr0 + 8;
            int gcb = kt * 64 + (lane & 3) * 2;
#pragma unroll
            for (int nt = 0; nt < 8; nt++) {
                int gc = gcb + nt * 8;
                if (gc     > gr0) sacc[nt][0] = -INFINITY;
                if (gc + 1 > gr0) sacc[nt][1] = -INFINITY;
                if (gc     > gr1) sacc[nt][2] = -INFINITY;
                if (gc + 1 > gr1) sacc[nt][3] = -INFINITY;
            }
        }

        float tm0 = -INFINITY, tm1 = -INFINITY;
#pragma unroll
        for (int nt = 0; nt < 8; nt++) {
            tm0 = fmaxf(tm0, fmaxf(sacc[nt][0], sacc[nt][1]));
            tm1 = fmaxf(tm1, fmaxf(sacc[nt][2], sacc[nt][3]));
        }
        tm0 = fmaxf(tm0, __shfl_xor_sync(0xffffffffu, tm0, 1));
        tm0 = fmaxf(tm0, __shfl_xor_sync(0xffffffffu, tm0, 2));
        tm1 = fmaxf(tm1, __shfl_xor_sync(0xffffffffu, tm1, 1));
        tm1 = fmaxf(tm1, __shfl_xor_sync(0xffffffffu, tm1, 2));

        float mn0 = fmaxf(m0, tm0), mn1 = fmaxf(m1, tm1);
        float al0 = __expf(m0 - mn0), al1 = __expf(m1 - mn1);
        m0 = mn0; m1 = mn1;

        float s0 = 0.0f, s1 = 0.0f;
#pragma unroll
        for (int nt = 0; nt < 8; nt++) {
            sacc[nt][0] = __expf(sacc[nt][0] - mn0);
            sacc[nt][1] = __expf(sacc[nt][1] - mn0);
            sacc[nt][2] = __expf(sacc[nt][2] - mn1);
            sacc[nt][3] = __expf(sacc[nt][3] - mn1);
            s0 += sacc[nt][0] + sacc[nt][1];
            s1 += sacc[nt][2] + sacc[nt][3];
        }
        s0 += __shfl_xor_sync(0xffffffffu, s0, 1);
        s0 += __shfl_xor_sync(0xffffffffu, s0, 2);
        s1 += __shfl_xor_sync(0xffffffffu, s1, 1);
        s1 += __shfl_xor_sync(0xffffffffu, s1, 2);
        l0 = l0 * al0 + s0;
        l1 = l1 * al1 + s1;

#pragma unroll
        for (int dt = 0; dt < 16; dt++) {
            oacc[dt][0] *= al0; oacc[dt][1] *= al0;
            oacc[dt][2] *= al1; oacc[dt][3] *= al1;
        }

        uint32_t aPh[4][4], aPl[4][4];
#pragma unroll
        for (int ks = 0; ks < 4; ks++) {
            float p00 = sacc[2 * ks][0],     p01 = sacc[2 * ks][1];
            float p02 = sacc[2 * ks][2],     p03 = sacc[2 * ks][3];
            float p10 = sacc[2 * ks + 1][0], p11 = sacc[2 * ks + 1][1];
            float p12 = sacc[2 * ks + 1][2], p13 = sacc[2 * ks + 1][3];
            aPh[ks][0] = packh2(p00, p01);
            aPh[ks][1] = packh2(p02, p03);
            aPh[ks][2] = packh2(p10, p11);
            aPh[ks][3] = packh2(p12, p13);
            __half2 t0 = *(__half2*)&aPh[ks][0];
            __half2 t1 = *(__half2*)&aPh[ks][1];
            __half2 t2 = *(__half2*)&aPh[ks][2];
            __half2 t3 = *(__half2*)&aPh[ks][3];
            aPl[ks][0] = packh2(p00 - __half2float(__low2half(t0)),
                                p01 - __half2float(__high2half(t0)));
            aPl[ks][1] = packh2(p02 - __half2float(__low2half(t1)),
                                p03 - __half2float(__high2half(t1)));
            aPl[ks][2] = packh2(p10 - __half2float(__low2half(t2)),
                                p11 - __half2float(__high2half(t2)));
            aPl[ks][3] = packh2(p12 - __half2float(__low2half(t3)),
                                p13 - __half2float(__high2half(t3)));
        }

#pragma unroll
        for (int ks = 0; ks < 4; ks++) {
#pragma unroll
            for (int dp = 0; dp < 8; dp++) {
                uint32_t bh[4];
                LDSM4T(bh[0], bh[1], bh[2], bh[3],
                       Vh + vLb + (uint32_t)(ks * 16) * FT + dp * 32);
                mma16816(oacc[2 * dp],     aPh[ks], &bh[0]);
                mma16816(oacc[2 * dp + 1], aPh[ks], &bh[2]);
                mma16816(oacc[2 * dp],     aPl[ks], &bh[0]);
                mma16816(oacc[2 * dp + 1], aPl[ks], &bh[2]);
            }
        }
    }

    float inv0 = 1.0f / l0, inv1 = 1.0f / l1;
    int grow = q0 + wid * 16 + r0;
#pragma unroll
    for (int dt = 0; dt < 16; dt++) {
        int col = h * HDIM + dt * 8 + (lane & 3) * 2;
        float v0 = oacc[dt][0] * inv0, v1 = oacc[dt][1] * inv0;
        float v2 = oacc[dt][2] * inv1, v3 = oacc[dt][3] * inv1;

        __half h0 = __float2half(v0), h1 = __float2half(v1);
        __half h2 = __float2half(v2), h3 = __float2half(v3);
        __half2 hi01 = __halves2half2(h0, h1);
        __half2 hi23 = __halves2half2(h2, h3);
        uint32_t lo01 = packh2(v0 - __half2float(h0), v1 - __half2float(h1));
        uint32_t lo23 = packh2(v2 - __half2float(h2), v3 - __half2float(h3));

        uint32_t* pA = (uint32_t*)(xp2 + (size_t)grow * (2 * HID) + col);
        pA[0]       = *(uint32_t*)&hi01;
        pA[HID / 2] = lo01;
        uint32_t* pB = (uint32_t*)(xp2 + (size_t)(grow + 8) * (2 * HID) + col);
        pB[0]       = *(uint32_t*)&hi23;
        pB[HID / 2] = lo23;
    }
}

// ============================================================================
// KV eviction
// ============================================================================
__global__ void evict_kernel(float* __restrict__ outk, float* __restrict__ outv)
{
    int idx = blockIdx.x * blockDim.x + threadIdx.x;
    if (idx >= NHEAD * EVLEN * HDIM) return;
    int d = idx & 127;
    int t = (idx >> 7) % EVLEN;
    int h = idx / (EVLEN * HDIM);
    int src = (t < SINKN) ? t : (S_LEN - RECENT) + (t - SINKN);
    size_t si = ((size_t)h * S_LEN + src) * HDIM + d;
    outk[idx] = g_k[si];
    outv[idx] = g_v[si];
}

// ============================================================================
extern "C" void kernel_launch(void* const* d_in, const int* in_sizes, int n_in,
                              void* d_out, int out_size)
{
    const float* X  = (const float*)d_in[0];
    const float* Wq = (const float*)d_in[1];
    const float* Wk = (const float*)d_in[2];
    const float* Wv = (const float*)d_in[3];
    const float* Wo = (const float*)d_in[4];
    float* out = (float*)d_out;

    float *qb, *kb, *vb;
    __half *xpA, *xp2, *wqk, *wv, *wo;
    cudaGetSymbolAddress((void**)&qb,  g_q);
    cudaGetSymbolAddress((void**)&kb,  g_k);
    cudaGetSymbolAddress((void**)&vb,  g_v);
    cudaGetSymbolAddress((void**)&xpA, g_xpA);
    cudaGetSymbolAddress((void**)&xp2, g_xp2);
    cudaGetSymbolAddress((void**)&wqk, g_wqk);
    cudaGetSymbolAddress((void**)&wv,  g_wv);
    cudaGetSymbolAddress((void**)&wo,  g_wo);

    cudaFuncSetAttribute(mma_gemm_qkv_kernel,
                         cudaFuncAttributeMaxDynamicSharedMemorySize, GEMM_SMEM);
    cudaFuncSetAttribute(mma_gemm_wo_kernel,
                         cudaFuncAttributeMaxDynamicSharedMemorySize, GEMM_SMEM);
    cudaFuncSetAttribute(flash_mma_kernel,
                         cudaFuncAttributeMaxDynamicSharedMemorySize, FA_SMEM);

    const int XO = S_LEN * 512;    // octs in X
    const int WO = HID * 512;      // octs in a weight
    const size_t WSEG2 = (size_t)HID * 2 * HID;

    rope_table_kernel<<<(S_LEN * 64 + 255) / 256, 256>>>();

    convert_split2h_kernel<<<(XO + 255) / 256, 256>>>(X, xpA, XO);
    convert_split2h_kernel<<<(WO + 255) / 256, 256>>>(Wq, wqk,         WO);
    convert_split2h_kernel<<<(WO + 255) / 256, 256>>>(Wk, wqk + WSEG2, WO);
    convert_roundh_kernel<<<(WO + 255) / 256, 256>>>(Wv, wv, WO);
    convert_roundh_kernel<<<(WO + 255) / 256, 256>>>(Wo, wo, WO);

    // merged Q,K,V projections — QK tiles first, V tiles backfill the tail
    mma_gemm_qkv_kernel<<<1536, 256, GEMM_SMEM>>>(xpA, wqk, wv, qb, kb, vb);

    rope_split_kernel<<<(NHEAD * S_LEN * 64) / 256, 256>>>();

    flash_mma_kernel<<<dim3(16, 32), 256, FA_SMEM>>>(xp2);

    // output projection (fp16 2-term)
    dim3 go(S_LEN / 128, HID / 128);           // (16, 32)
    mma_gemm_wo_kernel<<<go, 256, GEMM_SMEM>>>(xp2, wo, out);

    size_t attn_elems = (size_t)S_LEN * HID;
    size_t ev_elems   = (size_t)NHEAD * EVLEN * HDIM;
    evict_kernel<<<(int)((ev_elems + 255) / 256), 256>>>(out + attn_elems,
                                                         out + attn_elems + ev_elems);
}

// round 11
// speedup vs baseline: 4.4348x; 1.0202x over previous
#include <cuda_runtime.h>
#include <cuda_fp16.h>
#include <math.h>
#include <stdint.h>

#define S_LEN  2048
#define HID    4096
#define NHEAD  32
#define HDIM   128
#define RECENT 204
#define SINKN  4
#define EVLEN  (SINKN + RECENT)   // 208

#define STG    16384         // bytes per operand per stage (128 rows x 128 B)
#define GEMM_SMEM (3 * 2 * STG)   // 98304

// flash smem: 272 B per row (128 fp16 + pad)
#define FT     272
#define FTILE  (64 * FT)                // 17408
#define FQ     (128 * FT)               // 34816
#define FA_SMEM (FQ + 4 * FTILE)        // 104448

// convert segment boundaries (in octs of 8 floats; all 256-aligned)
#define OCTS_X (S_LEN * 512)            // 1048576
#define OCTS_W (HID * 512)              // 2097152
#define CV_B0  OCTS_X
#define CV_B1  (CV_B0 + OCTS_W)
#define CV_B2  (CV_B1 + OCTS_W)
#define CV_B3  (CV_B2 + OCTS_W)
#define CV_TOT (CV_B3 + OCTS_W)         // 9437184

// -------- static scratch --------
static __device__ float g_q[NHEAD * S_LEN * HDIM];
static __device__ float g_k[NHEAD * S_LEN * HDIM];
static __device__ float g_v[NHEAD * S_LEN * HDIM];
static __device__ __half g_xpA[(size_t)S_LEN * 2 * HID];   // X  [hi|lo]
static __device__ __half g_xp2[(size_t)S_LEN * 2 * HID];   // O  [hi|lo]
static __device__ __half g_wqk[2ULL * HID * 2 * HID];      // Wq|Wk, each [hi|lo]
static __device__ __half g_wv[(size_t)HID * HID];          // Wv hi
static __device__ __half g_wo[(size_t)HID * HID];          // Wo hi
static __device__ __half g_qh[NHEAD * S_LEN * HDIM];
static __device__ __half g_kh[NHEAD * S_LEN * HDIM];
static __device__ __half g_vh[NHEAD * S_LEN * HDIM];
static __device__ float g_cosT[S_LEN * 64];
static __device__ float g_sinT[S_LEN * 64];

// ============================ helpers =======================================
__device__ __forceinline__ uint32_t smem_u32(const void* p) {
    uint32_t a;
    asm("{ .reg .u64 t; cvta.to.shared.u64 t, %1; cvt.u32.u64 %0, t; }"
        : "=r"(a) : "l"(p));
    return a;
}
#define CP_ASYNC16(dst, src) \
    asm volatile("cp.async.cg.shared.global [%0], [%1], 16;" \
                 :: "r"(dst), "l"(src) : "memory")
#define CP_COMMIT() asm volatile("cp.async.commit_group;" ::: "memory")
#define CP_WAIT1()  asm volatile("cp.async.wait_group 1;" ::: "memory")
#define CP_WAIT0()  asm volatile("cp.async.wait_group 0;" ::: "memory")
#define LDSM4(r0, r1, r2, r3, addr) \
    asm volatile("ldmatrix.sync.aligned.m8n8.x4.shared.b16 {%0,%1,%2,%3}, [%4];" \
                 : "=r"(r0), "=r"(r1), "=r"(r2), "=r"(r3) : "r"(addr))
#define LDSM4T(r0, r1, r2, r3, addr) \
    asm volatile("ldmatrix.sync.aligned.m8n8.x4.trans.shared.b16 {%0,%1,%2,%3}, [%4];" \
                 : "=r"(r0), "=r"(r1), "=r"(r2), "=r"(r3) : "r"(addr))

__device__ __forceinline__ void mma16816(float* c, const uint32_t* a,
                                         const uint32_t* b) {
    asm volatile(
        "mma.sync.aligned.m16n8k16.row.col.f32.f16.f16.f32 "
        "{%0,%1,%2,%3}, {%4,%5,%6,%7}, {%8,%9}, {%0,%1,%2,%3};"
        : "+f"(c[0]), "+f"(c[1]), "+f"(c[2]), "+f"(c[3])
        : "r"(a[0]), "r"(a[1]), "r"(a[2]), "r"(a[3]), "r"(b[0]), "r"(b[1]));
}
__device__ __forceinline__ uint32_t packh2(float x, float y) {
    __half2 t = __halves2half2(__float2half(x), __float2half(y));
    return *(uint32_t*)&t;
}

// ============================================================================
// Fused conversions: one launch covering X/Wq/Wk (split2 [hi|lo]) and
// Wv/Wo (round). Segment selected by flat oct index; boundaries 256-aligned
// so the branch is uniform per block.
// ============================================================================
__global__ void convert_all_kernel(const float* __restrict__ X,
                                   const float* __restrict__ Wq,
                                   const float* __restrict__ Wk,
                                   const float* __restrict__ Wv,
                                   const float* __restrict__ Wo,
                                   __half* __restrict__ xpA,
                                   __half* __restrict__ wqk,
                                   __half* __restrict__ wv,
                                   __half* __restrict__ wo)
{
    int idx = blockIdx.x * blockDim.x + threadIdx.x;
    if (idx >= CV_TOT) return;

    const float* src;
    __half* dst;
    int local, mode;
    const size_t WSEG2 = (size_t)HID * 2 * HID;
    if (idx < CV_B0)      { src = X;  dst = xpA;         local = idx;         mode = 0; }
    else if (idx < CV_B1) { src = Wq; dst = wqk;         local = idx - CV_B0; mode = 0; }
    else if (idx < CV_B2) { src = Wk; dst = wqk + WSEG2; local = idx - CV_B1; mode = 0; }
    else if (idx < CV_B3) { src = Wv; dst = wv;          local = idx - CV_B2; mode = 1; }
    else                  { src = Wo; dst = wo;          local = idx - CV_B3; mode = 1; }

    const float* s = src + (size_t)local * 8;
    float4 x0 = *(const float4*)(s);
    float4 x1 = *(const float4*)(s + 4);
    float xs[8] = {x0.x, x0.y, x0.z, x0.w, x1.x, x1.y, x1.z, x1.w};

    __half hv[8];
    uint4 hi4;
#pragma unroll
    for (int i = 0; i < 8; i++) hv[i] = __float2half(xs[i]);
    ((__half2*)&hi4)[0] = __halves2half2(hv[0], hv[1]);
    ((__half2*)&hi4)[1] = __halves2half2(hv[2], hv[3]);
    ((__half2*)&hi4)[2] = __halves2half2(hv[4], hv[5]);
    ((__half2*)&hi4)[3] = __halves2half2(hv[6], hv[7]);

    if (mode == 1) {
        *(uint4*)(dst + (size_t)local * 8) = hi4;
    } else {
        __half lv[8];
        uint4 lo4;
#pragma unroll
        for (int i = 0; i < 8; i++)
            lv[i] = __float2half(xs[i] - __half2float(hv[i]));
        ((__half2*)&lo4)[0] = __halves2half2(lv[0], lv[1]);
        ((__half2*)&lo4)[1] = __halves2half2(lv[2], lv[3]);
        ((__half2*)&lo4)[2] = __halves2half2(lv[4], lv[5]);
        ((__half2*)&lo4)[3] = __halves2half2(lv[6], lv[7]);
        int r  = local >> 9;
        int c8 = (local & 511) * 8;
        size_t base = (size_t)r * (2 * HID) + c8;
        *(uint4*)(dst + base)       = hi4;
        *(uint4*)(dst + base + HID) = lo4;
    }
}

// ============================================================================
// Merged QKV GEMM (verified R10): A and B stored [hi|lo]; split-term sequence
// via per-stage offset mapping. QK 3-term (NK=192), V 2-term (NK=128).
// ============================================================================
__global__ __launch_bounds__(256, 2)
void mma_gemm_qkv_kernel(const __half* __restrict__ Ap,
                         const __half* __restrict__ Bqk,
                         const __half* __restrict__ Bv,
                         float* __restrict__ Cq, float* __restrict__ Ck,
                         float* __restrict__ Cv)
{
    extern __shared__ __align__(1024) char smem[];
    uint32_t sb = smem_u32(smem);

    int bid = blockIdx.x;
    bool isQK = bid < 1024;
    int t = isQK ? bid : bid - 1024;
    int m0 = (t & 15) * 128;
    int n0 = (t >> 4) * 128;
    int NK = isQK ? 192 : 128;
    int BROWB = isQK ? 16384 : 8192;

    int tid  = threadIdx.x;
    int wid  = tid >> 5, lane = tid & 31;
    int wm   = wid >> 1;
    int wn   = wid & 1;

    const char* Ag = (const char*)Ap + (size_t)m0 * 16384;
    const char* Bg = isQK ? (const char*)Bqk + (size_t)n0 * 16384
                          : (const char*)Bv  + (size_t)n0 * 8192;

    auto issue_stage = [&](int kt) {
        int buf = kt % 3;
        uint32_t sA = sb + (uint32_t)buf * (2 * STG);
        uint32_t sB = sA + STG;
        size_t akoff, bkoff;
        if (isQK) {
            akoff = (size_t)(kt & 63) * 128 + ((kt >= 128) ? 8192 : 0);
            bkoff = (size_t)(kt & 63) * 128 + ((kt >= 64 && kt < 128) ? 8192 : 0);
        } else {
            akoff = (size_t)kt * 128;
            bkoff = (size_t)(kt & 63) * 128;
        }
#pragma unroll
        for (int i = 0; i < 4; i++) {
            int u = tid + i * 256;
            int r = u >> 3, c = (u & 7) * 16;
            uint32_t sw = (uint32_t)(r * 128 + (c ^ ((r & 7) << 4)));
            CP_ASYNC16(sA + sw, Ag + (size_t)r * 16384 + akoff + c);
            CP_ASYNC16(sB + sw, Bg + (size_t)r * BROWB + bkoff + c);
        }
    };

    float acc[2][8][4];
#pragma unroll
    for (int i = 0; i < 2; i++)
#pragma unroll
        for (int j = 0; j < 8; j++)
#pragma unroll
            for (int q = 0; q < 4; q++) acc[i][j][q] = 0.0f;

    issue_stage(0); CP_COMMIT();
    issue_stage(1); CP_COMMIT();

    int arow = wm * 32 + (lane & 15);
    uint32_t aL = (uint32_t)(arow * 128 + (((lane >> 4) * 16) ^ ((arow & 7) << 4)));
    int brow = wn * 64 + (lane >> 4) * 8 + (lane & 7);
    uint32_t bL = (uint32_t)(brow * 128 + ((((lane >> 3) & 1) * 16) ^ ((brow & 7) << 4)));

#pragma unroll 1
    for (int kt = 0; kt < NK; kt++) {
        CP_WAIT1();
        __syncthreads();
        if (kt + 2 < NK) { issue_stage(kt + 2); CP_COMMIT(); }

        uint32_t sA = sb + (uint32_t)(kt % 3) * (2 * STG);
        uint32_t sB = sA + STG;

#pragma unroll
        for (int ks = 0; ks < 4; ks++) {
            uint32_t kx = (uint32_t)(ks << 5);
            uint32_t a[2][4], b[8][2];
            LDSM4(a[0][0], a[0][1], a[0][2], a[0][3], (sA + aL) ^ kx);
            LDSM4(a[1][0], a[1][1], a[1][2], a[1][3], (sA + aL + 2048) ^ kx);
#pragma unroll
            for (int tt = 0; tt < 4; tt++)
                LDSM4(b[2 * tt][0], b[2 * tt][1], b[2 * tt + 1][0], b[2 * tt + 1][1],
                      (sB + bL + (uint32_t)(tt * 2048)) ^ kx);
#pragma unroll
            for (int mt = 0; mt < 2; mt++)
#pragma unroll
                for (int nt = 0; nt < 8; nt++)
                    mma16816(acc[mt][nt], a[mt], b[nt]);
        }
    }
    CP_WAIT0();

    float* base;
    int hh;
    if (isQK) {
        base = (n0 >= 4096) ? Ck : Cq;
        hh = (n0 & 4095) >> 7;
    } else {
        base = Cv;
        hh = n0 >> 7;
    }

#pragma unroll
    for (int mt = 0; mt < 2; mt++) {
        int row = m0 + wm * 32 + mt * 16 + (lane >> 2);
#pragma unroll
        for (int nt = 0; nt < 8; nt++) {
            int col = wn * 64 + nt * 8 + (lane & 3) * 2;
            float2 v01 = make_float2(acc[mt][nt][0], acc[mt][nt][1]);
            float2 v23 = make_float2(acc[mt][nt][2], acc[mt][nt][3]);
            *(float2*)(base + ((size_t)hh * S_LEN + row) * HDIM + col)     = v01;
            *(float2*)(base + ((size_t)hh * S_LEN + row + 8) * HDIM + col) = v23;
        }
    }
}

// ============================================================================
// Wo GEMM (2-term fp16, NK=128), row-major out (verified R10).
// ============================================================================
__global__ __launch_bounds__(256, 2)
void mma_gemm_wo_kernel(const __half* __restrict__ Ap,
                        const __half* __restrict__ Bp,
                        float* __restrict__ C)
{
    extern __shared__ __align__(1024) char smem[];
    uint32_t sb = smem_u32(smem);

    int tid  = threadIdx.x;
    int wid  = tid >> 5, lane = tid & 31;
    int wm   = wid >> 1;
    int wn   = wid & 1;
    int m0   = blockIdx.x * 128;
    int n0   = blockIdx.y * 128;

    const char* Ag = (const char*)Ap + (size_t)m0 * 16384;
    const char* Bg = (const char*)Bp + (size_t)n0 * 8192;

    auto issue_stage = [&](int kt) {
        int buf = kt % 3;
        uint32_t sA = sb + (uint32_t)buf * (2 * STG);
        uint32_t sB = sA + STG;
        size_t akoff = (size_t)kt * 128;
        size_t bkoff = (size_t)(kt & 63) * 128;
#pragma unroll
        for (int i = 0; i < 4; i++) {
            int u = tid + i * 256;
            int r = u >> 3, c = (u & 7) * 16;
            uint32_t sw = (uint32_t)(r * 128 + (c ^ ((r & 7) << 4)));
            CP_ASYNC16(sA + sw, Ag + (size_t)r * 16384 + akoff + c);
            CP_ASYNC16(sB + sw, Bg + (size_t)r * 8192 + bkoff + c);
        }
    };

    float acc[2][8][4];
#pragma unroll
    for (int i = 0; i < 2; i++)
#pragma unroll
        for (int j = 0; j < 8; j++)
#pragma unroll
            for (int q = 0; q < 4; q++) acc[i][j][q] = 0.0f;

    issue_stage(0); CP_COMMIT();
    issue_stage(1); CP_COMMIT();

    int arow = wm * 32 + (lane & 15);
    uint32_t aL = (uint32_t)(arow * 128 + (((lane >> 4) * 16) ^ ((arow & 7) << 4)));
    int brow = wn * 64 + (lane >> 4) * 8 + (lane & 7);
    uint32_t bL = (uint32_t)(brow * 128 + ((((lane >> 3) & 1) * 16) ^ ((brow & 7) << 4)));

#pragma unroll 1
    for (int kt = 0; kt < 128; kt++) {
        CP_WAIT1();
        __syncthreads();
        if (kt + 2 < 128) { issue_stage(kt + 2); CP_COMMIT(); }

        uint32_t sA = sb + (uint32_t)(kt % 3) * (2 * STG);
        uint32_t sB = sA + STG;

#pragma unroll
        for (int ks = 0; ks < 4; ks++) {
            uint32_t kx = (uint32_t)(ks << 5);
            uint32_t a[2][4], b[8][2];
            LDSM4(a[0][0], a[0][1], a[0][2], a[0][3], (sA + aL) ^ kx);
            LDSM4(a[1][0], a[1][1], a[1][2], a[1][3], (sA + aL + 2048) ^ kx);
#pragma unroll
            for (int tt = 0; tt < 4; tt++)
                LDSM4(b[2 * tt][0], b[2 * tt][1], b[2 * tt + 1][0], b[2 * tt + 1][1],
                      (sB + bL + (uint32_t)(tt * 2048)) ^ kx);
#pragma unroll
            for (int mt = 0; mt < 2; mt++)
#pragma unroll
                for (int nt = 0; nt < 8; nt++)
                    mma16816(acc[mt][nt], a[mt], b[nt]);
        }
    }
    CP_WAIT0();

#pragma unroll
    for (int mt = 0; mt < 2; mt++) {
        int row = m0 + wm * 32 + mt * 16 + (lane >> 2);
#pragma unroll
        for (int nt = 0; nt < 8; nt++) {
            int col = n0 + wn * 64 + nt * 8 + (lane & 3) * 2;
            *(float2*)(C + (size_t)row * HID + col) =
                make_float2(acc[mt][nt][0], acc[mt][nt][1]);
            *(float2*)(C + (size_t)(row + 8) * HID + col) =
                make_float2(acc[mt][nt][2], acc[mt][nt][3]);
        }
    }
}

// ============================================================================
// RoPE table (fp64 angles)
// ============================================================================
__global__ void rope_table_kernel()
{
    int idx = blockIdx.x * blockDim.x + threadIdx.x;
    if (idx >= S_LEN * 64) return;
    int d = idx & 63;
    int s = idx >> 6;
    double inv = pow(10000.0, -(double)(2 * d) / 128.0);
    double sd, cd;
    sincos((double)s * inv, &sd, &cd);
    g_cosT[idx] = (float)cd;
    g_sinT[idx] = (float)sd;
}

// ============================================================================
// Fused rope + fp16 rounding: q scaled by (1/sqrt(HD))*log2(e) and rounded,
// k rounded, v rounded. Post-rope k written back fp32 for eviction.
// ============================================================================
__global__ void rope_split_kernel()
{
    int idx = blockIdx.x * blockDim.x + threadIdx.x;
    if (idx >= NHEAD * S_LEN * 64) return;
    int t = idx & (S_LEN * 64 - 1);
    int d = idx & 63;
    int s = (idx >> 6) & (S_LEN - 1);
    int h = idx >> 17;
    float c = g_cosT[t], sn = g_sinT[t];
    // (1/sqrt(128)) * log2(e) — exp2-domain softmax
    const float scale = 0.12751579107f;

    size_t base = ((size_t)h * S_LEN + s) * HDIM;
    float q1 = g_q[base + d], q2 = g_q[base + d + 64];
    float k1 = g_k[base + d], k2 = g_k[base + d + 64];
    float v1 = g_v[base + d], v2 = g_v[base + d + 64];

    float qr1 = (q1 * c - q2 * sn) * scale;
    float qr2 = (q2 * c + q1 * sn) * scale;
    float kr1 = k1 * c - k2 * sn;
    float kr2 = k2 * c + k1 * sn;

    g_k[base + d]      = kr1;
    g_k[base + d + 64] = kr2;

    g_qh[base + d]      = __float2half(qr1);
    g_qh[base + d + 64] = __float2half(qr2);
    g_kh[base + d]      = __float2half(kr1);
    g_kh[base + d + 64] = __float2half(kr2);
    g_vh[base + d]      = __float2half(v1);
    g_vh[base + d + 64] = __float2half(v2);
}

// ============================================================================
// Flash attention fp16: QK 1-term (Qh·Kh), PV 2-term ((Ph+Pl)·Vh).
// exp2-domain softmax (log2e folded into q scale). Br=128, 8 warps along M,
// register P, warp-local softmax. Epilogue writes Wo activations into g_xp2.
// ============================================================================
__global__ __launch_bounds__(256, 1)
void flash_mma_kernel(__half* __restrict__ xp2)
{
    extern __shared__ char fsm_raw[];
    uint32_t sb  = smem_u32(fsm_raw);
    uint32_t sQh = sb;
    uint32_t sKh = sb + FQ;              // + b*FTILE
    uint32_t sVh = sKh + 2 * FTILE;

    int qb  = 15 - blockIdx.x;
    int h   = blockIdx.y;
    int tid = threadIdx.x, wid = tid >> 5, lane = tid & 31;
    int q0  = qb * 128;
    int lastkt = 2 * qb + 1;

    const __half* qhp = g_qh + ((size_t)h * S_LEN + q0) * HDIM;
    const __half* khp = g_kh + (size_t)h * S_LEN * HDIM;
    const __half* vhp = g_vh + (size_t)h * S_LEN * HDIM;

    auto load_tile = [&](int kt, int bb) {
        uint32_t dKh = sKh + (uint32_t)bb * FTILE;
        uint32_t dVh = sVh + (uint32_t)bb * FTILE;
        const __half* s1 = khp + (size_t)kt * 64 * HDIM;
        const __half* s3 = vhp + (size_t)kt * 64 * HDIM;
#pragma unroll
        for (int i = 0; i < 4; i++) {
            int u = tid + i * 256;
            int r = u >> 4, cb = (u & 15) * 16, ce = (u & 15) * 8;
            CP_ASYNC16(dKh + r * FT + cb, s1 + r * HDIM + ce);
            CP_ASYNC16(dVh + r * FT + cb, s3 + r * HDIM + ce);
        }
    };

#pragma unroll
    for (int i = 0; i < 8; i++) {
        int u = tid + i * 256;
        int r = u >> 4, cb = (u & 15) * 16, ce = (u & 15) * 8;
        CP_ASYNC16(sQh + r * FT + cb, qhp + r * HDIM + ce);
    }
    load_tile(0, 0);
    CP_COMMIT();

    float oacc[16][4];
#pragma unroll
    for (int i = 0; i < 16; i++)
#pragma unroll
        for (int j = 0; j < 4; j++) oacc[i][j] = 0.0f;
    float m0 = -INFINITY, m1 = -INFINITY, l0 = 0.0f, l1 = 0.0f;

    uint32_t aLq = (uint32_t)((wid * 16 + (lane & 15)) * FT + (lane >> 4) * 16);
    uint32_t bLk = (uint32_t)(((lane >> 4) * 8 + (lane & 7)) * FT
                              + ((lane >> 3) & 1) * 16);
    uint32_t vLb = (uint32_t)((lane & 15) * FT + (lane >> 4) * 16);
    int r0 = lane >> 2;

#pragma unroll 1
    for (int kt = 0; kt <= lastkt; kt++) {
        int b = kt & 1;
        CP_WAIT0();
        __syncthreads();
        if (kt < lastkt) { load_tile(kt + 1, b ^ 1); CP_COMMIT(); }

        uint32_t Kh = sKh + (uint32_t)b * FTILE;
        uint32_t Vh = sVh + (uint32_t)b * FTILE;

        // ---- scores: Qh·Kh ----
        float sacc[8][4];
#pragma unroll
        for (int i = 0; i < 8; i++)
#pragma unroll
            for (int j = 0; j < 4; j++) sacc[i][j] = 0.0f;
#pragma unroll
        for (int ks = 0; ks < 8; ks++) {
            uint32_t ah[4];
            LDSM4(ah[0], ah[1], ah[2], ah[3], sQh + aLq + ks * 32);
#pragma unroll
            for (int t = 0; t < 4; t++) {
                uint32_t x[4];
                LDSM4(x[0], x[1], x[2], x[3], Kh + bLk + t * 16 * FT + ks * 32);
                mma16816(sacc[2 * t],     ah, &x[0]);
                mma16816(sacc[2 * t + 1], ah, &x[2]);
            }
        }

        if (kt >= 2 * qb) {
            int gr0 = q0 + wid * 16 + r0;
            int gr1 = gr0 + 8;
            int gcb = kt * 64 + (lane & 3) * 2;
#pragma unroll
            for (int nt = 0; nt < 8; nt++) {
                int gc = gcb + nt * 8;
                if (gc     > gr0) sacc[nt][0] = -INFINITY;
                if (gc + 1 > gr0) sacc[nt][1] = -INFINITY;
                if (gc     > gr1) sacc[nt][2] = -INFINITY;
                if (gc + 1 > gr1) sacc[nt][3] = -INFINITY;
            }
        }

        float tm0 = -INFINITY, tm1 = -INFINITY;
#pragma unroll
        for (int nt = 0; nt < 8; nt++) {
            tm0 = fmaxf(tm0, fmaxf(sacc[nt][0], sacc[nt][1]));
            tm1 = fmaxf(tm1, fmaxf(sacc[nt][2], sacc[nt][3]));
        }
        tm0 = fmaxf(tm0, __shfl_xor_sync(0xffffffffu, tm0, 1));
        tm0 = fmaxf(tm0, __shfl_xor_sync(0xffffffffu, tm0, 2));
        tm1 = fmaxf(tm1, __shfl_xor_sync(0xffffffffu, tm1, 1));
        tm1 = fmaxf(tm1, __shfl_xor_sync(0xffffffffu, tm1, 2));

        float mn0 = fmaxf(m0, tm0), mn1 = fmaxf(m1, tm1);
        float al0 = exp2f(m0 - mn0), al1 = exp2f(m1 - mn1);
        m0 = mn0; m1 = mn1;

        float s0 = 0.0f, s1 = 0.0f;
#pragma unroll
        for (int nt = 0; nt < 8; nt++) {
            sacc[nt][0] = exp2f(sacc[nt][0] - mn0);
            sacc[nt][1] = exp2f(sacc[nt][1] - mn0);
            sacc[nt][2] = exp2f(sacc[nt][2] - mn1);
            sacc[nt][3] = exp2f(sacc[nt][3] - mn1);
            s0 += sacc[nt][0] + sacc[nt][1];
            s1 += sacc[nt][2] + sacc[nt][3];
        }
        s0 += __shfl_xor_sync(0xffffffffu, s0, 1);
        s0 += __shfl_xor_sync(0xffffffffu, s0, 2);
        s1 += __shfl_xor_sync(0xffffffffu, s1, 1);
        s1 += __shfl_xor_sync(0xffffffffu, s1, 2);
        l0 = l0 * al0 + s0;
        l1 = l1 * al1 + s1;

#pragma unroll
        for (int dt = 0; dt < 16; dt++) {
            oacc[dt][0] *= al0; oacc[dt][1] *= al0;
            oacc[dt][2] *= al1; oacc[dt][3] *= al1;
        }

        uint32_t aPh[4][4], aPl[4][4];
#pragma unroll
        for (int ks = 0; ks < 4; ks++) {
            float p00 = sacc[2 * ks][0],     p01 = sacc[2 * ks][1];
            float p02 = sacc[2 * ks][2],     p03 = sacc[2 * ks][3];
            float p10 = sacc[2 * ks + 1][0], p11 = sacc[2 * ks + 1][1];
            float p12 = sacc[2 * ks + 1][2], p13 = sacc[2 * ks + 1][3];
            aPh[ks][0] = packh2(p00, p01);
            aPh[ks][1] = packh2(p02, p03);
            aPh[ks][2] = packh2(p10, p11);
            aPh[ks][3] = packh2(p12, p13);
            __half2 t0 = *(__half2*)&aPh[ks][0];
            __half2 t1 = *(__half2*)&aPh[ks][1];
            __half2 t2 = *(__half2*)&aPh[ks][2];
            __half2 t3 = *(__half2*)&aPh[ks][3];
            aPl[ks][0] = packh2(p00 - __half2float(__low2half(t0)),
                                p01 - __half2float(__high2half(t0)));
            aPl[ks][1] = packh2(p02 - __half2float(__low2half(t1)),
                                p03 - __half2float(__high2half(t1)));
            aPl[ks][2] = packh2(p10 - __half2float(__low2half(t2)),
                                p11 - __half2float(__high2half(t2)));
            aPl[ks][3] = packh2(p12 - __half2float(__low2half(t3)),
                                p13 - __half2float(__high2half(t3)));
        }

#pragma unroll
        for (int ks = 0; ks < 4; ks++) {
#pragma unroll
            for (int dp = 0; dp < 8; dp++) {
                uint32_t bh[4];
                LDSM4T(bh[0], bh[1], bh[2], bh[3],
                       Vh + vLb + (uint32_t)(ks * 16) * FT + dp * 32);
                mma16816(oacc[2 * dp],     aPh[ks], &bh[0]);
                mma16816(oacc[2 * dp + 1], aPh[ks], &bh[2]);
                mma16816(oacc[2 * dp],     aPl[ks], &bh[0]);
                mma16816(oacc[2 * dp + 1], aPl[ks], &bh[2]);
            }
        }
    }

    float inv0 = 1.0f / l0, inv1 = 1.0f / l1;
    int grow = q0 + wid * 16 + r0;
#pragma unroll
    for (int dt = 0; dt < 16; dt++) {
        int col = h * HDIM + dt * 8 + (lane & 3) * 2;
        float v0 = oacc[dt][0] * inv0, v1 = oacc[dt][1] * inv0;
        float v2 = oacc[dt][2] * inv1, v3 = oacc[dt][3] * inv1;

        __half h0 = __float2half(v0), h1 = __float2half(v1);
        __half h2 = __float2half(v2), h3 = __float2half(v3);
        __half2 hi01 = __halves2half2(h0, h1);
        __half2 hi23 = __halves2half2(h2, h3);
        uint32_t lo01 = packh2(v0 - __half2float(h0), v1 - __half2float(h1));
        uint32_t lo23 = packh2(v2 - __half2float(h2), v3 - __half2float(h3));

        uint32_t* pA = (uint32_t*)(xp2 + (size_t)grow * (2 * HID) + col);
        pA[0]       = *(uint32_t*)&hi01;
        pA[HID / 2] = lo01;
        uint32_t* pB = (uint32_t*)(xp2 + (size_t)(grow + 8) * (2 * HID) + col);
        pB[0]       = *(uint32_t*)&hi23;
        pB[HID / 2] = lo23;
    }
}

// ============================================================================
// KV eviction
// ============================================================================
__global__ void evict_kernel(float* __restrict__ outk, float* __restrict__ outv)
{
    int idx = blockIdx.x * blockDim.x + threadIdx.x;
    if (idx >= NHEAD * EVLEN * HDIM) return;
    int d = idx & 127;
    int t = (idx >> 7) % EVLEN;
    int h = idx / (EVLEN * HDIM);
    int src = (t < SINKN) ? t : (S_LEN - RECENT) + (t - SINKN);
    size_t si = ((size_t)h * S_LEN + src) * HDIM + d;
    outk[idx] = g_k[si];
    outv[idx] = g_v[si];
}

// ============================================================================
extern "C" void kernel_launch(void* const* d_in, const int* in_sizes, int n_in,
                              void* d_out, int out_size)
{
    const float* X  = (const float*)d_in[0];
    const float* Wq = (const float*)d_in[1];
    const float* Wk = (const float*)d_in[2];
    const float* Wv = (const float*)d_in[3];
    const float* Wo = (const float*)d_in[4];
    float* out = (float*)d_out;

    float *qb, *kb, *vb;
    __half *xpA, *xp2, *wqk, *wv, *wo;
    cudaGetSymbolAddress((void**)&qb,  g_q);
    cudaGetSymbolAddress((void**)&kb,  g_k);
    cudaGetSymbolAddress((void**)&vb,  g_v);
    cudaGetSymbolAddress((void**)&xpA, g_xpA);
    cudaGetSymbolAddress((void**)&xp2, g_xp2);
    cudaGetSymbolAddress((void**)&wqk, g_wqk);
    cudaGetSymbolAddress((void**)&wv,  g_wv);
    cudaGetSymbolAddress((void**)&wo,  g_wo);

    cudaFuncSetAttribute(mma_gemm_qkv_kernel,
                         cudaFuncAttributeMaxDynamicSharedMemorySize, GEMM_SMEM);
    cudaFuncSetAttribute(mma_gemm_wo_kernel,
                         cudaFuncAttributeMaxDynamicSharedMemorySize, GEMM_SMEM);
    cudaFuncSetAttribute(flash_mma_kernel,
                         cudaFuncAttributeMaxDynamicSharedMemorySize, FA_SMEM);

    rope_table_kernel<<<(S_LEN * 64 + 255) / 256, 256>>>();

    // all conversions in one launch
    convert_all_kernel<<<CV_TOT / 256, 256>>>(X, Wq, Wk, Wv, Wo,
                                              xpA, wqk, wv, wo);

    // merged Q,K,V projections — QK tiles first, V tiles backfill the tail
    mma_gemm_qkv_kernel<<<1536, 256, GEMM_SMEM>>>(xpA, wqk, wv, qb, kb, vb);

    rope_split_kernel<<<(NHEAD * S_LEN * 64) / 256, 256>>>();

    flash_mma_kernel<<<dim3(16, 32), 256, FA_SMEM>>>(xp2);

    // output projection (fp16 2-term)
    dim3 go(S_LEN / 128, HID / 128);           // (16, 32)
    mma_gemm_wo_kernel<<<go, 256, GEMM_SMEM>>>(xp2, wo, out);

    size_t attn_elems = (size_t)S_LEN * HID;
    size_t ev_elems   = (size_t)NHEAD * EVLEN * HDIM;
    evict_kernel<<<(int)((ev_elems + 255) / 256), 256>>>(out + attn_elems,
                                                         out + attn_elems + ev_elems);
}

// round 12
// speedup vs baseline: 5.2929x; 1.1935x over previous
#include <cuda_runtime.h>
#include <cuda_fp16.h>
#include <math.h>
#include <stdint.h>

#define S_LEN  2048
#define HID    4096
#define NHEAD  32
#define HDIM   128
#define RECENT 204
#define SINKN  4
#define EVLEN  (SINKN + RECENT)   // 208

#define STG    16384         // bytes per operand per stage (128 rows x 128 B)
#define GEMM_SMEM (3 * 2 * STG)   // 98304

// flash smem: 272 B per row (128 fp16 + pad)
#define FT     272
#define FTILE  (64 * FT)                // 17408
#define FQ     (128 * FT)               // 34816
#define FA_SMEM (FQ + 4 * FTILE)        // 104448

// convert segment boundaries (in octs of 8 floats; all 256-aligned)
#define OCTS_X (S_LEN * 512)            // 1048576
#define OCTS_W (HID * 512)              // 2097152
#define CV_B0  OCTS_X
#define CV_B1  (CV_B0 + OCTS_W)
#define CV_B2  (CV_B1 + OCTS_W)
#define CV_B3  (CV_B2 + OCTS_W)
#define CV_TOT (CV_B3 + OCTS_W)         // 9437184

// -------- static scratch --------
static __device__ float g_q[NHEAD * S_LEN * HDIM];
static __device__ float g_k[NHEAD * S_LEN * HDIM];
static __device__ float g_v[NHEAD * S_LEN * HDIM];
static __device__ __half g_xpA[(size_t)S_LEN * 2 * HID];   // X  [hi|lo]
static __device__ __half g_xp2[(size_t)S_LEN * 2 * HID];   // O  [hi|lo]
static __device__ __half g_wqkv[3ULL * HID * HID];         // Wq|Wk|Wv rounded
static __device__ __half g_wo[(size_t)HID * HID];          // Wo rounded
static __device__ __half g_qh[NHEAD * S_LEN * HDIM];
static __device__ __half g_kh[NHEAD * S_LEN * HDIM];
static __device__ __half g_vh[NHEAD * S_LEN * HDIM];
static __device__ float g_cosT[S_LEN * 64];
static __device__ float g_sinT[S_LEN * 64];

// ============================ helpers =======================================
__device__ __forceinline__ uint32_t smem_u32(const void* p) {
    uint32_t a;
    asm("{ .reg .u64 t; cvta.to.shared.u64 t, %1; cvt.u32.u64 %0, t; }"
        : "=r"(a) : "l"(p));
    return a;
}
#define CP_ASYNC16(dst, src) \
    asm volatile("cp.async.cg.shared.global [%0], [%1], 16;" \
                 :: "r"(dst), "l"(src) : "memory")
#define CP_COMMIT() asm volatile("cp.async.commit_group;" ::: "memory")
#define CP_WAIT1()  asm volatile("cp.async.wait_group 1;" ::: "memory")
#define CP_WAIT0()  asm volatile("cp.async.wait_group 0;" ::: "memory")
#define LDSM4(r0, r1, r2, r3, addr) \
    asm volatile("ldmatrix.sync.aligned.m8n8.x4.shared.b16 {%0,%1,%2,%3}, [%4];" \
                 : "=r"(r0), "=r"(r1), "=r"(r2), "=r"(r3) : "r"(addr))
#define LDSM4T(r0, r1, r2, r3, addr) \
    asm volatile("ldmatrix.sync.aligned.m8n8.x4.trans.shared.b16 {%0,%1,%2,%3}, [%4];" \
                 : "=r"(r0), "=r"(r1), "=r"(r2), "=r"(r3) : "r"(addr))

__device__ __forceinline__ void mma16816(float* c, const uint32_t* a,
                                         const uint32_t* b) {
    asm volatile(
        "mma.sync.aligned.m16n8k16.row.col.f32.f16.f16.f32 "
        "{%0,%1,%2,%3}, {%4,%5,%6,%7}, {%8,%9}, {%0,%1,%2,%3};"
        : "+f"(c[0]), "+f"(c[1]), "+f"(c[2]), "+f"(c[3])
        : "r"(a[0]), "r"(a[1]), "r"(a[2]), "r"(a[3]), "r"(b[0]), "r"(b[1]));
}
__device__ __forceinline__ uint32_t packh2(float x, float y) {
    __half2 t = __halves2half2(__float2half(x), __float2half(y));
    return *(uint32_t*)&t;
}

// ============================================================================
// Fused conversions: X -> split2 [hi|lo]; Wq/Wk/Wv -> rounded into g_wqkv
// segments; Wo -> rounded. One launch; segment by flat oct index.
// ============================================================================
__global__ void convert_all_kernel(const float* __restrict__ X,
                                   const float* __restrict__ Wq,
                                   const float* __restrict__ Wk,
                                   const float* __restrict__ Wv,
                                   const float* __restrict__ Wo,
                                   __half* __restrict__ xpA,
                                   __half* __restrict__ wqkv,
                                   __half* __restrict__ wo)
{
    int idx = blockIdx.x * blockDim.x + threadIdx.x;
    if (idx >= CV_TOT) return;

    const float* src;
    __half* dst;
    int local, mode;
    const size_t WSEG = (size_t)HID * HID;
    if (idx < CV_B0)      { src = X;  dst = xpA;            local = idx;         mode = 0; }
    else if (idx < CV_B1) { src = Wq; dst = wqkv;           local = idx - CV_B0; mode = 1; }
    else if (idx < CV_B2) { src = Wk; dst = wqkv + WSEG;    local = idx - CV_B1; mode = 1; }
    else if (idx < CV_B3) { src = Wv; dst = wqkv + 2 * WSEG;local = idx - CV_B2; mode = 1; }
    else                  { src = Wo; dst = wo;             local = idx - CV_B3; mode = 1; }

    const float* s = src + (size_t)local * 8;
    float4 x0 = *(const float4*)(s);
    float4 x1 = *(const float4*)(s + 4);
    float xs[8] = {x0.x, x0.y, x0.z, x0.w, x1.x, x1.y, x1.z, x1.w};

    __half hv[8];
    uint4 hi4;
#pragma unroll
    for (int i = 0; i < 8; i++) hv[i] = __float2half(xs[i]);
    ((__half2*)&hi4)[0] = __halves2half2(hv[0], hv[1]);
    ((__half2*)&hi4)[1] = __halves2half2(hv[2], hv[3]);
    ((__half2*)&hi4)[2] = __halves2half2(hv[4], hv[5]);
    ((__half2*)&hi4)[3] = __halves2half2(hv[6], hv[7]);

    if (mode == 1) {
        *(uint4*)(dst + (size_t)local * 8) = hi4;
    } else {
        __half lv[8];
        uint4 lo4;
#pragma unroll
        for (int i = 0; i < 8; i++)
            lv[i] = __float2half(xs[i] - __half2float(hv[i]));
        ((__half2*)&lo4)[0] = __halves2half2(lv[0], lv[1]);
        ((__half2*)&lo4)[1] = __halves2half2(lv[2], lv[3]);
        ((__half2*)&lo4)[2] = __halves2half2(lv[4], lv[5]);
        ((__half2*)&lo4)[3] = __halves2half2(lv[6], lv[7]);
        int r  = local >> 9;
        int c8 = (local & 511) * 8;
        size_t base = (size_t)r * (2 * HID) + c8;
        *(uint4*)(dst + base)       = hi4;
        *(uint4*)(dst + base + HID) = lo4;
    }
}

// ============================================================================
// Uniform 2-term GEMM: C = (Ah + Al) @ B^T, fp32 accum. NK=128; A=[hi|lo]
// (akoff = kt*128), B single segment wrap (bkoff = (kt&63)*128).
// HEADS=1: N=12288 over concat [Wq|Wk|Wv], writes heads layout into q/k/v.
// HEADS=0: N=4096 (Wo), row-major output into C0.
// ============================================================================
template <int HEADS>
__global__ __launch_bounds__(256, 2)
void mma_gemm_kernel(const __half* __restrict__ Ap,
                     const __half* __restrict__ Bp,
                     float* __restrict__ Cq, float* __restrict__ Ck,
                     float* __restrict__ Cv)
{
    extern __shared__ __align__(1024) char smem[];
    uint32_t sb = smem_u32(smem);

    int bid = blockIdx.x;
    int m0 = (bid & 15) * 128;        // m fastest for L2 reuse of A
    int n0 = (bid >> 4) * 128;

    int tid  = threadIdx.x;
    int wid  = tid >> 5, lane = tid & 31;
    int wm   = wid >> 1;
    int wn   = wid & 1;

    const char* Ag = (const char*)Ap + (size_t)m0 * 16384;
    const char* Bg = (const char*)Bp + (size_t)n0 * 8192;

    auto issue_stage = [&](int kt) {
        int buf = kt % 3;
        uint32_t sA = sb + (uint32_t)buf * (2 * STG);
        uint32_t sB = sA + STG;
        size_t akoff = (size_t)kt * 128;
        size_t bkoff = (size_t)(kt & 63) * 128;
#pragma unroll
        for (int i = 0; i < 4; i++) {
            int u = tid + i * 256;
            int r = u >> 3, c = (u & 7) * 16;
            uint32_t sw = (uint32_t)(r * 128 + (c ^ ((r & 7) << 4)));
            CP_ASYNC16(sA + sw, Ag + (size_t)r * 16384 + akoff + c);
            CP_ASYNC16(sB + sw, Bg + (size_t)r * 8192 + bkoff + c);
        }
    };

    float acc[2][8][4];
#pragma unroll
    for (int i = 0; i < 2; i++)
#pragma unroll
        for (int j = 0; j < 8; j++)
#pragma unroll
            for (int q = 0; q < 4; q++) acc[i][j][q] = 0.0f;

    issue_stage(0); CP_COMMIT();
    issue_stage(1); CP_COMMIT();

    int arow = wm * 32 + (lane & 15);
    uint32_t aL = (uint32_t)(arow * 128 + (((lane >> 4) * 16) ^ ((arow & 7) << 4)));
    int brow = wn * 64 + (lane >> 4) * 8 + (lane & 7);
    uint32_t bL = (uint32_t)(brow * 128 + ((((lane >> 3) & 1) * 16) ^ ((brow & 7) << 4)));

#pragma unroll 1
    for (int kt = 0; kt < 128; kt++) {
        CP_WAIT1();
        __syncthreads();
        if (kt + 2 < 128) { issue_stage(kt + 2); CP_COMMIT(); }

        uint32_t sA = sb + (uint32_t)(kt % 3) * (2 * STG);
        uint32_t sB = sA + STG;

#pragma unroll
        for (int ks = 0; ks < 4; ks++) {
            uint32_t kx = (uint32_t)(ks << 5);
            uint32_t a[2][4], b[8][2];
            LDSM4(a[0][0], a[0][1], a[0][2], a[0][3], (sA + aL) ^ kx);
            LDSM4(a[1][0], a[1][1], a[1][2], a[1][3], (sA + aL + 2048) ^ kx);
#pragma unroll
            for (int tt = 0; tt < 4; tt++)
                LDSM4(b[2 * tt][0], b[2 * tt][1], b[2 * tt + 1][0], b[2 * tt + 1][1],
                      (sB + bL + (uint32_t)(tt * 2048)) ^ kx);
#pragma unroll
            for (int mt = 0; mt < 2; mt++)
#pragma unroll
                for (int nt = 0; nt < 8; nt++)
                    mma16816(acc[mt][nt], a[mt], b[nt]);
        }
    }
    CP_WAIT0();

    if (HEADS) {
        float* base = (n0 < 4096) ? Cq : ((n0 < 8192) ? Ck : Cv);
        int hh = (n0 & 4095) >> 7;
#pragma unroll
        for (int mt = 0; mt < 2; mt++) {
            int row = m0 + wm * 32 + mt * 16 + (lane >> 2);
#pragma unroll
            for (int nt = 0; nt < 8; nt++) {
                int col = wn * 64 + nt * 8 + (lane & 3) * 2;
                *(float2*)(base + ((size_t)hh * S_LEN + row) * HDIM + col) =
                    make_float2(acc[mt][nt][0], acc[mt][nt][1]);
                *(float2*)(base + ((size_t)hh * S_LEN + row + 8) * HDIM + col) =
                    make_float2(acc[mt][nt][2], acc[mt][nt][3]);
            }
        }
    } else {
#pragma unroll
        for (int mt = 0; mt < 2; mt++) {
            int row = m0 + wm * 32 + mt * 16 + (lane >> 2);
#pragma unroll
            for (int nt = 0; nt < 8; nt++) {
                int col = n0 + wn * 64 + nt * 8 + (lane & 3) * 2;
                *(float2*)(Cq + (size_t)row * HID + col) =
                    make_float2(acc[mt][nt][0], acc[mt][nt][1]);
                *(float2*)(Cq + (size_t)(row + 8) * HID + col) =
                    make_float2(acc[mt][nt][2], acc[mt][nt][3]);
            }
        }
    }
}

// ============================================================================
// RoPE table (fp64 angles)
// ============================================================================
__global__ void rope_table_kernel()
{
    int idx = blockIdx.x * blockDim.x + threadIdx.x;
    if (idx >= S_LEN * 64) return;
    int d = idx & 63;
    int s = idx >> 6;
    double inv = pow(10000.0, -(double)(2 * d) / 128.0);
    double sd, cd;
    sincos((double)s * inv, &sd, &cd);
    g_cosT[idx] = (float)cd;
    g_sinT[idx] = (float)sd;
}

// ============================================================================
// Fused rope + fp16 rounding: q scaled by (1/sqrt(HD))*log2(e) and rounded,
// k rounded, v rounded. Post-rope k written back fp32 for eviction.
// ============================================================================
__global__ void rope_split_kernel()
{
    int idx = blockIdx.x * blockDim.x + threadIdx.x;
    if (idx >= NHEAD * S_LEN * 64) return;
    int t = idx & (S_LEN * 64 - 1);
    int d = idx & 63;
    int s = (idx >> 6) & (S_LEN - 1);
    int h = idx >> 17;
    float c = g_cosT[t], sn = g_sinT[t];
    const float scale = 0.12751579107f;   // (1/sqrt(128)) * log2(e)

    size_t base = ((size_t)h * S_LEN + s) * HDIM;
    float q1 = g_q[base + d], q2 = g_q[base + d + 64];
    float k1 = g_k[base + d], k2 = g_k[base + d + 64];
    float v1 = g_v[base + d], v2 = g_v[base + d + 64];

    float qr1 = (q1 * c - q2 * sn) * scale;
    float qr2 = (q2 * c + q1 * sn) * scale;
    float kr1 = k1 * c - k2 * sn;
    float kr2 = k2 * c + k1 * sn;

    g_k[base + d]      = kr1;
    g_k[base + d + 64] = kr2;

    g_qh[base + d]      = __float2half(qr1);
    g_qh[base + d + 64] = __float2half(qr2);
    g_kh[base + d]      = __float2half(kr1);
    g_kh[base + d + 64] = __float2half(kr2);
    g_vh[base + d]      = __float2half(v1);
    g_vh[base + d + 64] = __float2half(v2);
}

// ============================================================================
// Flash attention fp16 (verified R11): QK 1-term, PV 2-term, exp2 softmax.
// ============================================================================
__global__ __launch_bounds__(256, 1)
void flash_mma_kernel(__half* __restrict__ xp2)
{
    extern __shared__ char fsm_raw[];
    uint32_t sb  = smem_u32(fsm_raw);
    uint32_t sQh = sb;
    uint32_t sKh = sb + FQ;              // + b*FTILE
    uint32_t sVh = sKh + 2 * FTILE;

    int qb  = 15 - blockIdx.x;
    int h   = blockIdx.y;
    int tid = threadIdx.x, wid = tid >> 5, lane = tid & 31;
    int q0  = qb * 128;
    int lastkt = 2 * qb + 1;

    const __half* qhp = g_qh + ((size_t)h * S_LEN + q0) * HDIM;
    const __half* khp = g_kh + (size_t)h * S_LEN * HDIM;
    const __half* vhp = g_vh + (size_t)h * S_LEN * HDIM;

    auto load_tile = [&](int kt, int bb) {
        uint32_t dKh = sKh + (uint32_t)bb * FTILE;
        uint32_t dVh = sVh + (uint32_t)bb * FTILE;
        const __half* s1 = khp + (size_t)kt * 64 * HDIM;
        const __half* s3 = vhp + (size_t)kt * 64 * HDIM;
#pragma unroll
        for (int i = 0; i < 4; i++) {
            int u = tid + i * 256;
            int r = u >> 4, cb = (u & 15) * 16, ce = (u & 15) * 8;
            CP_ASYNC16(dKh + r * FT + cb, s1 + r * HDIM + ce);
            CP_ASYNC16(dVh + r * FT + cb, s3 + r * HDIM + ce);
        }
    };

#pragma unroll
    for (int i = 0; i < 8; i++) {
        int u = tid + i * 256;
        int r = u >> 4, cb = (u & 15) * 16, ce = (u & 15) * 8;
        CP_ASYNC16(sQh + r * FT + cb, qhp + r * HDIM + ce);
    }
    load_tile(0, 0);
    CP_COMMIT();

    float oacc[16][4];
#pragma unroll
    for (int i = 0; i < 16; i++)
#pragma unroll
        for (int j = 0; j < 4; j++) oacc[i][j] = 0.0f;
    float m0 = -INFINITY, m1 = -INFINITY, l0 = 0.0f, l1 = 0.0f;

    uint32_t aLq = (uint32_t)((wid * 16 + (lane & 15)) * FT + (lane >> 4) * 16);
    uint32_t bLk = (uint32_t)(((lane >> 4) * 8 + (lane & 7)) * FT
                              + ((lane >> 3) & 1) * 16);
    uint32_t vLb = (uint32_t)((lane & 15) * FT + (lane >> 4) * 16);
    int r0 = lane >> 2;

#pragma unroll 1
    for (int kt = 0; kt <= lastkt; kt++) {
        int b = kt & 1;
        CP_WAIT0();
        __syncthreads();
        if (kt < lastkt) { load_tile(kt + 1, b ^ 1); CP_COMMIT(); }

        uint32_t Kh = sKh + (uint32_t)b * FTILE;
        uint32_t Vh = sVh + (uint32_t)b * FTILE;

        float sacc[8][4];
#pragma unroll
        for (int i = 0; i < 8; i++)
#pragma unroll
            for (int j = 0; j < 4; j++) sacc[i][j] = 0.0f;
#pragma unroll
        for (int ks = 0; ks < 8; ks++) {
            uint32_t ah[4];
            LDSM4(ah[0], ah[1], ah[2], ah[3], sQh + aLq + ks * 32);
#pragma unroll
            for (int t = 0; t < 4; t++) {
                uint32_t x[4];
                LDSM4(x[0], x[1], x[2], x[3], Kh + bLk + t * 16 * FT + ks * 32);
                mma16816(sacc[2 * t],     ah, &x[0]);
                mma16816(sacc[2 * t + 1], ah, &x[2]);
            }
        }

        if (kt >= 2 * qb) {
            int gr0 = q0 + wid * 16 + r0;
            int gr1 = gr0 + 8;
            int gcb = kt * 64 + (lane & 3) * 2;
#pragma unroll
            for (int nt = 0; nt < 8; nt++) {
                int gc = gcb + nt * 8;
                if (gc     > gr0) sacc[nt][0] = -INFINITY;
                if (gc + 1 > gr0) sacc[nt][1] = -INFINITY;
                if (gc     > gr1) sacc[nt][2] = -INFINITY;
                if (gc + 1 > gr1) sacc[nt][3] = -INFINITY;
            }
        }

        float tm0 = -INFINITY, tm1 = -INFINITY;
#pragma unroll
        for (int nt = 0; nt < 8; nt++) {
            tm0 = fmaxf(tm0, fmaxf(sacc[nt][0], sacc[nt][1]));
            tm1 = fmaxf(tm1, fmaxf(sacc[nt][2], sacc[nt][3]));
        }
        tm0 = fmaxf(tm0, __shfl_xor_sync(0xffffffffu, tm0, 1));
        tm0 = fmaxf(tm0, __shfl_xor_sync(0xffffffffu, tm0, 2));
        tm1 = fmaxf(tm1, __shfl_xor_sync(0xffffffffu, tm1, 1));
        tm1 = fmaxf(tm1, __shfl_xor_sync(0xffffffffu, tm1, 2));

        float mn0 = fmaxf(m0, tm0), mn1 = fmaxf(m1, tm1);
        float al0 = exp2f(m0 - mn0), al1 = exp2f(m1 - mn1);
        m0 = mn0; m1 = mn1;

        float s0 = 0.0f, s1 = 0.0f;
#pragma unroll
        for (int nt = 0; nt < 8; nt++) {
            sacc[nt][0] = exp2f(sacc[nt][0] - mn0);
            sacc[nt][1] = exp2f(sacc[nt][1] - mn0);
            sacc[nt][2] = exp2f(sacc[nt][2] - mn1);
            sacc[nt][3] = exp2f(sacc[nt][3] - mn1);
            s0 += sacc[nt][0] + sacc[nt][1];
            s1 += sacc[nt][2] + sacc[nt][3];
        }
        s0 += __shfl_xor_sync(0xffffffffu, s0, 1);
        s0 += __shfl_xor_sync(0xffffffffu, s0, 2);
        s1 += __shfl_xor_sync(0xffffffffu, s1, 1);
        s1 += __shfl_xor_sync(0xffffffffu, s1, 2);
        l0 = l0 * al0 + s0;
        l1 = l1 * al1 + s1;

#pragma unroll
        for (int dt = 0; dt < 16; dt++) {
            oacc[dt][0] *= al0; oacc[dt][1] *= al0;
            oacc[dt][2] *= al1; oacc[dt][3] *= al1;
        }

        uint32_t aPh[4][4], aPl[4][4];
#pragma unroll
        for (int ks = 0; ks < 4; ks++) {
            float p00 = sacc[2 * ks][0],     p01 = sacc[2 * ks][1];
            float p02 = sacc[2 * ks][2],     p03 = sacc[2 * ks][3];
            float p10 = sacc[2 * ks + 1][0], p11 = sacc[2 * ks + 1][1];
            float p12 = sacc[2 * ks + 1][2], p13 = sacc[2 * ks + 1][3];
            aPh[ks][0] = packh2(p00, p01);
            aPh[ks][1] = packh2(p02, p03);
            aPh[ks][2] = packh2(p10, p11);
            aPh[ks][3] = packh2(p12, p13);
            __half2 t0 = *(__half2*)&aPh[ks][0];
            __half2 t1 = *(__half2*)&aPh[ks][1];
            __half2 t2 = *(__half2*)&aPh[ks][2];
            __half2 t3 = *(__half2*)&aPh[ks][3];
            aPl[ks][0] = packh2(p00 - __half2float(__low2half(t0)),
                                p01 - __half2float(__high2half(t0)));
            aPl[ks][1] = packh2(p02 - __half2float(__low2half(t1)),
                                p03 - __half2float(__high2half(t1)));
            aPl[ks][2] = packh2(p10 - __half2float(__low2half(t2)),
                                p11 - __half2float(__high2half(t2)));
            aPl[ks][3] = packh2(p12 - __half2float(__low2half(t3)),
                                p13 - __half2float(__high2half(t3)));
        }

#pragma unroll
        for (int ks = 0; ks < 4; ks++) {
#pragma unroll
            for (int dp = 0; dp < 8; dp++) {
                uint32_t bh[4];
                LDSM4T(bh[0], bh[1], bh[2], bh[3],
                       Vh + vLb + (uint32_t)(ks * 16) * FT + dp * 32);
                mma16816(oacc[2 * dp],     aPh[ks], &bh[0]);
                mma16816(oacc[2 * dp + 1], aPh[ks], &bh[2]);
                mma16816(oacc[2 * dp],     aPl[ks], &bh[0]);
                mma16816(oacc[2 * dp + 1], aPl[ks], &bh[2]);
            }
        }
    }

    float inv0 = 1.0f / l0, inv1 = 1.0f / l1;
    int grow = q0 + wid * 16 + r0;
#pragma unroll
    for (int dt = 0; dt < 16; dt++) {
        int col = h * HDIM + dt * 8 + (lane & 3) * 2;
        float v0 = oacc[dt][0] * inv0, v1 = oacc[dt][1] * inv0;
        float v2 = oacc[dt][2] * inv1, v3 = oacc[dt][3] * inv1;

        __half h0 = __float2half(v0), h1 = __float2half(v1);
        __half h2 = __float2half(v2), h3 = __float2half(v3);
        __half2 hi01 = __halves2half2(h0, h1);
        __half2 hi23 = __halves2half2(h2, h3);
        uint32_t lo01 = packh2(v0 - __half2float(h0), v1 - __half2float(h1));
        uint32_t lo23 = packh2(v2 - __half2float(h2), v3 - __half2float(h3));

        uint32_t* pA = (uint32_t*)(xp2 + (size_t)grow * (2 * HID) + col);
        pA[0]       = *(uint32_t*)&hi01;
        pA[HID / 2] = lo01;
        uint32_t* pB = (uint32_t*)(xp2 + (size_t)(grow + 8) * (2 * HID) + col);
        pB[0]       = *(uint32_t*)&hi23;
        pB[HID / 2] = lo23;
    }
}

// ============================================================================
// KV eviction
// ============================================================================
__global__ void evict_kernel(float* __restrict__ outk, float* __restrict__ outv)
{
    int idx = blockIdx.x * blockDim.x + threadIdx.x;
    if (idx >= NHEAD * EVLEN * HDIM) return;
    int d = idx & 127;
    int t = (idx >> 7) % EVLEN;
    int h = idx / (EVLEN * HDIM);
    int src = (t < SINKN) ? t : (S_LEN - RECENT) + (t - SINKN);
    size_t si = ((size_t)h * S_LEN + src) * HDIM + d;
    outk[idx] = g_k[si];
    outv[idx] = g_v[si];
}

// ============================================================================
extern "C" void kernel_launch(void* const* d_in, const int* in_sizes, int n_in,
                              void* d_out, int out_size)
{
    const float* X  = (const float*)d_in[0];
    const float* Wq = (const float*)d_in[1];
    const float* Wk = (const float*)d_in[2];
    const float* Wv = (const float*)d_in[3];
    const float* Wo = (const float*)d_in[4];
    float* out = (float*)d_out;

    float *qb, *kb, *vb;
    __half *xpA, *xp2, *wqkv, *wo;
    cudaGetSymbolAddress((void**)&qb,   g_q);
    cudaGetSymbolAddress((void**)&kb,   g_k);
    cudaGetSymbolAddress((void**)&vb,   g_v);
    cudaGetSymbolAddress((void**)&xpA,  g_xpA);
    cudaGetSymbolAddress((void**)&xp2,  g_xp2);
    cudaGetSymbolAddress((void**)&wqkv, g_wqkv);
    cudaGetSymbolAddress((void**)&wo,   g_wo);

    cudaFuncSetAttribute(mma_gemm_kernel<1>,
                         cudaFuncAttributeMaxDynamicSharedMemorySize, GEMM_SMEM);
    cudaFuncSetAttribute(mma_gemm_kernel<0>,
                         cudaFuncAttributeMaxDynamicSharedMemorySize, GEMM_SMEM);
    cudaFuncSetAttribute(flash_mma_kernel,
                         cudaFuncAttributeMaxDynamicSharedMemorySize, FA_SMEM);

    rope_table_kernel<<<(S_LEN * 64 + 255) / 256, 256>>>();

    // all conversions in one launch (X split; all weights rounded)
    convert_all_kernel<<<CV_TOT / 256, 256>>>(X, Wq, Wk, Wv, Wo,
                                              xpA, wqkv, wo);

    // uniform QKV projection: N = 12288 over concat weights, all 2-term
    mma_gemm_kernel<1><<<1536, 256, GEMM_SMEM>>>(xpA, wqkv, qb, kb, vb);

    rope_split_kernel<<<(NHEAD * S_LEN * 64) / 256, 256>>>();

    flash_mma_kernel<<<dim3(16, 32), 256, FA_SMEM>>>(xp2);

    // output projection (2-term, same kernel shape, row-major out)
    mma_gemm_kernel<0><<<512, 256, GEMM_SMEM>>>(xp2, wo, out, out, out);

    size_t attn_elems = (size_t)S_LEN * HID;
    size_t ev_elems   = (size_t)NHEAD * EVLEN * HDIM;
    evict_kernel<<<(int)((ev_elems + 255) / 256), 256>>>(out + attn_elems,
                                                         out + attn_elems + ev_elems);
}